// round 1
// baseline (speedup 1.0000x reference)
#include <cuda_runtime.h>
#include <cuda_bf16.h>
#include <math.h>

// Problem constants
#define BB 8
#define NN 4096
#define CC 640
#define SS 77
#define XD 768
#define HH 8
#define DH 80
#define KK 2
#define BETA 0.5f
#define TAU 0.1f
#define EPSI 1e-8f

// ---------------- scratch (no cudaMalloc allowed) ----------------
__device__ float g_Q[BB * NN * CC];      // 83.9 MB
__device__ float g_attn[BB * NN * CC];   // 83.9 MB
__device__ float g_K[BB * SS * CC];
__device__ float g_V[BB * SS * CC];
__device__ float g_Ve[BB * SS * CC];
__device__ float g_uhat[SS * CC];
__device__ float g_ahat[SS * CC];
__device__ float g_G[SS * 3];

// ---------------- block reduce helper ----------------
__device__ __forceinline__ float blockSum(float v, float* red) {
    #pragma unroll
    for (int o = 16; o; o >>= 1) v += __shfl_xor_sync(0xffffffffu, v, o);
    int w = threadIdx.x >> 5, l = threadIdx.x & 31;
    __syncthreads();
    if (l == 0) red[w] = v;
    __syncthreads();
    if (w == 0) {
        float x = (l < (int)(blockDim.x >> 5)) ? red[l] : 0.0f;
        #pragma unroll
        for (int o = 4; o; o >>= 1) x += __shfl_xor_sync(0xffffffffu, x, o);
        if (l == 0) red[0] = x;
    }
    __syncthreads();
    return red[0];
}

// ---------------- SGEMM: C[M,N] = A[M,K] @ B[K,N] (+bias) ----------------
// 128x128x16 tile, 256 threads, 8x8 micro-tile (2x2 blocks of 4x4).
// Dual mode: if B2 != nullptr, blocks with blockIdx.x >= nsplit compute C2 = A @ B2.
#define BM 128
#define BN 128
#define BKT 16

__global__ __launch_bounds__(256) void sgemm(
    const float* __restrict__ A, const float* __restrict__ B,
    const float* __restrict__ bias, float* __restrict__ C,
    const float* __restrict__ B2, float* __restrict__ C2,
    int M, int K, int N, int nsplit)
{
    __shared__ float As[BKT][BM];
    __shared__ float Bs[BKT][BN];

    int bx = blockIdx.x;
    const float* Bm = B;
    float* Cm = C;
    if (B2 != nullptr && bx >= nsplit) { Bm = B2; Cm = C2; bx -= nsplit; }

    const int tid = threadIdx.x;
    const int row0 = blockIdx.y * BM;
    const int col0 = bx * BN;
    const int tx = tid & 15;        // 0..15
    const int ty = tid >> 4;        // 0..15

    float acc[8][8];
    #pragma unroll
    for (int i = 0; i < 8; i++)
        #pragma unroll
        for (int j = 0; j < 8; j++) acc[i][j] = 0.0f;

    const int arow = tid >> 2;           // 0..63
    const int acol = (tid & 3) * 4;      // 0,4,8,12

    for (int k0 = 0; k0 < K; k0 += BKT) {
        // Load A tile (transposed into As), guarded on M
        #pragma unroll
        for (int i = 0; i < 2; i++) {
            int r = arow + i * 64;
            int gr = row0 + r;
            float4 av = make_float4(0.f, 0.f, 0.f, 0.f);
            if (gr < M) av = *(const float4*)(A + (size_t)gr * K + k0 + acol);
            As[acol + 0][r] = av.x;
            As[acol + 1][r] = av.y;
            As[acol + 2][r] = av.z;
            As[acol + 3][r] = av.w;
        }
        // Load B tile
        #pragma unroll
        for (int i = 0; i < 2; i++) {
            int fid = tid + i * 256;
            int r = fid >> 5;              // 0..15
            int c = (fid & 31) * 4;        // 0..124
            *(float4*)&Bs[r][c] = *(const float4*)(Bm + (size_t)(k0 + r) * N + col0 + c);
        }
        __syncthreads();

        #pragma unroll
        for (int kk = 0; kk < BKT; kk++) {
            float a[8], b[8];
            *(float4*)&a[0] = *(float4*)&As[kk][ty * 4];
            *(float4*)&a[4] = *(float4*)&As[kk][64 + ty * 4];
            *(float4*)&b[0] = *(float4*)&Bs[kk][tx * 4];
            *(float4*)&b[4] = *(float4*)&Bs[kk][64 + tx * 4];
            #pragma unroll
            for (int i = 0; i < 8; i++)
                #pragma unroll
                for (int j = 0; j < 8; j++)
                    acc[i][j] += a[i] * b[j];
        }
        __syncthreads();
    }

    // Store C with optional bias
    #pragma unroll
    for (int i = 0; i < 8; i++) {
        int r = (i < 4) ? (ty * 4 + i) : (64 + ty * 4 + (i - 4));
        int gr = row0 + r;
        if (gr >= M) continue;
        #pragma unroll
        for (int jb = 0; jb < 2; jb++) {
            int c = jb * 64 + tx * 4;
            float4 o;
            o.x = acc[i][jb * 4 + 0];
            o.y = acc[i][jb * 4 + 1];
            o.z = acc[i][jb * 4 + 2];
            o.w = acc[i][jb * 4 + 3];
            if (bias != nullptr) {
                o.x += bias[col0 + c + 0];
                o.y += bias[col0 + c + 1];
                o.z += bias[col0 + c + 2];
                o.w += bias[col0 + c + 3];
            }
            *(float4*)(Cm + (size_t)gr * N + col0 + c) = o;
        }
    }
}

// ---------------- CORA prep: per token s, compute u_hat, a_hat, Gram ----------------
__global__ __launch_bounds__(256) void cora_prep(
    const float* __restrict__ target, const float* __restrict__ anchor,
    const float* __restrict__ pres,
    float* __restrict__ uhat, float* __restrict__ ahat, float* __restrict__ Gout)
{
    __shared__ float red[32];
    __shared__ float ud[CC], ad[CC];
    const int s = blockIdx.x, tid = threadIdx.x;
    const float* p0 = pres + (size_t)s * CC;
    const float* p1 = pres + (size_t)(SS + s) * CC;
    const float* tg = target + (size_t)s * CC;
    const float* an = anchor + (size_t)s * CC;

    float g00 = 0, g01 = 0, g11 = 0, bt0 = 0, bt1 = 0, ba0 = 0, ba1 = 0;
    for (int d = tid; d < CC; d += 256) {
        float a = p0[d], b = p1[d], t = tg[d], u = an[d];
        g00 += a * a; g01 += a * b; g11 += b * b;
        bt0 += a * t; bt1 += b * t;
        ba0 += a * u; ba1 += b * u;
    }
    g00 = blockSum(g00, red); g01 = blockSum(g01, red); g11 = blockSum(g11, red);
    bt0 = blockSum(bt0, red); bt1 = blockSum(bt1, red);
    ba0 = blockSum(ba0, red); ba1 = blockSum(ba1, red);

    float det = g00 * g11 - g01 * g01;
    float ct0 = (g11 * bt0 - g01 * bt1) / det, ct1 = (g00 * bt1 - g01 * bt0) / det;
    float ca0 = (g11 * ba0 - g01 * ba1) / det, ca1 = (g00 * ba1 - g01 * ba0) / det;

    float nu2 = 0;
    for (int d = tid; d < CC; d += 256) {
        float udv = tg[d] - (p0[d] * ct0 + p1[d] * ct1);
        float adv = an[d] - (p0[d] * ca0 + p1[d] * ca1);
        ud[d] = udv; ad[d] = adv;
        nu2 += udv * udv;
    }
    nu2 = blockSum(nu2, red);
    float nu = sqrtf(nu2) + EPSI;

    float dua = 0;
    for (int d = tid; d < CC; d += 256) {
        float uh = ud[d] / nu;
        ud[d] = uh;
        uhat[(size_t)s * CC + d] = uh;
        dua += uh * ad[d];
    }
    dua = blockSum(dua, red);

    float na2 = 0;
    for (int d = tid; d < CC; d += 256) {
        float at = ad[d] - dua * ud[d];
        ad[d] = at;
        na2 += at * at;
    }
    na2 = blockSum(na2, red);
    float na = sqrtf(na2) + EPSI;

    for (int d = tid; d < CC; d += 256)
        ahat[(size_t)s * CC + d] = ad[d] / na;

    if (tid == 0) { Gout[s * 3 + 0] = g00; Gout[s * 3 + 1] = g01; Gout[s * 3 + 2] = g11; }
}

// ---------------- CORA apply: per (b,s) edit value vector ----------------
__global__ __launch_bounds__(256) void cora_apply(
    const float* __restrict__ Vin, const float* __restrict__ pres,
    const float* __restrict__ G, const float* __restrict__ uhat,
    const float* __restrict__ ahat, float* __restrict__ Ve)
{
    __shared__ float red[32];
    const int bs = blockIdx.x, s = bs % SS, tid = threadIdx.x;
    const float* v = Vin + (size_t)bs * CC;
    const float* p0 = pres + (size_t)s * CC;
    const float* p1 = pres + (size_t)(SS + s) * CC;
    const float* uh = uhat + (size_t)s * CC;
    const float* ah = ahat + (size_t)s * CC;

    float b0 = 0, b1 = 0;
    for (int d = tid; d < CC; d += 256) {
        float vd = v[d];
        b0 += p0[d] * vd; b1 += p1[d] * vd;
    }
    b0 = blockSum(b0, red); b1 = blockSum(b1, red);

    float g00 = G[s * 3], g01 = G[s * 3 + 1], g11 = G[s * 3 + 2];
    float det = g00 * g11 - g01 * g01;
    float c0 = (g11 * b0 - g01 * b1) / det;
    float c1 = (g00 * b1 - g01 * b0) / det;

    float nf2 = 0, t = 0;
    for (int d = tid; d < CC; d += 256) {
        float vp = p0[d] * c0 + p1[d] * c1;
        float vf = v[d] - vp;
        nf2 += vf * vf;
        t += uh[d] * vf;
    }
    nf2 = blockSum(nf2, red);
    t = blockSum(t, red);

    float denom = sqrtf(nf2) + EPSI;
    bool keep = (fabsf(t) / denom) < TAU;

    for (int d = tid; d < CC; d += 256) {
        float vp = p0[d] * c0 + p1[d] * c1;
        float vf = v[d] - vp;
        float vn = vp + vf - t * uh[d] + BETA * t * ah[d];
        Ve[(size_t)bs * CC + d] = keep ? v[d] : vn;
    }
}

// ---------------- fused attention: per (b,h,64-row tile) ----------------
// smem: Ks[77][84] + Vs[77][84] + Qs[64][80] + Ps[64][80]  = 92704 B (dynamic)
#define ATTN_SMEM_BYTES ((SS * 84 * 2 + 64 * DH * 2) * 4)

__global__ __launch_bounds__(256) void attn_kernel(
    const float* __restrict__ Q, const float* __restrict__ Kp,
    const float* __restrict__ Vp, float* __restrict__ O)
{
    extern __shared__ float sm[];
    float* Ks = sm;                      // 77*84
    float* Vs = Ks + SS * 84;            // 77*84
    float* Qs = Vs + SS * 84;            // 64*80
    float* Ps = Qs + 64 * DH;            // 64*80

    const int b = blockIdx.z, h = blockIdx.y;
    const int n0 = blockIdx.x * 64;
    const int tid = threadIdx.x;

    for (int i = tid; i < SS * DH; i += 256) {
        int s = i / DH, d = i % DH;
        size_t goff = ((size_t)(b * SS + s)) * CC + h * DH + d;
        Ks[s * 84 + d] = Kp[goff];
        Vs[s * 84 + d] = Vp[goff];
    }
    for (int i = tid; i < 64 * DH; i += 256) {
        int r = i / DH, d = i % DH;
        Qs[r * DH + d] = Q[((size_t)b * NN + n0 + r) * CC + h * DH + d];
    }
    __syncthreads();

    const int w = tid >> 5, l = tid & 31;
    const int rbase = w * 8;

    // scores: each lane owns s = l, l+32, l+64; 8 rows per warp
    float acc[8][3];
    #pragma unroll
    for (int r = 0; r < 8; r++)
        #pragma unroll
        for (int c = 0; c < 3; c++) acc[r][c] = 0.0f;

    const float4* Ks4 = (const float4*)Ks;  // row stride 21 float4
    #pragma unroll 4
    for (int dc = 0; dc < DH / 4; dc++) {
        float4 kv[3];
        #pragma unroll
        for (int c = 0; c < 3; c++) {
            int s = l + 32 * c;
            kv[c] = (s < SS) ? Ks4[s * 21 + dc] : make_float4(0.f, 0.f, 0.f, 0.f);
        }
        #pragma unroll
        for (int r = 0; r < 8; r++) {
            float4 qv = *(const float4*)(Qs + (rbase + r) * DH + dc * 4);
            #pragma unroll
            for (int c = 0; c < 3; c++)
                acc[r][c] += qv.x * kv[c].x + qv.y * kv[c].y + qv.z * kv[c].z + qv.w * kv[c].w;
        }
    }

    const float scale = 0.11180339887498948f; // 1/sqrt(80)
    #pragma unroll
    for (int r = 0; r < 8; r++) {
        float m = -1e30f;
        #pragma unroll
        for (int c = 0; c < 3; c++) {
            int s = l + 32 * c;
            float vsc = (s < SS) ? acc[r][c] * scale : -1e30f;
            acc[r][c] = vsc;
            m = fmaxf(m, vsc);
        }
        #pragma unroll
        for (int o = 16; o; o >>= 1) m = fmaxf(m, __shfl_xor_sync(0xffffffffu, m, o));
        float sum = 0.f;
        #pragma unroll
        for (int c = 0; c < 3; c++) {
            int s = l + 32 * c;
            float e = (s < SS) ? expf(acc[r][c] - m) : 0.f;
            acc[r][c] = e;
            sum += e;
        }
        #pragma unroll
        for (int o = 16; o; o >>= 1) sum += __shfl_xor_sync(0xffffffffu, sum, o);
        float inv = 1.0f / sum;
        #pragma unroll
        for (int c = 0; c < 3; c++) {
            int s = l + 32 * c;
            if (s < SS) Ps[(rbase + r) * DH + s] = acc[r][c] * inv;
        }
    }
    __syncwarp();

    // output: lane owns d = l, l+32, l+64
    float oacc[8][3];
    #pragma unroll
    for (int r = 0; r < 8; r++)
        #pragma unroll
        for (int j = 0; j < 3; j++) oacc[r][j] = 0.0f;

    for (int s = 0; s < SS; s++) {
        float vv[3];
        #pragma unroll
        for (int j = 0; j < 3; j++) {
            int d = l + 32 * j;
            vv[j] = (d < DH) ? Vs[s * 84 + d] : 0.f;
        }
        #pragma unroll
        for (int r = 0; r < 8; r++) {
            float pv = Ps[(rbase + r) * DH + s];
            #pragma unroll
            for (int j = 0; j < 3; j++) oacc[r][j] += pv * vv[j];
        }
    }

    #pragma unroll
    for (int r = 0; r < 8; r++)
        #pragma unroll
        for (int j = 0; j < 3; j++) {
            int d = l + 32 * j;
            if (d < DH)
                O[((size_t)b * NN + n0 + rbase + r) * CC + h * DH + d] = oacc[r][j];
        }
}

// ---------------- launch ----------------
extern "C" void kernel_launch(void* const* d_in, const int* in_sizes, int n_in,
                              void* d_out, int out_size)
{
    static float *Qb = nullptr, *Attn = nullptr, *Kb = nullptr, *Vb = nullptr,
                 *Veb = nullptr, *Uh = nullptr, *Ah = nullptr, *Gm = nullptr;
    static bool init = false;
    if (!init) {
        cudaGetSymbolAddress((void**)&Qb, g_Q);
        cudaGetSymbolAddress((void**)&Attn, g_attn);
        cudaGetSymbolAddress((void**)&Kb, g_K);
        cudaGetSymbolAddress((void**)&Vb, g_V);
        cudaGetSymbolAddress((void**)&Veb, g_Ve);
        cudaGetSymbolAddress((void**)&Uh, g_uhat);
        cudaGetSymbolAddress((void**)&Ah, g_ahat);
        cudaGetSymbolAddress((void**)&Gm, g_G);
        cudaFuncSetAttribute(attn_kernel, cudaFuncAttributeMaxDynamicSharedMemorySize,
                             ATTN_SMEM_BYTES);
        init = true;  // host-side idempotent setup only; identical GPU work every call
    }

    const float* X    = (const float*)d_in[0];  // [8,4096,640]
    const float* E    = (const float*)d_in[1];  // [8,77,768]
    const float* Wq   = (const float*)d_in[2];  // [640,640]
    const float* Wk   = (const float*)d_in[3];  // [768,640]
    const float* Wv   = (const float*)d_in[4];  // [768,640]
    const float* Wo   = (const float*)d_in[5];  // [640,640]
    const float* bo   = (const float*)d_in[6];  // [640]
    const float* tgt  = (const float*)d_in[7];  // [77,640]
    const float* anc  = (const float*)d_in[8];  // [77,640]
    const float* pres = (const float*)d_in[9];  // [2,77,640]
    float* out = (float*)d_out;

    // Q projection: [32768,640] x [640,640]
    sgemm<<<dim3(CC / BN, (BB * NN) / BM), 256>>>(
        X, Wq, nullptr, Qb, nullptr, nullptr, BB * NN, CC, CC, CC / BN);

    // K,V projections (dual-B single launch): [616,768] x [768,640]
    sgemm<<<dim3(2 * (CC / BN), (BB * SS + BM - 1) / BM), 256>>>(
        E, Wk, nullptr, Kb, Wv, Vb, BB * SS, XD, CC, CC / BN);

    // CORA erase on V
    cora_prep<<<SS, 256>>>(tgt, anc, pres, Uh, Ah, Gm);
    cora_apply<<<BB * SS, 256>>>(Vb, pres, Gm, Uh, Ah, Veb);

    // fused attention
    attn_kernel<<<dim3(NN / 64, HH, BB), 256, ATTN_SMEM_BYTES>>>(Qb, Kb, Veb, Attn);

    // output projection + bias
    sgemm<<<dim3(CC / BN, (BB * NN) / BM), 256>>>(
        Attn, Wo, bo, out, nullptr, nullptr, BB * NN, CC, CC, CC / BN);
}

// round 3
// speedup vs baseline: 1.7373x; 1.7373x over previous
#include <cuda_runtime.h>
#include <cuda_bf16.h>
#include <math.h>
#include <stdint.h>

// Problem constants
#define BB 8
#define NN 4096
#define CC 640
#define SS 77
#define XD 768
#define HH 8
#define DH 80
#define KK 2
#define BETA 0.5f
#define TAU 0.1f
#define EPSI 1e-8f

// ---------------- scratch (no cudaMalloc allowed) ----------------
__device__ float g_Q[BB * NN * CC];      // 83.9 MB
__device__ float g_attn[BB * NN * CC];   // 83.9 MB
__device__ float g_K[BB * SS * CC];
__device__ float g_V[BB * SS * CC];
__device__ float g_Ve[BB * SS * CC];
__device__ float g_uhat[SS * CC];
__device__ float g_ahat[SS * CC];
__device__ float g_G[SS * 3];

// ---------------- block reduce helper ----------------
__device__ __forceinline__ float blockSum(float v, float* red) {
    #pragma unroll
    for (int o = 16; o; o >>= 1) v += __shfl_xor_sync(0xffffffffu, v, o);
    int w = threadIdx.x >> 5, l = threadIdx.x & 31;
    __syncthreads();
    if (l == 0) red[w] = v;
    __syncthreads();
    if (w == 0) {
        float x = (l < (int)(blockDim.x >> 5)) ? red[l] : 0.0f;
        #pragma unroll
        for (int o = 4; o; o >>= 1) x += __shfl_xor_sync(0xffffffffu, x, o);
        if (l == 0) red[0] = x;
    }
    __syncthreads();
    return red[0];
}

// =====================================================================
// TF32 tensor-core GEMM: C[M,N] = A[M,K] @ B[K,N] (+bias)
// Requires M%128==0, N%128==0, K%16==0.
// 128x128x16 tile, 256 threads (8 warps in 2x4), each warp 64x32,
// m16n8k8 tf32 mma, register-prefetch pipeline.
// =====================================================================
#define TBM 128
#define TBN 128
#define TBK 16
#define ASTR 20     // A smem row stride (k-pad): conflict-free frag loads
#define BSTR 136    // B smem row stride (n-pad): conflict-free frag loads

__device__ __forceinline__ unsigned int f2tf(float x) {
    unsigned int r;
    asm("cvt.rna.tf32.f32 %0, %1;" : "=r"(r) : "f"(x));
    return r;
}

__global__ __launch_bounds__(256) void gemm_tf32(
    const float* __restrict__ A, const float* __restrict__ B,
    const float* __restrict__ bias, float* __restrict__ C,
    int M, int K, int N)
{
    __shared__ float As[TBM * ASTR];
    __shared__ float Bs[TBK * BSTR];

    const int tid = threadIdx.x;
    const int row0 = blockIdx.y * TBM;
    const int col0 = blockIdx.x * TBN;
    const int wid = tid >> 5, lane = tid & 31;
    const int wm = wid >> 2, wn = wid & 3;      // 2 x 4 warp grid
    const int g = lane >> 2, tg = lane & 3;

    // gmem load mapping
    const int am = tid >> 2;            // 0..63 (+64)
    const int ak = (tid & 3) * 4;       // 0,4,8,12
    const int br0 = tid >> 5;           // 0..7  (+8)
    const int bc0 = (tid & 31) * 4;     // 0..124

    const float* Ag = A + (size_t)(row0 + am) * K + ak;
    const float* Bg = B + (size_t)br0 * N + col0 + bc0;

    float acc[4][4][4];
    #pragma unroll
    for (int i = 0; i < 4; i++)
        #pragma unroll
        for (int j = 0; j < 4; j++)
            #pragma unroll
            for (int r = 0; r < 4; r++) acc[i][j][r] = 0.0f;

    float4 ra[2], rb[2];

    const int KT = K / TBK;

    // prologue: tile 0
    ra[0] = *(const float4*)(Ag);
    ra[1] = *(const float4*)(Ag + (size_t)64 * K);
    rb[0] = *(const float4*)(Bg);
    rb[1] = *(const float4*)(Bg + (size_t)8 * N);

    #pragma unroll 1
    for (int kt = 0; kt < KT; kt++) {
        // store current prefetch to smem (tf32-converted)
        {
            float* pa0 = &As[am * ASTR + ak];
            pa0[0] = __uint_as_float(f2tf(ra[0].x));
            pa0[1] = __uint_as_float(f2tf(ra[0].y));
            pa0[2] = __uint_as_float(f2tf(ra[0].z));
            pa0[3] = __uint_as_float(f2tf(ra[0].w));
            float* pa1 = &As[(am + 64) * ASTR + ak];
            pa1[0] = __uint_as_float(f2tf(ra[1].x));
            pa1[1] = __uint_as_float(f2tf(ra[1].y));
            pa1[2] = __uint_as_float(f2tf(ra[1].z));
            pa1[3] = __uint_as_float(f2tf(ra[1].w));
            float* pb0 = &Bs[br0 * BSTR + bc0];
            pb0[0] = __uint_as_float(f2tf(rb[0].x));
            pb0[1] = __uint_as_float(f2tf(rb[0].y));
            pb0[2] = __uint_as_float(f2tf(rb[0].z));
            pb0[3] = __uint_as_float(f2tf(rb[0].w));
            float* pb1 = &Bs[(br0 + 8) * BSTR + bc0];
            pb1[0] = __uint_as_float(f2tf(rb[1].x));
            pb1[1] = __uint_as_float(f2tf(rb[1].y));
            pb1[2] = __uint_as_float(f2tf(rb[1].z));
            pb1[3] = __uint_as_float(f2tf(rb[1].w));
        }
        __syncthreads();

        // prefetch next tile into registers (overlaps with MMA below)
        if (kt + 1 < KT) {
            const float* Agn = Ag + (kt + 1) * TBK;
            const float* Bgn = Bg + (size_t)(kt + 1) * TBK * N;
            ra[0] = *(const float4*)(Agn);
            ra[1] = *(const float4*)(Agn + (size_t)64 * K);
            rb[0] = *(const float4*)(Bgn);
            rb[1] = *(const float4*)(Bgn + (size_t)8 * N);
        }

        // compute: two k8 steps
        #pragma unroll
        for (int k8 = 0; k8 < 2; k8++) {
            unsigned int af[4][4], bf[4][2];
            #pragma unroll
            for (int i = 0; i < 4; i++) {
                const float* p = &As[(wm * 64 + i * 16 + g) * ASTR + k8 * 8 + tg];
                af[i][0] = __float_as_uint(p[0]);
                af[i][1] = __float_as_uint(p[8 * ASTR]);
                af[i][2] = __float_as_uint(p[4]);
                af[i][3] = __float_as_uint(p[8 * ASTR + 4]);
            }
            #pragma unroll
            for (int j = 0; j < 4; j++) {
                const float* p = &Bs[(k8 * 8 + tg) * BSTR + wn * 32 + j * 8 + g];
                bf[j][0] = __float_as_uint(p[0]);
                bf[j][1] = __float_as_uint(p[4 * BSTR]);
            }
            #pragma unroll
            for (int i = 0; i < 4; i++)
                #pragma unroll
                for (int j = 0; j < 4; j++) {
                    asm volatile(
                        "mma.sync.aligned.m16n8k8.row.col.f32.tf32.tf32.f32 "
                        "{%0,%1,%2,%3}, {%4,%5,%6,%7}, {%8,%9}, {%0,%1,%2,%3};"
                        : "+f"(acc[i][j][0]), "+f"(acc[i][j][1]),
                          "+f"(acc[i][j][2]), "+f"(acc[i][j][3])
                        : "r"(af[i][0]), "r"(af[i][1]), "r"(af[i][2]), "r"(af[i][3]),
                          "r"(bf[j][0]), "r"(bf[j][1]));
                }
        }
        __syncthreads();
    }

    // epilogue
    #pragma unroll
    for (int i = 0; i < 4; i++) {
        #pragma unroll
        for (int j = 0; j < 4; j++) {
            int row = row0 + wm * 64 + i * 16 + g;
            int col = col0 + wn * 32 + j * 8 + tg * 2;
            float b0 = 0.f, b1 = 0.f;
            if (bias != nullptr) { b0 = bias[col]; b1 = bias[col + 1]; }
            float2 v0 = make_float2(acc[i][j][0] + b0, acc[i][j][1] + b1);
            float2 v1 = make_float2(acc[i][j][2] + b0, acc[i][j][3] + b1);
            *(float2*)(C + (size_t)row * N + col) = v0;
            *(float2*)(C + (size_t)(row + 8) * N + col) = v1;
        }
    }
}

// ---------------- SGEMM (fp32 SIMT) for the small K/V projections ----------------
#define BM 128
#define BN 128
#define BKT 16

__global__ __launch_bounds__(256) void sgemm(
    const float* __restrict__ A, const float* __restrict__ B,
    const float* __restrict__ bias, float* __restrict__ C,
    const float* __restrict__ B2, float* __restrict__ C2,
    int M, int K, int N, int nsplit)
{
    __shared__ float As[BKT][BM];
    __shared__ float Bs[BKT][BN];

    int bx = blockIdx.x;
    const float* Bm = B;
    float* Cm = C;
    if (B2 != nullptr && bx >= nsplit) { Bm = B2; Cm = C2; bx -= nsplit; }

    const int tid = threadIdx.x;
    const int row0 = blockIdx.y * BM;
    const int col0 = bx * BN;
    const int tx = tid & 15;
    const int ty = tid >> 4;

    float acc[8][8];
    #pragma unroll
    for (int i = 0; i < 8; i++)
        #pragma unroll
        for (int j = 0; j < 8; j++) acc[i][j] = 0.0f;

    const int arow = tid >> 2;
    const int acol = (tid & 3) * 4;

    for (int k0 = 0; k0 < K; k0 += BKT) {
        #pragma unroll
        for (int i = 0; i < 2; i++) {
            int r = arow + i * 64;
            int gr = row0 + r;
            float4 av = make_float4(0.f, 0.f, 0.f, 0.f);
            if (gr < M) av = *(const float4*)(A + (size_t)gr * K + k0 + acol);
            As[acol + 0][r] = av.x;
            As[acol + 1][r] = av.y;
            As[acol + 2][r] = av.z;
            As[acol + 3][r] = av.w;
        }
        #pragma unroll
        for (int i = 0; i < 2; i++) {
            int fid = tid + i * 256;
            int r = fid >> 5;
            int c = (fid & 31) * 4;
            *(float4*)&Bs[r][c] = *(const float4*)(Bm + (size_t)(k0 + r) * N + col0 + c);
        }
        __syncthreads();

        #pragma unroll
        for (int kk = 0; kk < BKT; kk++) {
            float a[8], b[8];
            *(float4*)&a[0] = *(float4*)&As[kk][ty * 4];
            *(float4*)&a[4] = *(float4*)&As[kk][64 + ty * 4];
            *(float4*)&b[0] = *(float4*)&Bs[kk][tx * 4];
            *(float4*)&b[4] = *(float4*)&Bs[kk][64 + tx * 4];
            #pragma unroll
            for (int i = 0; i < 8; i++)
                #pragma unroll
                for (int j = 0; j < 8; j++)
                    acc[i][j] += a[i] * b[j];
        }
        __syncthreads();
    }

    #pragma unroll
    for (int i = 0; i < 8; i++) {
        int r = (i < 4) ? (ty * 4 + i) : (64 + ty * 4 + (i - 4));
        int gr = row0 + r;
        if (gr >= M) continue;
        #pragma unroll
        for (int jb = 0; jb < 2; jb++) {
            int c = jb * 64 + tx * 4;
            float4 o;
            o.x = acc[i][jb * 4 + 0];
            o.y = acc[i][jb * 4 + 1];
            o.z = acc[i][jb * 4 + 2];
            o.w = acc[i][jb * 4 + 3];
            if (bias != nullptr) {
                o.x += bias[col0 + c + 0];
                o.y += bias[col0 + c + 1];
                o.z += bias[col0 + c + 2];
                o.w += bias[col0 + c + 3];
            }
            *(float4*)(Cm + (size_t)gr * N + col0 + c) = o;
        }
    }
}

// ---------------- CORA prep ----------------
__global__ __launch_bounds__(256) void cora_prep(
    const float* __restrict__ target, const float* __restrict__ anchor,
    const float* __restrict__ pres,
    float* __restrict__ uhat, float* __restrict__ ahat, float* __restrict__ Gout)
{
    __shared__ float red[32];
    __shared__ float ud[CC], ad[CC];
    const int s = blockIdx.x, tid = threadIdx.x;
    const float* p0 = pres + (size_t)s * CC;
    const float* p1 = pres + (size_t)(SS + s) * CC;
    const float* tg = target + (size_t)s * CC;
    const float* an = anchor + (size_t)s * CC;

    float g00 = 0, g01 = 0, g11 = 0, bt0 = 0, bt1 = 0, ba0 = 0, ba1 = 0;
    for (int d = tid; d < CC; d += 256) {
        float a = p0[d], b = p1[d], t = tg[d], u = an[d];
        g00 += a * a; g01 += a * b; g11 += b * b;
        bt0 += a * t; bt1 += b * t;
        ba0 += a * u; ba1 += b * u;
    }
    g00 = blockSum(g00, red); g01 = blockSum(g01, red); g11 = blockSum(g11, red);
    bt0 = blockSum(bt0, red); bt1 = blockSum(bt1, red);
    ba0 = blockSum(ba0, red); ba1 = blockSum(ba1, red);

    float det = g00 * g11 - g01 * g01;
    float ct0 = (g11 * bt0 - g01 * bt1) / det, ct1 = (g00 * bt1 - g01 * bt0) / det;
    float ca0 = (g11 * ba0 - g01 * ba1) / det, ca1 = (g00 * ba1 - g01 * ba0) / det;

    float nu2 = 0;
    for (int d = tid; d < CC; d += 256) {
        float udv = tg[d] - (p0[d] * ct0 + p1[d] * ct1);
        float adv = an[d] - (p0[d] * ca0 + p1[d] * ca1);
        ud[d] = udv; ad[d] = adv;
        nu2 += udv * udv;
    }
    nu2 = blockSum(nu2, red);
    float nu = sqrtf(nu2) + EPSI;

    float dua = 0;
    for (int d = tid; d < CC; d += 256) {
        float uh = ud[d] / nu;
        ud[d] = uh;
        uhat[(size_t)s * CC + d] = uh;
        dua += uh * ad[d];
    }
    dua = blockSum(dua, red);

    float na2 = 0;
    for (int d = tid; d < CC; d += 256) {
        float at = ad[d] - dua * ud[d];
        ad[d] = at;
        na2 += at * at;
    }
    na2 = blockSum(na2, red);
    float na = sqrtf(na2) + EPSI;

    for (int d = tid; d < CC; d += 256)
        ahat[(size_t)s * CC + d] = ad[d] / na;

    if (tid == 0) { Gout[s * 3 + 0] = g00; Gout[s * 3 + 1] = g01; Gout[s * 3 + 2] = g11; }
}

// ---------------- CORA apply ----------------
__global__ __launch_bounds__(256) void cora_apply(
    const float* __restrict__ Vin, const float* __restrict__ pres,
    const float* __restrict__ G, const float* __restrict__ uhat,
    const float* __restrict__ ahat, float* __restrict__ Ve)
{
    __shared__ float red[32];
    const int bs = blockIdx.x, s = bs % SS, tid = threadIdx.x;
    const float* v = Vin + (size_t)bs * CC;
    const float* p0 = pres + (size_t)s * CC;
    const float* p1 = pres + (size_t)(SS + s) * CC;
    const float* uh = uhat + (size_t)s * CC;
    const float* ah = ahat + (size_t)s * CC;

    float b0 = 0, b1 = 0;
    for (int d = tid; d < CC; d += 256) {
        float vd = v[d];
        b0 += p0[d] * vd; b1 += p1[d] * vd;
    }
    b0 = blockSum(b0, red); b1 = blockSum(b1, red);

    float g00 = G[s * 3], g01 = G[s * 3 + 1], g11 = G[s * 3 + 2];
    float det = g00 * g11 - g01 * g01;
    float c0 = (g11 * b0 - g01 * b1) / det;
    float c1 = (g00 * b1 - g01 * b0) / det;

    float nf2 = 0, t = 0;
    for (int d = tid; d < CC; d += 256) {
        float vp = p0[d] * c0 + p1[d] * c1;
        float vf = v[d] - vp;
        nf2 += vf * vf;
        t += uh[d] * vf;
    }
    nf2 = blockSum(nf2, red);
    t = blockSum(t, red);

    float denom = sqrtf(nf2) + EPSI;
    bool keep = (fabsf(t) / denom) < TAU;

    for (int d = tid; d < CC; d += 256) {
        float vp = p0[d] * c0 + p1[d] * c1;
        float vf = v[d] - vp;
        float vn = vp + vf - t * uh[d] + BETA * t * ah[d];
        Ve[(size_t)bs * CC + d] = keep ? v[d] : vn;
    }
}

// ---------------- fused attention ----------------
#define ATTN_SMEM_BYTES ((SS * 84 * 2 + 64 * DH * 2) * 4)

__global__ __launch_bounds__(256) void attn_kernel(
    const float* __restrict__ Q, const float* __restrict__ Kp,
    const float* __restrict__ Vp, float* __restrict__ O)
{
    extern __shared__ float sm[];
    float* Ks = sm;
    float* Vs = Ks + SS * 84;
    float* Qs = Vs + SS * 84;
    float* Ps = Qs + 64 * DH;

    const int b = blockIdx.z, h = blockIdx.y;
    const int n0 = blockIdx.x * 64;
    const int tid = threadIdx.x;

    for (int i = tid; i < SS * DH; i += 256) {
        int s = i / DH, d = i % DH;
        size_t goff = ((size_t)(b * SS + s)) * CC + h * DH + d;
        Ks[s * 84 + d] = Kp[goff];
        Vs[s * 84 + d] = Vp[goff];
    }
    for (int i = tid; i < 64 * DH; i += 256) {
        int r = i / DH, d = i % DH;
        Qs[r * DH + d] = Q[((size_t)b * NN + n0 + r) * CC + h * DH + d];
    }
    __syncthreads();

    const int w = tid >> 5, l = tid & 31;
    const int rbase = w * 8;

    float acc[8][3];
    #pragma unroll
    for (int r = 0; r < 8; r++)
        #pragma unroll
        for (int c = 0; c < 3; c++) acc[r][c] = 0.0f;

    const float4* Ks4 = (const float4*)Ks;
    #pragma unroll 4
    for (int dc = 0; dc < DH / 4; dc++) {
        float4 kv[3];
        #pragma unroll
        for (int c = 0; c < 3; c++) {
            int s = l + 32 * c;
            kv[c] = (s < SS) ? Ks4[s * 21 + dc] : make_float4(0.f, 0.f, 0.f, 0.f);
        }
        #pragma unroll
        for (int r = 0; r < 8; r++) {
            float4 qv = *(const float4*)(Qs + (rbase + r) * DH + dc * 4);
            #pragma unroll
            for (int c = 0; c < 3; c++)
                acc[r][c] += qv.x * kv[c].x + qv.y * kv[c].y + qv.z * kv[c].z + qv.w * kv[c].w;
        }
    }

    const float scale = 0.11180339887498948f;
    #pragma unroll
    for (int r = 0; r < 8; r++) {
        float m = -1e30f;
        #pragma unroll
        for (int c = 0; c < 3; c++) {
            int s = l + 32 * c;
            float vsc = (s < SS) ? acc[r][c] * scale : -1e30f;
            acc[r][c] = vsc;
            m = fmaxf(m, vsc);
        }
        #pragma unroll
        for (int o = 16; o; o >>= 1) m = fmaxf(m, __shfl_xor_sync(0xffffffffu, m, o));
        float sum = 0.f;
        #pragma unroll
        for (int c = 0; c < 3; c++) {
            int s = l + 32 * c;
            float e = (s < SS) ? expf(acc[r][c] - m) : 0.f;
            acc[r][c] = e;
            sum += e;
        }
        #pragma unroll
        for (int o = 16; o; o >>= 1) sum += __shfl_xor_sync(0xffffffffu, sum, o);
        float inv = 1.0f / sum;
        #pragma unroll
        for (int c = 0; c < 3; c++) {
            int s = l + 32 * c;
            if (s < SS) Ps[(rbase + r) * DH + s] = acc[r][c] * inv;
        }
    }
    __syncwarp();

    float oacc[8][3];
    #pragma unroll
    for (int r = 0; r < 8; r++)
        #pragma unroll
        for (int j = 0; j < 3; j++) oacc[r][j] = 0.0f;

    for (int s = 0; s < SS; s++) {
        float vv[3];
        #pragma unroll
        for (int j = 0; j < 3; j++) {
            int d = l + 32 * j;
            vv[j] = (d < DH) ? Vs[s * 84 + d] : 0.f;
        }
        #pragma unroll
        for (int r = 0; r < 8; r++) {
            float pv = Ps[(rbase + r) * DH + s];
            #pragma unroll
            for (int j = 0; j < 3; j++) oacc[r][j] += pv * vv[j];
        }
    }

    #pragma unroll
    for (int r = 0; r < 8; r++)
        #pragma unroll
        for (int j = 0; j < 3; j++) {
            int d = l + 32 * j;
            if (d < DH)
                O[((size_t)b * NN + n0 + rbase + r) * CC + h * DH + d] = oacc[r][j];
        }
}

// ---------------- launch ----------------
extern "C" void kernel_launch(void* const* d_in, const int* in_sizes, int n_in,
                              void* d_out, int out_size)
{
    static float *Qb = nullptr, *Attn = nullptr, *Kb = nullptr, *Vb = nullptr,
                 *Veb = nullptr, *Uh = nullptr, *Ah = nullptr, *Gm = nullptr;
    static bool init = false;
    if (!init) {
        cudaGetSymbolAddress((void**)&Qb, g_Q);
        cudaGetSymbolAddress((void**)&Attn, g_attn);
        cudaGetSymbolAddress((void**)&Kb, g_K);
        cudaGetSymbolAddress((void**)&Vb, g_V);
        cudaGetSymbolAddress((void**)&Veb, g_Ve);
        cudaGetSymbolAddress((void**)&Uh, g_uhat);
        cudaGetSymbolAddress((void**)&Ah, g_ahat);
        cudaGetSymbolAddress((void**)&Gm, g_G);
        cudaFuncSetAttribute(attn_kernel, cudaFuncAttributeMaxDynamicSharedMemorySize,
                             ATTN_SMEM_BYTES);
        init = true;
    }

    const float* X    = (const float*)d_in[0];
    const float* E    = (const float*)d_in[1];
    const float* Wq   = (const float*)d_in[2];
    const float* Wk   = (const float*)d_in[3];
    const float* Wv   = (const float*)d_in[4];
    const float* Wo   = (const float*)d_in[5];
    const float* bo   = (const float*)d_in[6];
    const float* tgt  = (const float*)d_in[7];
    const float* anc  = (const float*)d_in[8];
    const float* pres = (const float*)d_in[9];
    float* out = (float*)d_out;

    // Q projection: tf32 tensor cores. [32768,640] x [640,640]
    gemm_tf32<<<dim3(CC / TBN, (BB * NN) / TBM), 256>>>(
        X, Wq, nullptr, Qb, BB * NN, CC, CC);

    // K,V projections (dual-B single launch, fp32 SIMT): [616,768] x [768,640]
    sgemm<<<dim3(2 * (CC / BN), (BB * SS + BM - 1) / BM), 256>>>(
        E, Wk, nullptr, Kb, Wv, Vb, BB * SS, XD, CC, CC / BN);

    // CORA erase on V
    cora_prep<<<SS, 256>>>(tgt, anc, pres, Uh, Ah, Gm);
    cora_apply<<<BB * SS, 256>>>(Vb, pres, Gm, Uh, Ah, Veb);

    // fused attention
    attn_kernel<<<dim3(NN / 64, HH, BB), 256, ATTN_SMEM_BYTES>>>(Qb, Kb, Veb, Attn);

    // output projection + bias: tf32 tensor cores
    gemm_tf32<<<dim3(CC / TBN, (BB * NN) / TBM), 256>>>(
        Attn, Wo, bo, out, BB * NN, CC, CC);
}

// round 4
// speedup vs baseline: 1.7875x; 1.0289x over previous
#include <cuda_runtime.h>
#include <cuda_bf16.h>
#include <math.h>
#include <stdint.h>

// Problem constants
#define BB 8
#define NN 4096
#define CC 640
#define SS 77
#define XD 768
#define HH 8
#define DH 80
#define KK 2
#define BETA 0.5f
#define TAU 0.1f
#define EPSI 1e-8f

// ---------------- scratch (no cudaMalloc allowed) ----------------
__device__ float g_Q[BB * NN * CC];      // 83.9 MB
__device__ float g_attn[BB * NN * CC];   // 83.9 MB
__device__ float g_K[BB * SS * CC];
__device__ float g_V[BB * SS * CC];
__device__ float g_Ve[BB * SS * CC];
__device__ float g_uhat[SS * CC];
__device__ float g_ahat[SS * CC];
__device__ float g_G[SS * 3];

// ---------------- block reduce helper ----------------
__device__ __forceinline__ float blockSum(float v, float* red) {
    #pragma unroll
    for (int o = 16; o; o >>= 1) v += __shfl_xor_sync(0xffffffffu, v, o);
    int w = threadIdx.x >> 5, l = threadIdx.x & 31;
    __syncthreads();
    if (l == 0) red[w] = v;
    __syncthreads();
    if (w == 0) {
        float x = (l < (int)(blockDim.x >> 5)) ? red[l] : 0.0f;
        #pragma unroll
        for (int o = 4; o; o >>= 1) x += __shfl_xor_sync(0xffffffffu, x, o);
        if (l == 0) red[0] = x;
    }
    __syncthreads();
    return red[0];
}

// =====================================================================
// TF32 tensor-core GEMM: C[M,N] = A[M,K] @ B[K,N] (+bias)
// Requires N%128==0, K%16==0. M guarded.
// 128x128x16 tile, 256 threads (8 warps in 2x4), each warp 64x32,
// m16n8k8 tf32 mma, double-buffered smem + register prefetch.
// =====================================================================
#define TBM 128
#define TBN 128
#define TBK 16
#define ASTR 20     // A smem row stride (k-pad): conflict-free frag loads
#define BSTR 136    // B smem row stride (n-pad): conflict-free frag loads

__device__ __forceinline__ unsigned int f2tf(float x) {
    unsigned int r;
    asm("cvt.rna.tf32.f32 %0, %1;" : "=r"(r) : "f"(x));
    return r;
}

__global__ __launch_bounds__(256) void gemm_tf32(
    const float* __restrict__ A, const float* __restrict__ B,
    const float* __restrict__ bias, float* __restrict__ C,
    int M, int K, int N)
{
    __shared__ float As[2][TBM * ASTR];
    __shared__ float Bs[2][TBK * BSTR];

    const int tid = threadIdx.x;
    const int row0 = blockIdx.y * TBM;
    const int col0 = blockIdx.x * TBN;
    const int wid = tid >> 5, lane = tid & 31;
    const int wm = wid >> 2, wn = wid & 3;      // 2 x 4 warp grid
    const int g = lane >> 2, tg = lane & 3;

    // gmem load mapping
    const int am = tid >> 2;            // 0..63 (+64)
    const int ak = (tid & 3) * 4;       // 0,4,8,12
    const int br0 = tid >> 5;           // 0..7  (+8)
    const int bc0 = (tid & 31) * 4;     // 0..124

    const bool mok0 = (row0 + am) < M;
    const bool mok1 = (row0 + am + 64) < M;
    // clamp row so the pointer itself is always valid
    const int amr0 = mok0 ? (row0 + am) : (M - 1);
    const int amr1 = mok1 ? (row0 + am + 64) : (M - 1);

    const float* Ag0 = A + (size_t)amr0 * K + ak;
    const float* Ag1 = A + (size_t)amr1 * K + ak;
    const float* Bg = B + (size_t)br0 * N + col0 + bc0;

    float acc[4][4][4];
    #pragma unroll
    for (int i = 0; i < 4; i++)
        #pragma unroll
        for (int j = 0; j < 4; j++)
            #pragma unroll
            for (int r = 0; r < 4; r++) acc[i][j][r] = 0.0f;

    const int KT = K / TBK;
    float4 ra[2], rb[2];
    const float4 z4 = make_float4(0.f, 0.f, 0.f, 0.f);

    // ---- prologue: tile 0 -> regs -> smem[0]; tile 1 -> regs ----
    ra[0] = mok0 ? *(const float4*)(Ag0) : z4;
    ra[1] = mok1 ? *(const float4*)(Ag1) : z4;
    rb[0] = *(const float4*)(Bg);
    rb[1] = *(const float4*)(Bg + (size_t)8 * N);
    {
        float* pa0 = &As[0][am * ASTR + ak];
        pa0[0] = __uint_as_float(f2tf(ra[0].x));
        pa0[1] = __uint_as_float(f2tf(ra[0].y));
        pa0[2] = __uint_as_float(f2tf(ra[0].z));
        pa0[3] = __uint_as_float(f2tf(ra[0].w));
        float* pa1 = &As[0][(am + 64) * ASTR + ak];
        pa1[0] = __uint_as_float(f2tf(ra[1].x));
        pa1[1] = __uint_as_float(f2tf(ra[1].y));
        pa1[2] = __uint_as_float(f2tf(ra[1].z));
        pa1[3] = __uint_as_float(f2tf(ra[1].w));
        float* pb0 = &Bs[0][br0 * BSTR + bc0];
        pb0[0] = __uint_as_float(f2tf(rb[0].x));
        pb0[1] = __uint_as_float(f2tf(rb[0].y));
        pb0[2] = __uint_as_float(f2tf(rb[0].z));
        pb0[3] = __uint_as_float(f2tf(rb[0].w));
        float* pb1 = &Bs[0][(br0 + 8) * BSTR + bc0];
        pb1[0] = __uint_as_float(f2tf(rb[1].x));
        pb1[1] = __uint_as_float(f2tf(rb[1].y));
        pb1[2] = __uint_as_float(f2tf(rb[1].z));
        pb1[3] = __uint_as_float(f2tf(rb[1].w));
    }
    if (KT > 1) {
        ra[0] = mok0 ? *(const float4*)(Ag0 + TBK) : z4;
        ra[1] = mok1 ? *(const float4*)(Ag1 + TBK) : z4;
        rb[0] = *(const float4*)(Bg + (size_t)TBK * N);
        rb[1] = *(const float4*)(Bg + (size_t)(TBK + 8) * N);
    }
    __syncthreads();

    #pragma unroll 1
    for (int kt = 0; kt < KT; kt++) {
        const int cur = kt & 1;
        const int nxt = cur ^ 1;

        // store prefetched tile kt+1 into the other buffer (overlaps MMA pipe)
        if (kt + 1 < KT) {
            float* pa0 = &As[nxt][am * ASTR + ak];
            pa0[0] = __uint_as_float(f2tf(ra[0].x));
            pa0[1] = __uint_as_float(f2tf(ra[0].y));
            pa0[2] = __uint_as_float(f2tf(ra[0].z));
            pa0[3] = __uint_as_float(f2tf(ra[0].w));
            float* pa1 = &As[nxt][(am + 64) * ASTR + ak];
            pa1[0] = __uint_as_float(f2tf(ra[1].x));
            pa1[1] = __uint_as_float(f2tf(ra[1].y));
            pa1[2] = __uint_as_float(f2tf(ra[1].z));
            pa1[3] = __uint_as_float(f2tf(ra[1].w));
            float* pb0 = &Bs[nxt][br0 * BSTR + bc0];
            pb0[0] = __uint_as_float(f2tf(rb[0].x));
            pb0[1] = __uint_as_float(f2tf(rb[0].y));
            pb0[2] = __uint_as_float(f2tf(rb[0].z));
            pb0[3] = __uint_as_float(f2tf(rb[0].w));
            float* pb1 = &Bs[nxt][(br0 + 8) * BSTR + bc0];
            pb1[0] = __uint_as_float(f2tf(rb[1].x));
            pb1[1] = __uint_as_float(f2tf(rb[1].y));
            pb1[2] = __uint_as_float(f2tf(rb[1].z));
            pb1[3] = __uint_as_float(f2tf(rb[1].w));
        }
        // prefetch tile kt+2 into registers (gmem latency hidden by MMA)
        if (kt + 2 < KT) {
            const float* a0 = Ag0 + (kt + 2) * TBK;
            const float* a1 = Ag1 + (kt + 2) * TBK;
            const float* bg = Bg + (size_t)(kt + 2) * TBK * N;
            ra[0] = mok0 ? *(const float4*)(a0) : z4;
            ra[1] = mok1 ? *(const float4*)(a1) : z4;
            rb[0] = *(const float4*)(bg);
            rb[1] = *(const float4*)(bg + (size_t)8 * N);
        }

        // compute on current buffer: two k8 steps
        #pragma unroll
        for (int k8 = 0; k8 < 2; k8++) {
            unsigned int af[4][4], bf[4][2];
            #pragma unroll
            for (int i = 0; i < 4; i++) {
                const float* p = &As[cur][(wm * 64 + i * 16 + g) * ASTR + k8 * 8 + tg];
                af[i][0] = __float_as_uint(p[0]);
                af[i][1] = __float_as_uint(p[8 * ASTR]);
                af[i][2] = __float_as_uint(p[4]);
                af[i][3] = __float_as_uint(p[8 * ASTR + 4]);
            }
            #pragma unroll
            for (int j = 0; j < 4; j++) {
                const float* p = &Bs[cur][(k8 * 8 + tg) * BSTR + wn * 32 + j * 8 + g];
                bf[j][0] = __float_as_uint(p[0]);
                bf[j][1] = __float_as_uint(p[4 * BSTR]);
            }
            #pragma unroll
            for (int i = 0; i < 4; i++)
                #pragma unroll
                for (int j = 0; j < 4; j++) {
                    asm volatile(
                        "mma.sync.aligned.m16n8k8.row.col.f32.tf32.tf32.f32 "
                        "{%0,%1,%2,%3}, {%4,%5,%6,%7}, {%8,%9}, {%0,%1,%2,%3};"
                        : "+f"(acc[i][j][0]), "+f"(acc[i][j][1]),
                          "+f"(acc[i][j][2]), "+f"(acc[i][j][3])
                        : "r"(af[i][0]), "r"(af[i][1]), "r"(af[i][2]), "r"(af[i][3]),
                          "r"(bf[j][0]), "r"(bf[j][1]));
                }
        }
        __syncthreads();
    }

    // epilogue (M-guarded)
    #pragma unroll
    for (int i = 0; i < 4; i++) {
        #pragma unroll
        for (int j = 0; j < 4; j++) {
            int row = row0 + wm * 64 + i * 16 + g;
            int col = col0 + wn * 32 + j * 8 + tg * 2;
            float b0 = 0.f, b1 = 0.f;
            if (bias != nullptr) { b0 = bias[col]; b1 = bias[col + 1]; }
            if (row < M) {
                float2 v0 = make_float2(acc[i][j][0] + b0, acc[i][j][1] + b1);
                *(float2*)(C + (size_t)row * N + col) = v0;
            }
            if (row + 8 < M) {
                float2 v1 = make_float2(acc[i][j][2] + b0, acc[i][j][3] + b1);
                *(float2*)(C + (size_t)(row + 8) * N + col) = v1;
            }
        }
    }
}

// ---------------- CORA prep ----------------
__global__ __launch_bounds__(256) void cora_prep(
    const float* __restrict__ target, const float* __restrict__ anchor,
    const float* __restrict__ pres,
    float* __restrict__ uhat, float* __restrict__ ahat, float* __restrict__ Gout)
{
    __shared__ float red[32];
    __shared__ float ud[CC], ad[CC];
    const int s = blockIdx.x, tid = threadIdx.x;
    const float* p0 = pres + (size_t)s * CC;
    const float* p1 = pres + (size_t)(SS + s) * CC;
    const float* tg = target + (size_t)s * CC;
    const float* an = anchor + (size_t)s * CC;

    float g00 = 0, g01 = 0, g11 = 0, bt0 = 0, bt1 = 0, ba0 = 0, ba1 = 0;
    for (int d = tid; d < CC; d += 256) {
        float a = p0[d], b = p1[d], t = tg[d], u = an[d];
        g00 += a * a; g01 += a * b; g11 += b * b;
        bt0 += a * t; bt1 += b * t;
        ba0 += a * u; ba1 += b * u;
    }
    g00 = blockSum(g00, red); g01 = blockSum(g01, red); g11 = blockSum(g11, red);
    bt0 = blockSum(bt0, red); bt1 = blockSum(bt1, red);
    ba0 = blockSum(ba0, red); ba1 = blockSum(ba1, red);

    float det = g00 * g11 - g01 * g01;
    float ct0 = (g11 * bt0 - g01 * bt1) / det, ct1 = (g00 * bt1 - g01 * bt0) / det;
    float ca0 = (g11 * ba0 - g01 * ba1) / det, ca1 = (g00 * ba1 - g01 * ba0) / det;

    float nu2 = 0;
    for (int d = tid; d < CC; d += 256) {
        float udv = tg[d] - (p0[d] * ct0 + p1[d] * ct1);
        float adv = an[d] - (p0[d] * ca0 + p1[d] * ca1);
        ud[d] = udv; ad[d] = adv;
        nu2 += udv * udv;
    }
    nu2 = blockSum(nu2, red);
    float nu = sqrtf(nu2) + EPSI;

    float dua = 0;
    for (int d = tid; d < CC; d += 256) {
        float uh = ud[d] / nu;
        ud[d] = uh;
        uhat[(size_t)s * CC + d] = uh;
        dua += uh * ad[d];
    }
    dua = blockSum(dua, red);

    float na2 = 0;
    for (int d = tid; d < CC; d += 256) {
        float at = ad[d] - dua * ud[d];
        ad[d] = at;
        na2 += at * at;
    }
    na2 = blockSum(na2, red);
    float na = sqrtf(na2) + EPSI;

    for (int d = tid; d < CC; d += 256)
        ahat[(size_t)s * CC + d] = ad[d] / na;

    if (tid == 0) { Gout[s * 3 + 0] = g00; Gout[s * 3 + 1] = g01; Gout[s * 3 + 2] = g11; }
}

// ---------------- CORA apply ----------------
__global__ __launch_bounds__(256) void cora_apply(
    const float* __restrict__ Vin, const float* __restrict__ pres,
    const float* __restrict__ G, const float* __restrict__ uhat,
    const float* __restrict__ ahat, float* __restrict__ Ve)
{
    __shared__ float red[32];
    const int bs = blockIdx.x, s = bs % SS, tid = threadIdx.x;
    const float* v = Vin + (size_t)bs * CC;
    const float* p0 = pres + (size_t)s * CC;
    const float* p1 = pres + (size_t)(SS + s) * CC;
    const float* uh = uhat + (size_t)s * CC;
    const float* ah = ahat + (size_t)s * CC;

    float b0 = 0, b1 = 0;
    for (int d = tid; d < CC; d += 256) {
        float vd = v[d];
        b0 += p0[d] * vd; b1 += p1[d] * vd;
    }
    b0 = blockSum(b0, red); b1 = blockSum(b1, red);

    float g00 = G[s * 3], g01 = G[s * 3 + 1], g11 = G[s * 3 + 2];
    float det = g00 * g11 - g01 * g01;
    float c0 = (g11 * b0 - g01 * b1) / det;
    float c1 = (g00 * b1 - g01 * b0) / det;

    float nf2 = 0, t = 0;
    for (int d = tid; d < CC; d += 256) {
        float vp = p0[d] * c0 + p1[d] * c1;
        float vf = v[d] - vp;
        nf2 += vf * vf;
        t += uh[d] * vf;
    }
    nf2 = blockSum(nf2, red);
    t = blockSum(t, red);

    float denom = sqrtf(nf2) + EPSI;
    bool keep = (fabsf(t) / denom) < TAU;

    for (int d = tid; d < CC; d += 256) {
        float vp = p0[d] * c0 + p1[d] * c1;
        float vf = v[d] - vp;
        float vn = vp + vf - t * uh[d] + BETA * t * ah[d];
        Ve[(size_t)bs * CC + d] = keep ? v[d] : vn;
    }
}

// ---------------- fused attention ----------------
#define ATTN_SMEM_BYTES ((SS * 84 * 2 + 64 * DH * 2) * 4)

__global__ __launch_bounds__(256) void attn_kernel(
    const float* __restrict__ Q, const float* __restrict__ Kp,
    const float* __restrict__ Vp, float* __restrict__ O)
{
    extern __shared__ float sm[];
    float* Ks = sm;
    float* Vs = Ks + SS * 84;
    float* Qs = Vs + SS * 84;
    float* Ps = Qs + 64 * DH;

    const int b = blockIdx.z, h = blockIdx.y;
    const int n0 = blockIdx.x * 64;
    const int tid = threadIdx.x;

    for (int i = tid; i < SS * DH; i += 256) {
        int s = i / DH, d = i % DH;
        size_t goff = ((size_t)(b * SS + s)) * CC + h * DH + d;
        Ks[s * 84 + d] = Kp[goff];
        Vs[s * 84 + d] = Vp[goff];
    }
    for (int i = tid; i < 64 * DH; i += 256) {
        int r = i / DH, d = i % DH;
        Qs[r * DH + d] = Q[((size_t)b * NN + n0 + r) * CC + h * DH + d];
    }
    __syncthreads();

    const int w = tid >> 5, l = tid & 31;
    const int rbase = w * 8;

    float acc[8][3];
    #pragma unroll
    for (int r = 0; r < 8; r++)
        #pragma unroll
        for (int c = 0; c < 3; c++) acc[r][c] = 0.0f;

    const float4* Ks4 = (const float4*)Ks;
    #pragma unroll 4
    for (int dc = 0; dc < DH / 4; dc++) {
        float4 kv[3];
        #pragma unroll
        for (int c = 0; c < 3; c++) {
            int s = l + 32 * c;
            kv[c] = (s < SS) ? Ks4[s * 21 + dc] : make_float4(0.f, 0.f, 0.f, 0.f);
        }
        #pragma unroll
        for (int r = 0; r < 8; r++) {
            float4 qv = *(const float4*)(Qs + (rbase + r) * DH + dc * 4);
            #pragma unroll
            for (int c = 0; c < 3; c++)
                acc[r][c] += qv.x * kv[c].x + qv.y * kv[c].y + qv.z * kv[c].z + qv.w * kv[c].w;
        }
    }

    const float scale = 0.11180339887498948f;
    #pragma unroll
    for (int r = 0; r < 8; r++) {
        float m = -1e30f;
        #pragma unroll
        for (int c = 0; c < 3; c++) {
            int s = l + 32 * c;
            float vsc = (s < SS) ? acc[r][c] * scale : -1e30f;
            acc[r][c] = vsc;
            m = fmaxf(m, vsc);
        }
        #pragma unroll
        for (int o = 16; o; o >>= 1) m = fmaxf(m, __shfl_xor_sync(0xffffffffu, m, o));
        float sum = 0.f;
        #pragma unroll
        for (int c = 0; c < 3; c++) {
            int s = l + 32 * c;
            float e = (s < SS) ? expf(acc[r][c] - m) : 0.f;
            acc[r][c] = e;
            sum += e;
        }
        #pragma unroll
        for (int o = 16; o; o >>= 1) sum += __shfl_xor_sync(0xffffffffu, sum, o);
        float inv = 1.0f / sum;
        #pragma unroll
        for (int c = 0; c < 3; c++) {
            int s = l + 32 * c;
            if (s < SS) Ps[(rbase + r) * DH + s] = acc[r][c] * inv;
        }
    }
    __syncwarp();

    float oacc[8][3];
    #pragma unroll
    for (int r = 0; r < 8; r++)
        #pragma unroll
        for (int j = 0; j < 3; j++) oacc[r][j] = 0.0f;

    for (int s = 0; s < SS; s++) {
        float vv[3];
        #pragma unroll
        for (int j = 0; j < 3; j++) {
            int d = l + 32 * j;
            vv[j] = (d < DH) ? Vs[s * 84 + d] : 0.f;
        }
        #pragma unroll
        for (int r = 0; r < 8; r++) {
            float pv = Ps[(rbase + r) * DH + s];
            #pragma unroll
            for (int j = 0; j < 3; j++) oacc[r][j] += pv * vv[j];
        }
    }

    #pragma unroll
    for (int r = 0; r < 8; r++)
        #pragma unroll
        for (int j = 0; j < 3; j++) {
            int d = l + 32 * j;
            if (d < DH)
                O[((size_t)b * NN + n0 + rbase + r) * CC + h * DH + d] = oacc[r][j];
        }
}

// ---------------- launch ----------------
extern "C" void kernel_launch(void* const* d_in, const int* in_sizes, int n_in,
                              void* d_out, int out_size)
{
    static float *Qb = nullptr, *Attn = nullptr, *Kb = nullptr, *Vb = nullptr,
                 *Veb = nullptr, *Uh = nullptr, *Ah = nullptr, *Gm = nullptr;
    static bool init = false;
    if (!init) {
        cudaGetSymbolAddress((void**)&Qb, g_Q);
        cudaGetSymbolAddress((void**)&Attn, g_attn);
        cudaGetSymbolAddress((void**)&Kb, g_K);
        cudaGetSymbolAddress((void**)&Vb, g_V);
        cudaGetSymbolAddress((void**)&Veb, g_Ve);
        cudaGetSymbolAddress((void**)&Uh, g_uhat);
        cudaGetSymbolAddress((void**)&Ah, g_ahat);
        cudaGetSymbolAddress((void**)&Gm, g_G);
        cudaFuncSetAttribute(attn_kernel, cudaFuncAttributeMaxDynamicSharedMemorySize,
                             ATTN_SMEM_BYTES);
        init = true;
    }

    const float* X    = (const float*)d_in[0];
    const float* E    = (const float*)d_in[1];
    const float* Wq   = (const float*)d_in[2];
    const float* Wk   = (const float*)d_in[3];
    const float* Wv   = (const float*)d_in[4];
    const float* Wo   = (const float*)d_in[5];
    const float* bo   = (const float*)d_in[6];
    const float* tgt  = (const float*)d_in[7];
    const float* anc  = (const float*)d_in[8];
    const float* pres = (const float*)d_in[9];
    float* out = (float*)d_out;

    // Q projection: tf32 tensor cores. [32768,640] x [640,640]
    gemm_tf32<<<dim3(CC / TBN, (BB * NN) / TBM), 256>>>(
        X, Wq, nullptr, Qb, BB * NN, CC, CC);

    // K,V projections: tf32 tensor cores (M=616 guarded). [616,768] x [768,640]
    gemm_tf32<<<dim3(CC / TBN, (BB * SS + TBM - 1) / TBM), 256>>>(
        E, Wk, nullptr, Kb, BB * SS, XD, CC);
    gemm_tf32<<<dim3(CC / TBN, (BB * SS + TBM - 1) / TBM), 256>>>(
        E, Wv, nullptr, Vb, BB * SS, XD, CC);

    // CORA erase on V
    cora_prep<<<SS, 256>>>(tgt, anc, pres, Uh, Ah, Gm);
    cora_apply<<<BB * SS, 256>>>(Vb, pres, Gm, Uh, Ah, Veb);

    // fused attention
    attn_kernel<<<dim3(NN / 64, HH, BB), 256, ATTN_SMEM_BYTES>>>(Qb, Kb, Veb, Attn);

    // output projection + bias: tf32 tensor cores
    gemm_tf32<<<dim3(CC / TBN, (BB * NN) / TBM), 256>>>(
        Attn, Wo, bo, out, BB * NN, CC, CC);
}

// round 6
// speedup vs baseline: 2.1005x; 1.1751x over previous
#include <cuda_runtime.h>
#include <cuda_fp16.h>
#include <math.h>
#include <stdint.h>

// Problem constants
#define BB 8
#define NN 4096
#define CC 640
#define SS 77
#define XD 768
#define HH 8
#define DH 80
#define BETA 0.5f
#define TAU 0.1f
#define EPSI 1e-8f

// ---------------- scratch (no cudaMalloc allowed) ----------------
__device__ float g_Q[BB * NN * CC];      // 83.9 MB
__device__ float g_attn[BB * NN * CC];   // 83.9 MB
__device__ float g_K[BB * SS * CC];
__device__ float g_V[BB * SS * CC];
__device__ float g_Ve[BB * SS * CC];
__device__ float g_uhat[SS * CC];
__device__ float g_ahat[SS * CC];
__device__ float g_G[SS * 3];
__device__ __half g_Wh[4][XD * CC];      // transposed fp16 weights [n][k]

// ---------------- block reduce helper ----------------
__device__ __forceinline__ float blockSum(float v, float* red) {
    #pragma unroll
    for (int o = 16; o; o >>= 1) v += __shfl_xor_sync(0xffffffffu, v, o);
    int w = threadIdx.x >> 5, l = threadIdx.x & 31;
    __syncthreads();
    if (l == 0) red[w] = v;
    __syncthreads();
    if (w == 0) {
        float x = (l < (int)(blockDim.x >> 5)) ? red[l] : 0.0f;
        #pragma unroll
        for (int o = 4; o; o >>= 1) x += __shfl_xor_sync(0xffffffffu, x, o);
        if (l == 0) red[0] = x;
    }
    __syncthreads();
    return red[0];
}

// ---------------- weight transpose + fp16 convert: Wt[n,k] = h(W[k,n]) ------
__global__ __launch_bounds__(256) void transpose_h(
    const float* __restrict__ W, __half* __restrict__ Wt, int K, int N)
{
    __shared__ float t[32][33];
    const int k0 = blockIdx.y * 32, n0 = blockIdx.x * 32;
    const int tx = threadIdx.x & 31, ty = threadIdx.x >> 5;   // 32 x 8
    #pragma unroll
    for (int i = ty; i < 32; i += 8) {
        int k = k0 + i, n = n0 + tx;
        if (k < K && n < N) t[i][tx] = W[(size_t)k * N + n];
    }
    __syncthreads();
    #pragma unroll
    for (int i = ty; i < 32; i += 8) {
        int n = n0 + i, k = k0 + tx;
        if (k < K && n < N)
            Wt[(size_t)n * K + k] = __float2half_rn(t[tx][i]);
    }
}

// =====================================================================
// FP16 tensor-core GEMM: C[M,640] = A[M,K] @ W[K,640] (W given as Wt[640,K] fp16)
// Tile 128x128x32, 256 threads (8 warps 2x4), warp tile 64x32,
// mma.sync m16n8k16 f16 (fp32 accum), double-buffered smem + reg prefetch.
// M guarded; requires K % 32 == 0.
// =====================================================================
#define HBK 32
#define HSTR 40          // halfs per smem row (pad 32 -> 40: conflict-free frags)

__global__ __launch_bounds__(256) void gemm_fp16(
    const float* __restrict__ A, const __half* __restrict__ Bt,
    const float* __restrict__ bias, float* __restrict__ C,
    int M, int K)
{
    __shared__ __half As[2][128 * HSTR];
    __shared__ __half Bs[2][128 * HSTR];

    const int tid = threadIdx.x;
    const int wid = tid >> 5, lane = tid & 31;
    const int wm = wid >> 2, wn = wid & 3;    // 2 x 4 warp grid
    const int g = lane >> 2, tg = lane & 3;
    const int row0 = blockIdx.y * 128, col0 = blockIdx.x * 128;

    // gmem<->smem mapping: 4 chunks, each thread handles row lr+j*32, 4 cols
    const int lr = tid >> 3;            // 0..31
    const int lc = (tid & 7) * 4;       // 0,4,..,28

    float acc[4][4][4];
    #pragma unroll
    for (int i = 0; i < 4; i++)
        #pragma unroll
        for (int j = 0; j < 4; j++)
            #pragma unroll
            for (int r = 0; r < 4; r++) acc[i][j][r] = 0.0f;

    const int KT = K / HBK;
    const float4 z4 = make_float4(0.f, 0.f, 0.f, 0.f);

    bool mok[4];
    const float* Agp[4];
    const __half* Bgp[4];
    #pragma unroll
    for (int j = 0; j < 4; j++) {
        int r = row0 + lr + j * 32;
        mok[j] = r < M;
        Agp[j] = A + (size_t)(mok[j] ? r : (M - 1)) * K + lc;
        Bgp[j] = Bt + (size_t)(col0 + lr + j * 32) * K + lc;
    }

    float4 ra[4];
    uint2 rb[4];

    // ---- tile 0 -> smem[0] ----
    #pragma unroll
    for (int j = 0; j < 4; j++) {
        ra[j] = mok[j] ? *(const float4*)(Agp[j]) : z4;
        rb[j] = *(const uint2*)(Bgp[j]);
    }
    #pragma unroll
    for (int j = 0; j < 4; j++) {
        __half2 h0 = __floats2half2_rn(ra[j].x, ra[j].y);
        __half2 h1 = __floats2half2_rn(ra[j].z, ra[j].w);
        *(__half2*)&As[0][(lr + j * 32) * HSTR + lc] = h0;
        *(__half2*)&As[0][(lr + j * 32) * HSTR + lc + 2] = h1;
        *(uint2*)&Bs[0][(lr + j * 32) * HSTR + lc] = rb[j];
    }
    // prefetch tile 1
    if (KT > 1) {
        #pragma unroll
        for (int j = 0; j < 4; j++) {
            ra[j] = mok[j] ? *(const float4*)(Agp[j] + HBK) : z4;
            rb[j] = *(const uint2*)(Bgp[j] + HBK);
        }
    }
    __syncthreads();

    #pragma unroll 1
    for (int kt = 0; kt < KT; kt++) {
        const int cur = kt & 1;
        const int nxt = cur ^ 1;

        // store prefetched tile kt+1 (overlaps MMA below)
        if (kt + 1 < KT) {
            #pragma unroll
            for (int j = 0; j < 4; j++) {
                __half2 h0 = __floats2half2_rn(ra[j].x, ra[j].y);
                __half2 h1 = __floats2half2_rn(ra[j].z, ra[j].w);
                *(__half2*)&As[nxt][(lr + j * 32) * HSTR + lc] = h0;
                *(__half2*)&As[nxt][(lr + j * 32) * HSTR + lc + 2] = h1;
                *(uint2*)&Bs[nxt][(lr + j * 32) * HSTR + lc] = rb[j];
            }
        }
        // prefetch tile kt+2 into regs
        if (kt + 2 < KT) {
            #pragma unroll
            for (int j = 0; j < 4; j++) {
                ra[j] = mok[j] ? *(const float4*)(Agp[j] + (kt + 2) * HBK) : z4;
                rb[j] = *(const uint2*)(Bgp[j] + (kt + 2) * HBK);
            }
        }

        // compute: two k16 steps on current buffer
        const unsigned int* Au = (const unsigned int*)&As[cur][0];
        const unsigned int* Bu = (const unsigned int*)&Bs[cur][0];
        #pragma unroll
        for (int k16 = 0; k16 < 2; k16++) {
            unsigned int af[4][4], bf[4][2];
            #pragma unroll
            for (int i = 0; i < 4; i++) {
                const unsigned int* p = Au + (wm * 64 + i * 16 + g) * (HSTR / 2) + k16 * 8 + tg;
                af[i][0] = p[0];
                af[i][1] = p[8 * (HSTR / 2)];
                af[i][2] = p[4];
                af[i][3] = p[8 * (HSTR / 2) + 4];
            }
            #pragma unroll
            for (int jn = 0; jn < 4; jn++) {
                const unsigned int* p = Bu + (wn * 32 + jn * 8 + g) * (HSTR / 2) + k16 * 8 + tg;
                bf[jn][0] = p[0];
                bf[jn][1] = p[4];
            }
            #pragma unroll
            for (int i = 0; i < 4; i++)
                #pragma unroll
                for (int jn = 0; jn < 4; jn++) {
                    asm volatile(
                        "mma.sync.aligned.m16n8k16.row.col.f32.f16.f16.f32 "
                        "{%0,%1,%2,%3}, {%4,%5,%6,%7}, {%8,%9}, {%0,%1,%2,%3};"
                        : "+f"(acc[i][jn][0]), "+f"(acc[i][jn][1]),
                          "+f"(acc[i][jn][2]), "+f"(acc[i][jn][3])
                        : "r"(af[i][0]), "r"(af[i][1]), "r"(af[i][2]), "r"(af[i][3]),
                          "r"(bf[jn][0]), "r"(bf[jn][1]));
                }
        }
        __syncthreads();
    }

    // epilogue (M-guarded), fp32 + bias
    #pragma unroll
    for (int i = 0; i < 4; i++) {
        #pragma unroll
        for (int jn = 0; jn < 4; jn++) {
            int row = row0 + wm * 64 + i * 16 + g;
            int col = col0 + wn * 32 + jn * 8 + tg * 2;
            float b0 = 0.f, b1 = 0.f;
            if (bias != nullptr) { b0 = bias[col]; b1 = bias[col + 1]; }
            if (row < M) {
                float2 v0 = make_float2(acc[i][jn][0] + b0, acc[i][jn][1] + b1);
                *(float2*)(C + (size_t)row * CC + col) = v0;
            }
            if (row + 8 < M) {
                float2 v1 = make_float2(acc[i][jn][2] + b0, acc[i][jn][3] + b1);
                *(float2*)(C + (size_t)(row + 8) * CC + col) = v1;
            }
        }
    }
}

// ---------------- CORA prep ----------------
__global__ __launch_bounds__(256) void cora_prep(
    const float* __restrict__ target, const float* __restrict__ anchor,
    const float* __restrict__ pres,
    float* __restrict__ uhat, float* __restrict__ ahat, float* __restrict__ Gout)
{
    __shared__ float red[32];
    __shared__ float ud[CC], ad[CC];
    const int s = blockIdx.x, tid = threadIdx.x;
    const float* p0 = pres + (size_t)s * CC;
    const float* p1 = pres + (size_t)(SS + s) * CC;
    const float* tg = target + (size_t)s * CC;
    const float* an = anchor + (size_t)s * CC;

    float g00 = 0, g01 = 0, g11 = 0, bt0 = 0, bt1 = 0, ba0 = 0, ba1 = 0;
    for (int d = tid; d < CC; d += 256) {
        float a = p0[d], b = p1[d], t = tg[d], u = an[d];
        g00 += a * a; g01 += a * b; g11 += b * b;
        bt0 += a * t; bt1 += b * t;
        ba0 += a * u; ba1 += b * u;
    }
    g00 = blockSum(g00, red); g01 = blockSum(g01, red); g11 = blockSum(g11, red);
    bt0 = blockSum(bt0, red); bt1 = blockSum(bt1, red);
    ba0 = blockSum(ba0, red); ba1 = blockSum(ba1, red);

    float det = g00 * g11 - g01 * g01;
    float ct0 = (g11 * bt0 - g01 * bt1) / det, ct1 = (g00 * bt1 - g01 * bt0) / det;
    float ca0 = (g11 * ba0 - g01 * ba1) / det, ca1 = (g00 * ba1 - g01 * ba0) / det;

    float nu2 = 0;
    for (int d = tid; d < CC; d += 256) {
        float udv = tg[d] - (p0[d] * ct0 + p1[d] * ct1);
        float adv = an[d] - (p0[d] * ca0 + p1[d] * ca1);
        ud[d] = udv; ad[d] = adv;
        nu2 += udv * udv;
    }
    nu2 = blockSum(nu2, red);
    float nu = sqrtf(nu2) + EPSI;

    float dua = 0;
    for (int d = tid; d < CC; d += 256) {
        float uh = ud[d] / nu;
        ud[d] = uh;
        uhat[(size_t)s * CC + d] = uh;
        dua += uh * ad[d];
    }
    dua = blockSum(dua, red);

    float na2 = 0;
    for (int d = tid; d < CC; d += 256) {
        float at = ad[d] - dua * ud[d];
        ad[d] = at;
        na2 += at * at;
    }
    na2 = blockSum(na2, red);
    float na = sqrtf(na2) + EPSI;

    for (int d = tid; d < CC; d += 256)
        ahat[(size_t)s * CC + d] = ad[d] / na;

    if (tid == 0) { Gout[s * 3 + 0] = g00; Gout[s * 3 + 1] = g01; Gout[s * 3 + 2] = g11; }
}

// ---------------- CORA apply ----------------
__global__ __launch_bounds__(256) void cora_apply(
    const float* __restrict__ Vin, const float* __restrict__ pres,
    const float* __restrict__ G, const float* __restrict__ uhat,
    const float* __restrict__ ahat, float* __restrict__ Ve)
{
    __shared__ float red[32];
    const int bs = blockIdx.x, s = bs % SS, tid = threadIdx.x;
    const float* v = Vin + (size_t)bs * CC;
    const float* p0 = pres + (size_t)s * CC;
    const float* p1 = pres + (size_t)(SS + s) * CC;
    const float* uh = uhat + (size_t)s * CC;
    const float* ah = ahat + (size_t)s * CC;

    float b0 = 0, b1 = 0;
    for (int d = tid; d < CC; d += 256) {
        float vd = v[d];
        b0 += p0[d] * vd; b1 += p1[d] * vd;
    }
    b0 = blockSum(b0, red); b1 = blockSum(b1, red);

    float g00 = G[s * 3], g01 = G[s * 3 + 1], g11 = G[s * 3 + 2];
    float det = g00 * g11 - g01 * g01;
    float c0 = (g11 * b0 - g01 * b1) / det;
    float c1 = (g00 * b1 - g01 * b0) / det;

    float nf2 = 0, t = 0;
    for (int d = tid; d < CC; d += 256) {
        float vp = p0[d] * c0 + p1[d] * c1;
        float vf = v[d] - vp;
        nf2 += vf * vf;
        t += uh[d] * vf;
    }
    nf2 = blockSum(nf2, red);
    t = blockSum(t, red);

    float denom = sqrtf(nf2) + EPSI;
    bool keep = (fabsf(t) / denom) < TAU;

    for (int d = tid; d < CC; d += 256) {
        float vp = p0[d] * c0 + p1[d] * c1;
        float vf = v[d] - vp;
        float vn = vp + vf - t * uh[d] + BETA * t * ah[d];
        Ve[(size_t)bs * CC + d] = keep ? v[d] : vn;
    }
}

// ---------------- fused attention ----------------
#define ATTN_SMEM_BYTES ((SS * 84 * 2 + 64 * DH * 2) * 4)

__global__ __launch_bounds__(256) void attn_kernel(
    const float* __restrict__ Q, const float* __restrict__ Kp,
    const float* __restrict__ Vp, float* __restrict__ O)
{
    extern __shared__ float smf[];
    float* Ks = smf;
    float* Vs = Ks + SS * 84;
    float* Qs = Vs + SS * 84;
    float* Ps = Qs + 64 * DH;

    const int b = blockIdx.z, h = blockIdx.y;
    const int n0 = blockIdx.x * 64;
    const int tid = threadIdx.x;

    for (int i = tid; i < SS * DH; i += 256) {
        int s = i / DH, d = i % DH;
        size_t goff = ((size_t)(b * SS + s)) * CC + h * DH + d;
        Ks[s * 84 + d] = Kp[goff];
        Vs[s * 84 + d] = Vp[goff];
    }
    for (int i = tid; i < 64 * DH; i += 256) {
        int r = i / DH, d = i % DH;
        Qs[r * DH + d] = Q[((size_t)b * NN + n0 + r) * CC + h * DH + d];
    }
    __syncthreads();

    const int w = tid >> 5, l = tid & 31;
    const int rbase = w * 8;

    float acc[8][3];
    #pragma unroll
    for (int r = 0; r < 8; r++)
        #pragma unroll
        for (int c = 0; c < 3; c++) acc[r][c] = 0.0f;

    const float4* Ks4 = (const float4*)Ks;
    #pragma unroll 4
    for (int dc = 0; dc < DH / 4; dc++) {
        float4 kv[3];
        #pragma unroll
        for (int c = 0; c < 3; c++) {
            int s = l + 32 * c;
            kv[c] = (s < SS) ? Ks4[s * 21 + dc] : make_float4(0.f, 0.f, 0.f, 0.f);
        }
        #pragma unroll
        for (int r = 0; r < 8; r++) {
            float4 qv = *(const float4*)(Qs + (rbase + r) * DH + dc * 4);
            #pragma unroll
            for (int c = 0; c < 3; c++)
                acc[r][c] += qv.x * kv[c].x + qv.y * kv[c].y + qv.z * kv[c].z + qv.w * kv[c].w;
        }
    }

    const float scale = 0.11180339887498948f;
    #pragma unroll
    for (int r = 0; r < 8; r++) {
        float m = -1e30f;
        #pragma unroll
        for (int c = 0; c < 3; c++) {
            int s = l + 32 * c;
            float vsc = (s < SS) ? acc[r][c] * scale : -1e30f;
            acc[r][c] = vsc;
            m = fmaxf(m, vsc);
        }
        #pragma unroll
        for (int o = 16; o; o >>= 1) m = fmaxf(m, __shfl_xor_sync(0xffffffffu, m, o));
        float sum = 0.f;
        #pragma unroll
        for (int c = 0; c < 3; c++) {
            int s = l + 32 * c;
            float e = (s < SS) ? expf(acc[r][c] - m) : 0.f;
            acc[r][c] = e;
            sum += e;
        }
        #pragma unroll
        for (int o = 16; o; o >>= 1) sum += __shfl_xor_sync(0xffffffffu, sum, o);
        float inv = 1.0f / sum;
        #pragma unroll
        for (int c = 0; c < 3; c++) {
            int s = l + 32 * c;
            if (s < SS) Ps[(rbase + r) * DH + s] = acc[r][c] * inv;
        }
    }
    __syncwarp();

    float oacc[8][3];
    #pragma unroll
    for (int r = 0; r < 8; r++)
        #pragma unroll
        for (int j = 0; j < 3; j++) oacc[r][j] = 0.0f;

    for (int s = 0; s < SS; s++) {
        float vv[3];
        #pragma unroll
        for (int j = 0; j < 3; j++) {
            int d = l + 32 * j;
            vv[j] = (d < DH) ? Vs[s * 84 + d] : 0.f;
        }
        #pragma unroll
        for (int r = 0; r < 8; r++) {
            float pv = Ps[(rbase + r) * DH + s];
            #pragma unroll
            for (int j = 0; j < 3; j++) oacc[r][j] += pv * vv[j];
        }
    }

    #pragma unroll
    for (int r = 0; r < 8; r++)
        #pragma unroll
        for (int j = 0; j < 3; j++) {
            int d = l + 32 * j;
            if (d < DH)
                O[((size_t)b * NN + n0 + rbase + r) * CC + h * DH + d] = oacc[r][j];
        }
}

// ---------------- launch ----------------
extern "C" void kernel_launch(void* const* d_in, const int* in_sizes, int n_in,
                              void* d_out, int out_size)
{
    static float *Qb = nullptr, *Attn = nullptr, *Kb = nullptr, *Vb = nullptr,
                 *Veb = nullptr, *Uh = nullptr, *Ah = nullptr, *Gm = nullptr;
    static __half *Wh = nullptr;
    static bool init = false;
    if (!init) {
        cudaGetSymbolAddress((void**)&Qb, g_Q);
        cudaGetSymbolAddress((void**)&Attn, g_attn);
        cudaGetSymbolAddress((void**)&Kb, g_K);
        cudaGetSymbolAddress((void**)&Vb, g_V);
        cudaGetSymbolAddress((void**)&Veb, g_Ve);
        cudaGetSymbolAddress((void**)&Uh, g_uhat);
        cudaGetSymbolAddress((void**)&Ah, g_ahat);
        cudaGetSymbolAddress((void**)&Gm, g_G);
        cudaGetSymbolAddress((void**)&Wh, g_Wh);
        cudaFuncSetAttribute(attn_kernel, cudaFuncAttributeMaxDynamicSharedMemorySize,
                             ATTN_SMEM_BYTES);
        init = true;
    }

    const float* X    = (const float*)d_in[0];
    const float* E    = (const float*)d_in[1];
    const float* Wq   = (const float*)d_in[2];
    const float* Wk   = (const float*)d_in[3];
    const float* Wv   = (const float*)d_in[4];
    const float* Wo   = (const float*)d_in[5];
    const float* bo   = (const float*)d_in[6];
    const float* tgt  = (const float*)d_in[7];
    const float* anc  = (const float*)d_in[8];
    const float* pres = (const float*)d_in[9];
    float* out = (float*)d_out;

    __half* WqT = Wh + 0 * (XD * CC);
    __half* WkT = Wh + 1 * (XD * CC);
    __half* WvT = Wh + 2 * (XD * CC);
    __half* WoT = Wh + 3 * (XD * CC);

    // transpose + fp16-convert the 4 weight matrices
    transpose_h<<<dim3(CC / 32, CC / 32), 256>>>(Wq, WqT, CC, CC);
    transpose_h<<<dim3(CC / 32, XD / 32), 256>>>(Wk, WkT, XD, CC);
    transpose_h<<<dim3(CC / 32, XD / 32), 256>>>(Wv, WvT, XD, CC);
    transpose_h<<<dim3(CC / 32, CC / 32), 256>>>(Wo, WoT, CC, CC);

    // Q projection: [32768,640] x [640,640] (fp16 tensor cores)
    gemm_fp16<<<dim3(CC / 128, (BB * NN) / 128), 256>>>(
        X, WqT, nullptr, Qb, BB * NN, CC);

    // K,V projections: [616,768] x [768,640] (M guarded)
    gemm_fp16<<<dim3(CC / 128, (BB * SS + 127) / 128), 256>>>(
        E, WkT, nullptr, Kb, BB * SS, XD);
    gemm_fp16<<<dim3(CC / 128, (BB * SS + 127) / 128), 256>>>(
        E, WvT, nullptr, Vb, BB * SS, XD);

    // CORA erase on V
    cora_prep<<<SS, 256>>>(tgt, anc, pres, Uh, Ah, Gm);
    cora_apply<<<BB * SS, 256>>>(Vb, pres, Gm, Uh, Ah, Veb);

    // fused attention
    attn_kernel<<<dim3(NN / 64, HH, BB), 256, ATTN_SMEM_BYTES>>>(Qb, Kb, Veb, Attn);

    // output projection + bias
    gemm_fp16<<<dim3(CC / 128, (BB * NN) / 128), 256>>>(
        Attn, WoT, bo, out, BB * NN, CC);
}

// round 7
// speedup vs baseline: 2.2158x; 1.0549x over previous
#include <cuda_runtime.h>
#include <cuda_fp16.h>
#include <math.h>
#include <stdint.h>

// Problem constants
#define BB 8
#define NN 4096
#define CC 640
#define SS 77
#define XD 768
#define HH 8
#define DH 80
#define BETA 0.5f
#define TAU 0.1f
#define EPSI 1e-8f

// ---------------- scratch (no cudaMalloc allowed) ----------------
__device__ float g_Q[BB * NN * CC];        // 83.9 MB
__device__ __half g_attnh[BB * NN * CC];   // 41.9 MB (attention out, fp16)
__device__ float g_K[BB * SS * CC];
__device__ float g_V[BB * SS * CC];
__device__ float g_Ve[BB * SS * CC];
__device__ float g_uhat[SS * CC];
__device__ float g_ahat[SS * CC];
__device__ float g_G[SS * 3];
__device__ __half g_Wh[4][XD * CC];        // transposed fp16 weights [n][k]

// ---------------- block reduce helper ----------------
__device__ __forceinline__ float blockSum(float v, float* red) {
    #pragma unroll
    for (int o = 16; o; o >>= 1) v += __shfl_xor_sync(0xffffffffu, v, o);
    int w = threadIdx.x >> 5, l = threadIdx.x & 31;
    __syncthreads();
    if (l == 0) red[w] = v;
    __syncthreads();
    if (w == 0) {
        float x = (l < (int)(blockDim.x >> 5)) ? red[l] : 0.0f;
        #pragma unroll
        for (int o = 4; o; o >>= 1) x += __shfl_xor_sync(0xffffffffu, x, o);
        if (l == 0) red[0] = x;
    }
    __syncthreads();
    return red[0];
}

// ---------------- weight transpose + fp16 convert: Wt[n,k] = h(W[k,n]) ------
__global__ __launch_bounds__(256) void transpose_h(
    const float* __restrict__ W, __half* __restrict__ Wt, int K, int N)
{
    __shared__ float t[32][33];
    const int k0 = blockIdx.y * 32, n0 = blockIdx.x * 32;
    const int tx = threadIdx.x & 31, ty = threadIdx.x >> 5;   // 32 x 8
    #pragma unroll
    for (int i = ty; i < 32; i += 8) {
        int k = k0 + i, n = n0 + tx;
        if (k < K && n < N) t[i][tx] = W[(size_t)k * N + n];
    }
    __syncthreads();
    #pragma unroll
    for (int i = ty; i < 32; i += 8) {
        int n = n0 + i, k = k0 + tx;
        if (k < K && n < N)
            Wt[(size_t)n * K + k] = __float2half_rn(t[tx][i]);
    }
}

// =====================================================================
// FP16 tensor-core GEMM v2: C[M,640] = A[M,K] @ W[K,640]
// (W as Wt[640,K] fp16; A fp32 or fp16 via template)
// CTA tile 256x128x32, 8 warps (4x2), warp tile 64x64,
// mma.sync m16n8k16, double-buffered dynamic smem + reg prefetch.
// M guarded; requires K % 32 == 0.
// =====================================================================
#define HSTR 40                  // halfs per smem row (conflict-free frags)
#define AS_BUF (256 * HSTR)      // halfs per A buffer
#define BS_BUF (128 * HSTR)      // halfs per B buffer
#define GV2_SMEM ((2 * AS_BUF + 2 * BS_BUF) * 2)   // bytes = 61440

template <int AHALF>
__global__ __launch_bounds__(256) void gemm_v2(
    const void* __restrict__ Ap, const __half* __restrict__ Bt,
    const float* __restrict__ bias, float* __restrict__ C,
    int M, int K)
{
    extern __shared__ __half sh[];
    __half* Asm = sh;                    // 2 x AS_BUF
    __half* Bsm = sh + 2 * AS_BUF;       // 2 x BS_BUF

    const int tid = threadIdx.x;
    const int wid = tid >> 5, lane = tid & 31;
    const int wm = wid >> 1, wn = wid & 1;    // 4 x 2 warp grid
    const int g = lane >> 2, tg = lane & 3;
    const int row0 = blockIdx.y * 256, col0 = blockIdx.x * 128;

    const int lr = tid >> 3;            // 0..31
    const int lc = (tid & 7) * 4;       // 0,4,..,28

    float acc[4][8][4];
    #pragma unroll
    for (int i = 0; i < 4; i++)
        #pragma unroll
        for (int j = 0; j < 8; j++)
            #pragma unroll
            for (int r = 0; r < 4; r++) acc[i][j][r] = 0.0f;

    const int KT = K / 32;
    const float4 z4 = make_float4(0.f, 0.f, 0.f, 0.f);

    bool mok[8];
    const float* Agf[8];
    const __half* Agh[8];
    #pragma unroll
    for (int j = 0; j < 8; j++) {
        int r = row0 + lr + j * 32;
        mok[j] = r < M;
        int rr = mok[j] ? r : (M - 1);
        if (AHALF) Agh[j] = (const __half*)Ap + (size_t)rr * K + lc;
        else       Agf[j] = (const float*)Ap + (size_t)rr * K + lc;
    }
    const __half* Bgp[4];
    #pragma unroll
    for (int j = 0; j < 4; j++)
        Bgp[j] = Bt + (size_t)(col0 + lr + j * 32) * K + lc;

    float4 raf[8];
    uint2 rah[8];
    uint2 rb[4];

    // ---- tile 0 load ----
    #pragma unroll
    for (int j = 0; j < 8; j++) {
        if (AHALF) rah[j] = mok[j] ? *(const uint2*)(Agh[j]) : make_uint2(0u, 0u);
        else       raf[j] = mok[j] ? *(const float4*)(Agf[j]) : z4;
    }
    #pragma unroll
    for (int j = 0; j < 4; j++) rb[j] = *(const uint2*)(Bgp[j]);

    // ---- store tile 0 -> buffer 0 ----
    #pragma unroll
    for (int j = 0; j < 8; j++) {
        __half* dst = &Asm[(lr + j * 32) * HSTR + lc];
        if (AHALF) {
            *(uint2*)dst = rah[j];
        } else {
            *(__half2*)dst       = __floats2half2_rn(raf[j].x, raf[j].y);
            *(__half2*)(dst + 2) = __floats2half2_rn(raf[j].z, raf[j].w);
        }
    }
    #pragma unroll
    for (int j = 0; j < 4; j++)
        *(uint2*)&Bsm[(lr + j * 32) * HSTR + lc] = rb[j];

    // prefetch tile 1
    if (KT > 1) {
        #pragma unroll
        for (int j = 0; j < 8; j++) {
            if (AHALF) rah[j] = mok[j] ? *(const uint2*)(Agh[j] + 32) : make_uint2(0u, 0u);
            else       raf[j] = mok[j] ? *(const float4*)(Agf[j] + 32) : z4;
        }
        #pragma unroll
        for (int j = 0; j < 4; j++) rb[j] = *(const uint2*)(Bgp[j] + 32);
    }
    __syncthreads();

    #pragma unroll 1
    for (int kt = 0; kt < KT; kt++) {
        const int cur = kt & 1;
        const int nxt = cur ^ 1;

        // store prefetched tile kt+1 (overlaps MMA below)
        if (kt + 1 < KT) {
            #pragma unroll
            for (int j = 0; j < 8; j++) {
                __half* dst = &Asm[nxt * AS_BUF + (lr + j * 32) * HSTR + lc];
                if (AHALF) {
                    *(uint2*)dst = rah[j];
                } else {
                    *(__half2*)dst       = __floats2half2_rn(raf[j].x, raf[j].y);
                    *(__half2*)(dst + 2) = __floats2half2_rn(raf[j].z, raf[j].w);
                }
            }
            #pragma unroll
            for (int j = 0; j < 4; j++)
                *(uint2*)&Bsm[nxt * BS_BUF + (lr + j * 32) * HSTR + lc] = rb[j];
        }
        // prefetch tile kt+2
        if (kt + 2 < KT) {
            #pragma unroll
            for (int j = 0; j < 8; j++) {
                if (AHALF) rah[j] = mok[j] ? *(const uint2*)(Agh[j] + (kt + 2) * 32) : make_uint2(0u, 0u);
                else       raf[j] = mok[j] ? *(const float4*)(Agf[j] + (kt + 2) * 32) : z4;
            }
            #pragma unroll
            for (int j = 0; j < 4; j++) rb[j] = *(const uint2*)(Bgp[j] + (kt + 2) * 32);
        }

        // compute: two k16 steps
        const unsigned int* Au = (const unsigned int*)(Asm + cur * AS_BUF);
        const unsigned int* Bu = (const unsigned int*)(Bsm + cur * BS_BUF);
        #pragma unroll
        for (int k16 = 0; k16 < 2; k16++) {
            unsigned int af[4][4], bf[8][2];
            #pragma unroll
            for (int i = 0; i < 4; i++) {
                const unsigned int* p = Au + (wm * 64 + i * 16 + g) * (HSTR / 2) + k16 * 8 + tg;
                af[i][0] = p[0];
                af[i][1] = p[8 * (HSTR / 2)];
                af[i][2] = p[4];
                af[i][3] = p[8 * (HSTR / 2) + 4];
            }
            #pragma unroll
            for (int jn = 0; jn < 8; jn++) {
                const unsigned int* p = Bu + (wn * 64 + jn * 8 + g) * (HSTR / 2) + k16 * 8 + tg;
                bf[jn][0] = p[0];
                bf[jn][1] = p[4];
            }
            #pragma unroll
            for (int i = 0; i < 4; i++)
                #pragma unroll
                for (int jn = 0; jn < 8; jn++) {
                    asm volatile(
                        "mma.sync.aligned.m16n8k16.row.col.f32.f16.f16.f32 "
                        "{%0,%1,%2,%3}, {%4,%5,%6,%7}, {%8,%9}, {%0,%1,%2,%3};"
                        : "+f"(acc[i][jn][0]), "+f"(acc[i][jn][1]),
                          "+f"(acc[i][jn][2]), "+f"(acc[i][jn][3])
                        : "r"(af[i][0]), "r"(af[i][1]), "r"(af[i][2]), "r"(af[i][3]),
                          "r"(bf[jn][0]), "r"(bf[jn][1]));
                }
        }
        __syncthreads();
    }

    // epilogue (M-guarded), fp32 + bias
    #pragma unroll
    for (int i = 0; i < 4; i++) {
        #pragma unroll
        for (int jn = 0; jn < 8; jn++) {
            int row = row0 + wm * 64 + i * 16 + g;
            int col = col0 + wn * 64 + jn * 8 + tg * 2;
            float b0 = 0.f, b1 = 0.f;
            if (bias != nullptr) { b0 = bias[col]; b1 = bias[col + 1]; }
            if (row < M) {
                float2 v0 = make_float2(acc[i][jn][0] + b0, acc[i][jn][1] + b1);
                *(float2*)(C + (size_t)row * CC + col) = v0;
            }
            if (row + 8 < M) {
                float2 v1 = make_float2(acc[i][jn][2] + b0, acc[i][jn][3] + b1);
                *(float2*)(C + (size_t)(row + 8) * CC + col) = v1;
            }
        }
    }
}

// ---------------- CORA prep ----------------
__global__ __launch_bounds__(256) void cora_prep(
    const float* __restrict__ target, const float* __restrict__ anchor,
    const float* __restrict__ pres,
    float* __restrict__ uhat, float* __restrict__ ahat, float* __restrict__ Gout)
{
    __shared__ float red[32];
    __shared__ float ud[CC], ad[CC];
    const int s = blockIdx.x, tid = threadIdx.x;
    const float* p0 = pres + (size_t)s * CC;
    const float* p1 = pres + (size_t)(SS + s) * CC;
    const float* tg = target + (size_t)s * CC;
    const float* an = anchor + (size_t)s * CC;

    float g00 = 0, g01 = 0, g11 = 0, bt0 = 0, bt1 = 0, ba0 = 0, ba1 = 0;
    for (int d = tid; d < CC; d += 256) {
        float a = p0[d], b = p1[d], t = tg[d], u = an[d];
        g00 += a * a; g01 += a * b; g11 += b * b;
        bt0 += a * t; bt1 += b * t;
        ba0 += a * u; ba1 += b * u;
    }
    g00 = blockSum(g00, red); g01 = blockSum(g01, red); g11 = blockSum(g11, red);
    bt0 = blockSum(bt0, red); bt1 = blockSum(bt1, red);
    ba0 = blockSum(ba0, red); ba1 = blockSum(ba1, red);

    float det = g00 * g11 - g01 * g01;
    float ct0 = (g11 * bt0 - g01 * bt1) / det, ct1 = (g00 * bt1 - g01 * bt0) / det;
    float ca0 = (g11 * ba0 - g01 * ba1) / det, ca1 = (g00 * ba1 - g01 * ba0) / det;

    float nu2 = 0;
    for (int d = tid; d < CC; d += 256) {
        float udv = tg[d] - (p0[d] * ct0 + p1[d] * ct1);
        float adv = an[d] - (p0[d] * ca0 + p1[d] * ca1);
        ud[d] = udv; ad[d] = adv;
        nu2 += udv * udv;
    }
    nu2 = blockSum(nu2, red);
    float nu = sqrtf(nu2) + EPSI;

    float dua = 0;
    for (int d = tid; d < CC; d += 256) {
        float uh = ud[d] / nu;
        ud[d] = uh;
        uhat[(size_t)s * CC + d] = uh;
        dua += uh * ad[d];
    }
    dua = blockSum(dua, red);

    float na2 = 0;
    for (int d = tid; d < CC; d += 256) {
        float at = ad[d] - dua * ud[d];
        ad[d] = at;
        na2 += at * at;
    }
    na2 = blockSum(na2, red);
    float na = sqrtf(na2) + EPSI;

    for (int d = tid; d < CC; d += 256)
        ahat[(size_t)s * CC + d] = ad[d] / na;

    if (tid == 0) { Gout[s * 3 + 0] = g00; Gout[s * 3 + 1] = g01; Gout[s * 3 + 2] = g11; }
}

// ---------------- CORA apply ----------------
__global__ __launch_bounds__(256) void cora_apply(
    const float* __restrict__ Vin, const float* __restrict__ pres,
    const float* __restrict__ G, const float* __restrict__ uhat,
    const float* __restrict__ ahat, float* __restrict__ Ve)
{
    __shared__ float red[32];
    const int bs = blockIdx.x, s = bs % SS, tid = threadIdx.x;
    const float* v = Vin + (size_t)bs * CC;
    const float* p0 = pres + (size_t)s * CC;
    const float* p1 = pres + (size_t)(SS + s) * CC;
    const float* uh = uhat + (size_t)s * CC;
    const float* ah = ahat + (size_t)s * CC;

    float b0 = 0, b1 = 0;
    for (int d = tid; d < CC; d += 256) {
        float vd = v[d];
        b0 += p0[d] * vd; b1 += p1[d] * vd;
    }
    b0 = blockSum(b0, red); b1 = blockSum(b1, red);

    float g00 = G[s * 3], g01 = G[s * 3 + 1], g11 = G[s * 3 + 2];
    float det = g00 * g11 - g01 * g01;
    float c0 = (g11 * b0 - g01 * b1) / det;
    float c1 = (g00 * b1 - g01 * b0) / det;

    float nf2 = 0, t = 0;
    for (int d = tid; d < CC; d += 256) {
        float vp = p0[d] * c0 + p1[d] * c1;
        float vf = v[d] - vp;
        nf2 += vf * vf;
        t += uh[d] * vf;
    }
    nf2 = blockSum(nf2, red);
    t = blockSum(t, red);

    float denom = sqrtf(nf2) + EPSI;
    bool keep = (fabsf(t) / denom) < TAU;

    for (int d = tid; d < CC; d += 256) {
        float vp = p0[d] * c0 + p1[d] * c1;
        float vf = v[d] - vp;
        float vn = vp + vf - t * uh[d] + BETA * t * ah[d];
        Ve[(size_t)bs * CC + d] = keep ? v[d] : vn;
    }
}

// ---------------- fused attention (fp32 math, fp16 output) ----------------
#define ATTN_SMEM_BYTES ((SS * 84 * 2 + 64 * DH * 2) * 4)

__global__ __launch_bounds__(256) void attn_kernel(
    const float* __restrict__ Q, const float* __restrict__ Kp,
    const float* __restrict__ Vp, __half* __restrict__ O)
{
    extern __shared__ float smf[];
    float* Ks = smf;
    float* Vs = Ks + SS * 84;
    float* Qs = Vs + SS * 84;
    float* Ps = Qs + 64 * DH;

    const int b = blockIdx.z, h = blockIdx.y;
    const int n0 = blockIdx.x * 64;
    const int tid = threadIdx.x;

    for (int i = tid; i < SS * DH; i += 256) {
        int s = i / DH, d = i % DH;
        size_t goff = ((size_t)(b * SS + s)) * CC + h * DH + d;
        Ks[s * 84 + d] = Kp[goff];
        Vs[s * 84 + d] = Vp[goff];
    }
    for (int i = tid; i < 64 * DH; i += 256) {
        int r = i / DH, d = i % DH;
        Qs[r * DH + d] = Q[((size_t)b * NN + n0 + r) * CC + h * DH + d];
    }
    __syncthreads();

    const int w = tid >> 5, l = tid & 31;
    const int rbase = w * 8;

    float acc[8][3];
    #pragma unroll
    for (int r = 0; r < 8; r++)
        #pragma unroll
        for (int c = 0; c < 3; c++) acc[r][c] = 0.0f;

    const float4* Ks4 = (const float4*)Ks;
    #pragma unroll 4
    for (int dc = 0; dc < DH / 4; dc++) {
        float4 kv[3];
        #pragma unroll
        for (int c = 0; c < 3; c++) {
            int s = l + 32 * c;
            kv[c] = (s < SS) ? Ks4[s * 21 + dc] : make_float4(0.f, 0.f, 0.f, 0.f);
        }
        #pragma unroll
        for (int r = 0; r < 8; r++) {
            float4 qv = *(const float4*)(Qs + (rbase + r) * DH + dc * 4);
            #pragma unroll
            for (int c = 0; c < 3; c++)
                acc[r][c] += qv.x * kv[c].x + qv.y * kv[c].y + qv.z * kv[c].z + qv.w * kv[c].w;
        }
    }

    const float scale = 0.11180339887498948f;
    #pragma unroll
    for (int r = 0; r < 8; r++) {
        float m = -1e30f;
        #pragma unroll
        for (int c = 0; c < 3; c++) {
            int s = l + 32 * c;
            float vsc = (s < SS) ? acc[r][c] * scale : -1e30f;
            acc[r][c] = vsc;
            m = fmaxf(m, vsc);
        }
        #pragma unroll
        for (int o = 16; o; o >>= 1) m = fmaxf(m, __shfl_xor_sync(0xffffffffu, m, o));
        float sum = 0.f;
        #pragma unroll
        for (int c = 0; c < 3; c++) {
            int s = l + 32 * c;
            float e = (s < SS) ? expf(acc[r][c] - m) : 0.f;
            acc[r][c] = e;
            sum += e;
        }
        #pragma unroll
        for (int o = 16; o; o >>= 1) sum += __shfl_xor_sync(0xffffffffu, sum, o);
        float inv = 1.0f / sum;
        #pragma unroll
        for (int c = 0; c < 3; c++) {
            int s = l + 32 * c;
            if (s < SS) Ps[(rbase + r) * DH + s] = acc[r][c] * inv;
        }
    }
    __syncwarp();

    float oacc[8][3];
    #pragma unroll
    for (int r = 0; r < 8; r++)
        #pragma unroll
        for (int j = 0; j < 3; j++) oacc[r][j] = 0.0f;

    for (int s = 0; s < SS; s++) {
        float vv[3];
        #pragma unroll
        for (int j = 0; j < 3; j++) {
            int d = l + 32 * j;
            vv[j] = (d < DH) ? Vs[s * 84 + d] : 0.f;
        }
        #pragma unroll
        for (int r = 0; r < 8; r++) {
            float pv = Ps[(rbase + r) * DH + s];
            #pragma unroll
            for (int j = 0; j < 3; j++) oacc[r][j] += pv * vv[j];
        }
    }

    #pragma unroll
    for (int r = 0; r < 8; r++)
        #pragma unroll
        for (int j = 0; j < 3; j++) {
            int d = l + 32 * j;
            if (d < DH)
                O[((size_t)b * NN + n0 + rbase + r) * CC + h * DH + d] =
                    __float2half_rn(oacc[r][j]);
        }
}

// ---------------- launch ----------------
extern "C" void kernel_launch(void* const* d_in, const int* in_sizes, int n_in,
                              void* d_out, int out_size)
{
    static float *Qb = nullptr, *Kb = nullptr, *Vb = nullptr,
                 *Veb = nullptr, *Uh = nullptr, *Ah = nullptr, *Gm = nullptr;
    static __half *Attnh = nullptr, *Wh = nullptr;
    static bool init = false;
    if (!init) {
        cudaGetSymbolAddress((void**)&Qb, g_Q);
        cudaGetSymbolAddress((void**)&Attnh, g_attnh);
        cudaGetSymbolAddress((void**)&Kb, g_K);
        cudaGetSymbolAddress((void**)&Vb, g_V);
        cudaGetSymbolAddress((void**)&Veb, g_Ve);
        cudaGetSymbolAddress((void**)&Uh, g_uhat);
        cudaGetSymbolAddress((void**)&Ah, g_ahat);
        cudaGetSymbolAddress((void**)&Gm, g_G);
        cudaGetSymbolAddress((void**)&Wh, g_Wh);
        cudaFuncSetAttribute(attn_kernel, cudaFuncAttributeMaxDynamicSharedMemorySize,
                             ATTN_SMEM_BYTES);
        cudaFuncSetAttribute(gemm_v2<0>, cudaFuncAttributeMaxDynamicSharedMemorySize,
                             GV2_SMEM);
        cudaFuncSetAttribute(gemm_v2<1>, cudaFuncAttributeMaxDynamicSharedMemorySize,
                             GV2_SMEM);
        init = true;
    }

    const float* X    = (const float*)d_in[0];
    const float* E    = (const float*)d_in[1];
    const float* Wq   = (const float*)d_in[2];
    const float* Wk   = (const float*)d_in[3];
    const float* Wv   = (const float*)d_in[4];
    const float* Wo   = (const float*)d_in[5];
    const float* bo   = (const float*)d_in[6];
    const float* tgt  = (const float*)d_in[7];
    const float* anc  = (const float*)d_in[8];
    const float* pres = (const float*)d_in[9];
    float* out = (float*)d_out;

    __half* WqT = Wh + 0 * (XD * CC);
    __half* WkT = Wh + 1 * (XD * CC);
    __half* WvT = Wh + 2 * (XD * CC);
    __half* WoT = Wh + 3 * (XD * CC);

    // transpose + fp16-convert the 4 weight matrices
    transpose_h<<<dim3(CC / 32, CC / 32), 256>>>(Wq, WqT, CC, CC);
    transpose_h<<<dim3(CC / 32, XD / 32), 256>>>(Wk, WkT, XD, CC);
    transpose_h<<<dim3(CC / 32, XD / 32), 256>>>(Wv, WvT, XD, CC);
    transpose_h<<<dim3(CC / 32, CC / 32), 256>>>(Wo, WoT, CC, CC);

    // Q projection: [32768,640] x [640,640]
    gemm_v2<0><<<dim3(CC / 128, (BB * NN) / 256), 256, GV2_SMEM>>>(
        X, WqT, nullptr, Qb, BB * NN, CC);

    // K,V projections: [616,768] x [768,640] (M guarded)
    gemm_v2<0><<<dim3(CC / 128, (BB * SS + 255) / 256), 256, GV2_SMEM>>>(
        E, WkT, nullptr, Kb, BB * SS, XD);
    gemm_v2<0><<<dim3(CC / 128, (BB * SS + 255) / 256), 256, GV2_SMEM>>>(
        E, WvT, nullptr, Vb, BB * SS, XD);

    // CORA erase on V
    cora_prep<<<SS, 256>>>(tgt, anc, pres, Uh, Ah, Gm);
    cora_apply<<<BB * SS, 256>>>(Vb, pres, Gm, Uh, Ah, Veb);

    // fused attention (writes fp16)
    attn_kernel<<<dim3(NN / 64, HH, BB), 256, ATTN_SMEM_BYTES>>>(Qb, Kb, Veb, Attnh);

    // output projection + bias (A already fp16)
    gemm_v2<1><<<dim3(CC / 128, (BB * NN) / 256), 256, GV2_SMEM>>>(
        Attnh, WoT, bo, out, BB * NN, CC);
}

// round 8
// speedup vs baseline: 3.7009x; 1.6703x over previous
#include <cuda_runtime.h>
#include <cuda_fp16.h>
#include <math.h>
#include <stdint.h>

// Problem constants
#define BB 8
#define NN 4096
#define CC 640
#define SS 77
#define XD 768
#define HH 8
#define DH 80
#define BETA 0.5f
#define TAU 0.1f
#define EPSI 1e-8f

// ---------------- scratch (no cudaMalloc allowed) ----------------
__device__ __half g_Qh[BB * NN * CC];      // 41.9 MB (Q, fp16)
__device__ __half g_attnh[BB * NN * CC];   // 41.9 MB (attention out, fp16)
__device__ __half g_Kh[BB * SS * CC];      // K, fp16
__device__ float g_V[BB * SS * CC];
__device__ float g_Ve[BB * SS * CC];
__device__ float g_uhat[SS * CC];
__device__ float g_ahat[SS * CC];
__device__ float g_G[SS * 3];
__device__ __half g_Wh[4][XD * CC];        // transposed fp16 weights [n][k]

// ---------------- block reduce helper ----------------
__device__ __forceinline__ float blockSum(float v, float* red) {
    #pragma unroll
    for (int o = 16; o; o >>= 1) v += __shfl_xor_sync(0xffffffffu, v, o);
    int w = threadIdx.x >> 5, l = threadIdx.x & 31;
    __syncthreads();
    if (l == 0) red[w] = v;
    __syncthreads();
    if (w == 0) {
        float x = (l < (int)(blockDim.x >> 5)) ? red[l] : 0.0f;
        #pragma unroll
        for (int o = 4; o; o >>= 1) x += __shfl_xor_sync(0xffffffffu, x, o);
        if (l == 0) red[0] = x;
    }
    __syncthreads();
    return red[0];
}

// ---------------- weight transpose + fp16 convert: Wt[n,k] = h(W[k,n]) ------
__global__ __launch_bounds__(256) void transpose_h(
    const float* __restrict__ W, __half* __restrict__ Wt, int K, int N)
{
    __shared__ float t[32][33];
    const int k0 = blockIdx.y * 32, n0 = blockIdx.x * 32;
    const int tx = threadIdx.x & 31, ty = threadIdx.x >> 5;   // 32 x 8
    #pragma unroll
    for (int i = ty; i < 32; i += 8) {
        int k = k0 + i, n = n0 + tx;
        if (k < K && n < N) t[i][tx] = W[(size_t)k * N + n];
    }
    __syncthreads();
    #pragma unroll
    for (int i = ty; i < 32; i += 8) {
        int n = n0 + i, k = k0 + tx;
        if (k < K && n < N)
            Wt[(size_t)n * K + k] = __float2half_rn(t[tx][i]);
    }
}

// =====================================================================
// FP16 tensor-core GEMM v2: C[M,640] = A[M,K] @ W[K,640]
// A fp32/fp16 via AHALF; C fp32/fp16 via OUTH.
// CTA tile 256x128x32, 8 warps (4x2), warp tile 64x64, m16n8k16.
// =====================================================================
#define HSTR 40
#define AS_BUF (256 * HSTR)
#define BS_BUF (128 * HSTR)
#define GV2_SMEM ((2 * AS_BUF + 2 * BS_BUF) * 2)   // 61440 B

template <int AHALF, int OUTH>
__global__ __launch_bounds__(256) void gemm_v2(
    const void* __restrict__ Ap, const __half* __restrict__ Bt,
    const float* __restrict__ bias, void* __restrict__ Cp,
    int M, int K)
{
    extern __shared__ __half sh[];
    __half* Asm = sh;
    __half* Bsm = sh + 2 * AS_BUF;

    const int tid = threadIdx.x;
    const int wid = tid >> 5, lane = tid & 31;
    const int wm = wid >> 1, wn = wid & 1;
    const int g = lane >> 2, tg = lane & 3;
    const int row0 = blockIdx.y * 256, col0 = blockIdx.x * 128;

    const int lr = tid >> 3;
    const int lc = (tid & 7) * 4;

    float acc[4][8][4];
    #pragma unroll
    for (int i = 0; i < 4; i++)
        #pragma unroll
        for (int j = 0; j < 8; j++)
            #pragma unroll
            for (int r = 0; r < 4; r++) acc[i][j][r] = 0.0f;

    const int KT = K / 32;
    const float4 z4 = make_float4(0.f, 0.f, 0.f, 0.f);

    bool mok[8];
    const float* Agf[8];
    const __half* Agh[8];
    #pragma unroll
    for (int j = 0; j < 8; j++) {
        int r = row0 + lr + j * 32;
        mok[j] = r < M;
        int rr = mok[j] ? r : (M - 1);
        if (AHALF) Agh[j] = (const __half*)Ap + (size_t)rr * K + lc;
        else       Agf[j] = (const float*)Ap + (size_t)rr * K + lc;
    }
    const __half* Bgp[4];
    #pragma unroll
    for (int j = 0; j < 4; j++)
        Bgp[j] = Bt + (size_t)(col0 + lr + j * 32) * K + lc;

    float4 raf[8];
    uint2 rah[8];
    uint2 rb[4];

    #pragma unroll
    for (int j = 0; j < 8; j++) {
        if (AHALF) rah[j] = mok[j] ? *(const uint2*)(Agh[j]) : make_uint2(0u, 0u);
        else       raf[j] = mok[j] ? *(const float4*)(Agf[j]) : z4;
    }
    #pragma unroll
    for (int j = 0; j < 4; j++) rb[j] = *(const uint2*)(Bgp[j]);

    #pragma unroll
    for (int j = 0; j < 8; j++) {
        __half* dst = &Asm[(lr + j * 32) * HSTR + lc];
        if (AHALF) {
            *(uint2*)dst = rah[j];
        } else {
            *(__half2*)dst       = __floats2half2_rn(raf[j].x, raf[j].y);
            *(__half2*)(dst + 2) = __floats2half2_rn(raf[j].z, raf[j].w);
        }
    }
    #pragma unroll
    for (int j = 0; j < 4; j++)
        *(uint2*)&Bsm[(lr + j * 32) * HSTR + lc] = rb[j];

    if (KT > 1) {
        #pragma unroll
        for (int j = 0; j < 8; j++) {
            if (AHALF) rah[j] = mok[j] ? *(const uint2*)(Agh[j] + 32) : make_uint2(0u, 0u);
            else       raf[j] = mok[j] ? *(const float4*)(Agf[j] + 32) : z4;
        }
        #pragma unroll
        for (int j = 0; j < 4; j++) rb[j] = *(const uint2*)(Bgp[j] + 32);
    }
    __syncthreads();

    #pragma unroll 1
    for (int kt = 0; kt < KT; kt++) {
        const int cur = kt & 1;
        const int nxt = cur ^ 1;

        if (kt + 1 < KT) {
            #pragma unroll
            for (int j = 0; j < 8; j++) {
                __half* dst = &Asm[nxt * AS_BUF + (lr + j * 32) * HSTR + lc];
                if (AHALF) {
                    *(uint2*)dst = rah[j];
                } else {
                    *(__half2*)dst       = __floats2half2_rn(raf[j].x, raf[j].y);
                    *(__half2*)(dst + 2) = __floats2half2_rn(raf[j].z, raf[j].w);
                }
            }
            #pragma unroll
            for (int j = 0; j < 4; j++)
                *(uint2*)&Bsm[nxt * BS_BUF + (lr + j * 32) * HSTR + lc] = rb[j];
        }
        if (kt + 2 < KT) {
            #pragma unroll
            for (int j = 0; j < 8; j++) {
                if (AHALF) rah[j] = mok[j] ? *(const uint2*)(Agh[j] + (kt + 2) * 32) : make_uint2(0u, 0u);
                else       raf[j] = mok[j] ? *(const float4*)(Agf[j] + (kt + 2) * 32) : z4;
            }
            #pragma unroll
            for (int j = 0; j < 4; j++) rb[j] = *(const uint2*)(Bgp[j] + (kt + 2) * 32);
        }

        const unsigned int* Au = (const unsigned int*)(Asm + cur * AS_BUF);
        const unsigned int* Bu = (const unsigned int*)(Bsm + cur * BS_BUF);
        #pragma unroll
        for (int k16 = 0; k16 < 2; k16++) {
            unsigned int af[4][4], bf[8][2];
            #pragma unroll
            for (int i = 0; i < 4; i++) {
                const unsigned int* p = Au + (wm * 64 + i * 16 + g) * (HSTR / 2) + k16 * 8 + tg;
                af[i][0] = p[0];
                af[i][1] = p[8 * (HSTR / 2)];
                af[i][2] = p[4];
                af[i][3] = p[8 * (HSTR / 2) + 4];
            }
            #pragma unroll
            for (int jn = 0; jn < 8; jn++) {
                const unsigned int* p = Bu + (wn * 64 + jn * 8 + g) * (HSTR / 2) + k16 * 8 + tg;
                bf[jn][0] = p[0];
                bf[jn][1] = p[4];
            }
            #pragma unroll
            for (int i = 0; i < 4; i++)
                #pragma unroll
                for (int jn = 0; jn < 8; jn++) {
                    asm volatile(
                        "mma.sync.aligned.m16n8k16.row.col.f32.f16.f16.f32 "
                        "{%0,%1,%2,%3}, {%4,%5,%6,%7}, {%8,%9}, {%0,%1,%2,%3};"
                        : "+f"(acc[i][jn][0]), "+f"(acc[i][jn][1]),
                          "+f"(acc[i][jn][2]), "+f"(acc[i][jn][3])
                        : "r"(af[i][0]), "r"(af[i][1]), "r"(af[i][2]), "r"(af[i][3]),
                          "r"(bf[jn][0]), "r"(bf[jn][1]));
                }
        }
        __syncthreads();
    }

    // epilogue
    #pragma unroll
    for (int i = 0; i < 4; i++) {
        #pragma unroll
        for (int jn = 0; jn < 8; jn++) {
            int row = row0 + wm * 64 + i * 16 + g;
            int col = col0 + wn * 64 + jn * 8 + tg * 2;
            float b0 = 0.f, b1 = 0.f;
            if (bias != nullptr) { b0 = bias[col]; b1 = bias[col + 1]; }
            if (row < M) {
                if (OUTH)
                    *(__half2*)((__half*)Cp + (size_t)row * CC + col) =
                        __floats2half2_rn(acc[i][jn][0] + b0, acc[i][jn][1] + b1);
                else
                    *(float2*)((float*)Cp + (size_t)row * CC + col) =
                        make_float2(acc[i][jn][0] + b0, acc[i][jn][1] + b1);
            }
            if (row + 8 < M) {
                if (OUTH)
                    *(__half2*)((__half*)Cp + (size_t)(row + 8) * CC + col) =
                        __floats2half2_rn(acc[i][jn][2] + b0, acc[i][jn][3] + b1);
                else
                    *(float2*)((float*)Cp + (size_t)(row + 8) * CC + col) =
                        make_float2(acc[i][jn][2] + b0, acc[i][jn][3] + b1);
            }
        }
    }
}

// ---------------- CORA prep ----------------
__global__ __launch_bounds__(256) void cora_prep(
    const float* __restrict__ target, const float* __restrict__ anchor,
    const float* __restrict__ pres,
    float* __restrict__ uhat, float* __restrict__ ahat, float* __restrict__ Gout)
{
    __shared__ float red[32];
    __shared__ float ud[CC], ad[CC];
    const int s = blockIdx.x, tid = threadIdx.x;
    const float* p0 = pres + (size_t)s * CC;
    const float* p1 = pres + (size_t)(SS + s) * CC;
    const float* tg = target + (size_t)s * CC;
    const float* an = anchor + (size_t)s * CC;

    float g00 = 0, g01 = 0, g11 = 0, bt0 = 0, bt1 = 0, ba0 = 0, ba1 = 0;
    for (int d = tid; d < CC; d += 256) {
        float a = p0[d], b = p1[d], t = tg[d], u = an[d];
        g00 += a * a; g01 += a * b; g11 += b * b;
        bt0 += a * t; bt1 += b * t;
        ba0 += a * u; ba1 += b * u;
    }
    g00 = blockSum(g00, red); g01 = blockSum(g01, red); g11 = blockSum(g11, red);
    bt0 = blockSum(bt0, red); bt1 = blockSum(bt1, red);
    ba0 = blockSum(ba0, red); ba1 = blockSum(ba1, red);

    float det = g00 * g11 - g01 * g01;
    float ct0 = (g11 * bt0 - g01 * bt1) / det, ct1 = (g00 * bt1 - g01 * bt0) / det;
    float ca0 = (g11 * ba0 - g01 * ba1) / det, ca1 = (g00 * ba1 - g01 * ba0) / det;

    float nu2 = 0;
    for (int d = tid; d < CC; d += 256) {
        float udv = tg[d] - (p0[d] * ct0 + p1[d] * ct1);
        float adv = an[d] - (p0[d] * ca0 + p1[d] * ca1);
        ud[d] = udv; ad[d] = adv;
        nu2 += udv * udv;
    }
    nu2 = blockSum(nu2, red);
    float nu = sqrtf(nu2) + EPSI;

    float dua = 0;
    for (int d = tid; d < CC; d += 256) {
        float uh = ud[d] / nu;
        ud[d] = uh;
        uhat[(size_t)s * CC + d] = uh;
        dua += uh * ad[d];
    }
    dua = blockSum(dua, red);

    float na2 = 0;
    for (int d = tid; d < CC; d += 256) {
        float at = ad[d] - dua * ud[d];
        ad[d] = at;
        na2 += at * at;
    }
    na2 = blockSum(na2, red);
    float na = sqrtf(na2) + EPSI;

    for (int d = tid; d < CC; d += 256)
        ahat[(size_t)s * CC + d] = ad[d] / na;

    if (tid == 0) { Gout[s * 3 + 0] = g00; Gout[s * 3 + 1] = g01; Gout[s * 3 + 2] = g11; }
}

// ---------------- CORA apply ----------------
__global__ __launch_bounds__(256) void cora_apply(
    const float* __restrict__ Vin, const float* __restrict__ pres,
    const float* __restrict__ G, const float* __restrict__ uhat,
    const float* __restrict__ ahat, float* __restrict__ Ve)
{
    __shared__ float red[32];
    const int bs = blockIdx.x, s = bs % SS, tid = threadIdx.x;
    const float* v = Vin + (size_t)bs * CC;
    const float* p0 = pres + (size_t)s * CC;
    const float* p1 = pres + (size_t)(SS + s) * CC;
    const float* uh = uhat + (size_t)s * CC;
    const float* ah = ahat + (size_t)s * CC;

    float b0 = 0, b1 = 0;
    for (int d = tid; d < CC; d += 256) {
        float vd = v[d];
        b0 += p0[d] * vd; b1 += p1[d] * vd;
    }
    b0 = blockSum(b0, red); b1 = blockSum(b1, red);

    float g00 = G[s * 3], g01 = G[s * 3 + 1], g11 = G[s * 3 + 2];
    float det = g00 * g11 - g01 * g01;
    float c0 = (g11 * b0 - g01 * b1) / det;
    float c1 = (g00 * b1 - g01 * b0) / det;

    float nf2 = 0, t = 0;
    for (int d = tid; d < CC; d += 256) {
        float vp = p0[d] * c0 + p1[d] * c1;
        float vf = v[d] - vp;
        nf2 += vf * vf;
        t += uh[d] * vf;
    }
    nf2 = blockSum(nf2, red);
    t = blockSum(t, red);

    float denom = sqrtf(nf2) + EPSI;
    bool keep = (fabsf(t) / denom) < TAU;

    for (int d = tid; d < CC; d += 256) {
        float vp = p0[d] * c0 + p1[d] * c1;
        float vf = v[d] - vp;
        float vn = vp + vf - t * uh[d] + BETA * t * ah[d];
        Ve[(size_t)bs * CC + d] = keep ? v[d] : vn;
    }
}

// =====================================================================
// Tensor-core attention: per (b, h, 128-row tile).
// smem: Qs[128][88] fp16, Ks[80][88] fp16, Vt[80][88] fp16 (V transposed).
// Each warp: 16 query rows. scores (m16n8k16) -> reg softmax -> PV (reg reuse).
// =====================================================================
#define AQ_ROWS 128
#define ASTRH 88
#define ATTN2_SMEM ((AQ_ROWS * ASTRH + 80 * ASTRH + 80 * ASTRH) * 2)

__global__ __launch_bounds__(256) void attn_tc(
    const __half* __restrict__ Q, const __half* __restrict__ Kp,
    const float* __restrict__ Vp, __half* __restrict__ O)
{
    extern __shared__ __half ash[];
    __half* Qs = ash;                       // [128][88]
    __half* Ks = Qs + AQ_ROWS * ASTRH;      // [80][88]
    __half* Vt = Ks + 80 * ASTRH;           // [80][88]  Vt[d][s]

    const int b = blockIdx.z, h = blockIdx.y;
    const int n0 = blockIdx.x * AQ_ROWS;
    const int tid = threadIdx.x;

    // zero K/V regions (pad rows/cols must be 0, not garbage)
    {
        unsigned int* z = (unsigned int*)Ks;
        for (int i = tid; i < 2 * 80 * ASTRH / 2; i += 256) z[i] = 0u;
    }
    __syncthreads();

    // load Q (fp16, vectorized 4 halfs)
    for (int i = tid * 4; i < AQ_ROWS * DH; i += 1024) {
        int r = i / DH, d = i % DH;
        *(uint2*)&Qs[r * ASTRH + d] =
            *(const uint2*)(Q + ((size_t)(b * NN + n0 + r)) * CC + h * DH + d);
    }
    // load K (fp16)
    for (int i = tid * 4; i < SS * DH; i += 1024) {
        int r = i / DH, d = i % DH;
        *(uint2*)&Ks[r * ASTRH + d] =
            *(const uint2*)(Kp + ((size_t)(b * SS + r)) * CC + h * DH + d);
    }
    // load V transposed (fp32 -> fp16): Vt[d][s]
    for (int i = tid; i < SS * DH; i += 256) {
        int s = i / DH, d = i % DH;
        Vt[d * ASTRH + s] =
            __float2half_rn(Vp[((size_t)(b * SS + s)) * CC + h * DH + d]);
    }
    __syncthreads();

    const int w = tid >> 5, lane = tid & 31;
    const int g = lane >> 2, tg = lane & 3;
    const int qrow = w * 16;

    // ---- scores: c[j][*] = Q[16,80] @ K^T -> [16, 80] (10 n-tiles) ----
    float c[10][4];
    #pragma unroll
    for (int j = 0; j < 10; j++)
        #pragma unroll
        for (int e = 0; e < 4; e++) c[j][e] = 0.0f;

    const unsigned int* Qu = (const unsigned int*)Qs;
    const unsigned int* Ku = (const unsigned int*)Ks;
    #pragma unroll
    for (int kk = 0; kk < 5; kk++) {
        unsigned int a0, a1, a2, a3;
        const unsigned int* p = Qu + (qrow + g) * (ASTRH / 2) + kk * 8 + tg;
        a0 = p[0];
        a1 = p[8 * (ASTRH / 2)];
        a2 = p[4];
        a3 = p[8 * (ASTRH / 2) + 4];
        #pragma unroll
        for (int j = 0; j < 10; j++) {
            const unsigned int* q = Ku + (j * 8 + g) * (ASTRH / 2) + kk * 8 + tg;
            unsigned int b0 = q[0], b1 = q[4];
            asm volatile(
                "mma.sync.aligned.m16n8k16.row.col.f32.f16.f16.f32 "
                "{%0,%1,%2,%3}, {%4,%5,%6,%7}, {%8,%9}, {%0,%1,%2,%3};"
                : "+f"(c[j][0]), "+f"(c[j][1]), "+f"(c[j][2]), "+f"(c[j][3])
                : "r"(a0), "r"(a1), "r"(a2), "r"(a3), "r"(b0), "r"(b1));
        }
    }

    // ---- softmax over s (cols), rows g and g+8 ----
    const float scale = 0.11180339887498948f;   // 1/sqrt(80)
    const float NEG = -1e30f;
    #pragma unroll
    for (int j = 0; j < 10; j++)
        #pragma unroll
        for (int e = 0; e < 4; e++) c[j][e] *= scale;
    // mask cols 77..79 (tile 9: tg==2 -> elem1; tg==3 -> both)
    if (tg == 2) { c[9][1] = NEG; c[9][3] = NEG; }
    if (tg == 3) { c[9][0] = NEG; c[9][1] = NEG; c[9][2] = NEG; c[9][3] = NEG; }

    float m0 = NEG, m1 = NEG;
    #pragma unroll
    for (int j = 0; j < 10; j++) {
        m0 = fmaxf(m0, fmaxf(c[j][0], c[j][1]));
        m1 = fmaxf(m1, fmaxf(c[j][2], c[j][3]));
    }
    m0 = fmaxf(m0, __shfl_xor_sync(0xffffffffu, m0, 1));
    m0 = fmaxf(m0, __shfl_xor_sync(0xffffffffu, m0, 2));
    m1 = fmaxf(m1, __shfl_xor_sync(0xffffffffu, m1, 1));
    m1 = fmaxf(m1, __shfl_xor_sync(0xffffffffu, m1, 2));

    float s0 = 0.f, s1 = 0.f;
    #pragma unroll
    for (int j = 0; j < 10; j++) {
        c[j][0] = expf(c[j][0] - m0);
        c[j][1] = expf(c[j][1] - m0);
        c[j][2] = expf(c[j][2] - m1);
        c[j][3] = expf(c[j][3] - m1);
        s0 += c[j][0] + c[j][1];
        s1 += c[j][2] + c[j][3];
    }
    s0 += __shfl_xor_sync(0xffffffffu, s0, 1);
    s0 += __shfl_xor_sync(0xffffffffu, s0, 2);
    s1 += __shfl_xor_sync(0xffffffffu, s1, 1);
    s1 += __shfl_xor_sync(0xffffffffu, s1, 2);
    const float i0 = 1.0f / s0, i1 = 1.0f / s1;
    #pragma unroll
    for (int j = 0; j < 10; j++) {
        c[j][0] *= i0; c[j][1] *= i0;
        c[j][2] *= i1; c[j][3] *= i1;
    }

    // ---- PV: o[16, 80] = P[16, 80] @ V[80, 80] (V^T in smem as B) ----
    float o[10][4];
    #pragma unroll
    for (int j = 0; j < 10; j++)
        #pragma unroll
        for (int e = 0; e < 4; e++) o[j][e] = 0.0f;

    const unsigned int* Vu = (const unsigned int*)Vt;
    #pragma unroll
    for (int kk = 0; kk < 5; kk++) {
        // A-frag from score registers (C layout == A layout)
        __half2 ha0 = __floats2half2_rn(c[2 * kk][0],     c[2 * kk][1]);
        __half2 ha1 = __floats2half2_rn(c[2 * kk][2],     c[2 * kk][3]);
        __half2 ha2 = __floats2half2_rn(c[2 * kk + 1][0], c[2 * kk + 1][1]);
        __half2 ha3 = __floats2half2_rn(c[2 * kk + 1][2], c[2 * kk + 1][3]);
        unsigned int a0 = *(unsigned int*)&ha0;
        unsigned int a1 = *(unsigned int*)&ha1;
        unsigned int a2 = *(unsigned int*)&ha2;
        unsigned int a3 = *(unsigned int*)&ha3;
        #pragma unroll
        for (int jd = 0; jd < 10; jd++) {
            const unsigned int* q = Vu + (jd * 8 + g) * (ASTRH / 2) + kk * 8 + tg;
            unsigned int b0 = q[0], b1 = q[4];
            asm volatile(
                "mma.sync.aligned.m16n8k16.row.col.f32.f16.f16.f32 "
                "{%0,%1,%2,%3}, {%4,%5,%6,%7}, {%8,%9}, {%0,%1,%2,%3};"
                : "+f"(o[jd][0]), "+f"(o[jd][1]), "+f"(o[jd][2]), "+f"(o[jd][3])
                : "r"(a0), "r"(a1), "r"(a2), "r"(a3), "r"(b0), "r"(b1));
        }
    }

    // ---- write O (fp16) ----
    const int r0 = n0 + qrow + g;
    #pragma unroll
    for (int jd = 0; jd < 10; jd++) {
        int col = h * DH + jd * 8 + tg * 2;
        *(__half2*)(O + ((size_t)(b * NN + r0)) * CC + col) =
            __floats2half2_rn(o[jd][0], o[jd][1]);
        *(__half2*)(O + ((size_t)(b * NN + r0 + 8)) * CC + col) =
            __floats2half2_rn(o[jd][2], o[jd][3]);
    }
}

// ---------------- launch ----------------
extern "C" void kernel_launch(void* const* d_in, const int* in_sizes, int n_in,
                              void* d_out, int out_size)
{
    static float *Vb = nullptr, *Veb = nullptr, *Uh = nullptr, *Ah = nullptr,
                 *Gm = nullptr;
    static __half *Qh = nullptr, *Kh = nullptr, *Attnh = nullptr, *Wh = nullptr;
    static bool init = false;
    if (!init) {
        cudaGetSymbolAddress((void**)&Qh, g_Qh);
        cudaGetSymbolAddress((void**)&Attnh, g_attnh);
        cudaGetSymbolAddress((void**)&Kh, g_Kh);
        cudaGetSymbolAddress((void**)&Vb, g_V);
        cudaGetSymbolAddress((void**)&Veb, g_Ve);
        cudaGetSymbolAddress((void**)&Uh, g_uhat);
        cudaGetSymbolAddress((void**)&Ah, g_ahat);
        cudaGetSymbolAddress((void**)&Gm, g_G);
        cudaGetSymbolAddress((void**)&Wh, g_Wh);
        cudaFuncSetAttribute(attn_tc, cudaFuncAttributeMaxDynamicSharedMemorySize,
                             ATTN2_SMEM);
        cudaFuncSetAttribute(gemm_v2<0, 0>, cudaFuncAttributeMaxDynamicSharedMemorySize, GV2_SMEM);
        cudaFuncSetAttribute(gemm_v2<0, 1>, cudaFuncAttributeMaxDynamicSharedMemorySize, GV2_SMEM);
        cudaFuncSetAttribute(gemm_v2<1, 0>, cudaFuncAttributeMaxDynamicSharedMemorySize, GV2_SMEM);
        init = true;
    }

    const float* X    = (const float*)d_in[0];
    const float* E    = (const float*)d_in[1];
    const float* Wq   = (const float*)d_in[2];
    const float* Wk   = (const float*)d_in[3];
    const float* Wv   = (const float*)d_in[4];
    const float* Wo   = (const float*)d_in[5];
    const float* bo   = (const float*)d_in[6];
    const float* tgt  = (const float*)d_in[7];
    const float* anc  = (const float*)d_in[8];
    const float* pres = (const float*)d_in[9];
    float* out = (float*)d_out;

    __half* WqT = Wh + 0 * (XD * CC);
    __half* WkT = Wh + 1 * (XD * CC);
    __half* WvT = Wh + 2 * (XD * CC);
    __half* WoT = Wh + 3 * (XD * CC);

    transpose_h<<<dim3(CC / 32, CC / 32), 256>>>(Wq, WqT, CC, CC);
    transpose_h<<<dim3(CC / 32, XD / 32), 256>>>(Wk, WkT, XD, CC);
    transpose_h<<<dim3(CC / 32, XD / 32), 256>>>(Wv, WvT, XD, CC);
    transpose_h<<<dim3(CC / 32, CC / 32), 256>>>(Wo, WoT, CC, CC);

    // Q projection -> fp16
    gemm_v2<0, 1><<<dim3(CC / 128, (BB * NN) / 256), 256, GV2_SMEM>>>(
        X, WqT, nullptr, Qh, BB * NN, CC);

    // K projection -> fp16; V projection -> fp32 (CORA needs fp32)
    gemm_v2<0, 1><<<dim3(CC / 128, (BB * SS + 255) / 256), 256, GV2_SMEM>>>(
        E, WkT, nullptr, Kh, BB * SS, XD);
    gemm_v2<0, 0><<<dim3(CC / 128, (BB * SS + 255) / 256), 256, GV2_SMEM>>>(
        E, WvT, nullptr, Vb, BB * SS, XD);

    // CORA erase on V
    cora_prep<<<SS, 256>>>(tgt, anc, pres, Uh, Ah, Gm);
    cora_apply<<<BB * SS, 256>>>(Vb, pres, Gm, Uh, Ah, Veb);

    // tensor-core attention (writes fp16)
    attn_tc<<<dim3(NN / AQ_ROWS, HH, BB), 256, ATTN2_SMEM>>>(Qh, Kh, Veb, Attnh);

    // output projection + bias (A fp16, out fp32)
    gemm_v2<1, 0><<<dim3(CC / 128, (BB * NN) / 256), 256, GV2_SMEM>>>(
        Attnh, WoT, bo, out, BB * NN, CC);
}

// round 9
// speedup vs baseline: 4.0714x; 1.1001x over previous
#include <cuda_runtime.h>
#include <cuda_fp16.h>
#include <math.h>
#include <stdint.h>

// Problem constants
#define BB 8
#define NN 4096
#define CC 640
#define SS 77
#define XD 768
#define HH 8
#define DH 80
#define BETA 0.5f
#define TAU 0.1f
#define EPSI 1e-8f

// ---------------- scratch (no cudaMalloc allowed) ----------------
__device__ __half g_Xh[BB * NN * CC];      // 41.9 MB (X, fp16)
__device__ __half g_Qh[BB * NN * CC];      // 41.9 MB (Q, fp16)
__device__ __half g_attnh[BB * NN * CC];   // 41.9 MB (attention out, fp16)
__device__ __half g_Eh[BB * SS * XD];      // E, fp16
__device__ __half g_Kh[BB * SS * CC];      // K, fp16
__device__ float g_V[BB * SS * CC];
__device__ float g_Ve[BB * SS * CC];
__device__ float g_uhat[SS * CC];
__device__ float g_ahat[SS * CC];
__device__ float g_G[SS * 3];
__device__ __half g_Wh[4][XD * CC];        // transposed fp16 weights [n][k]

// ---------------- block reduce helper ----------------
__device__ __forceinline__ float blockSum(float v, float* red) {
    #pragma unroll
    for (int o = 16; o; o >>= 1) v += __shfl_xor_sync(0xffffffffu, v, o);
    int w = threadIdx.x >> 5, l = threadIdx.x & 31;
    __syncthreads();
    if (l == 0) red[w] = v;
    __syncthreads();
    if (w == 0) {
        float x = (l < (int)(blockDim.x >> 5)) ? red[l] : 0.0f;
        #pragma unroll
        for (int o = 4; o; o >>= 1) x += __shfl_xor_sync(0xffffffffu, x, o);
        if (l == 0) red[0] = x;
    }
    __syncthreads();
    return red[0];
}

// ---------------- fp32 -> fp16 bulk convert (n % 8 == 0) ----------------
__global__ __launch_bounds__(256) void to_half8(
    const float* __restrict__ src, __half* __restrict__ dst, int n)
{
    int i = (blockIdx.x * 256 + threadIdx.x) * 8;
    if (i >= n) return;
    float4 a = *(const float4*)(src + i);
    float4 b = *(const float4*)(src + i + 4);
    __half2 h[4];
    h[0] = __floats2half2_rn(a.x, a.y);
    h[1] = __floats2half2_rn(a.z, a.w);
    h[2] = __floats2half2_rn(b.x, b.y);
    h[3] = __floats2half2_rn(b.z, b.w);
    *(uint4*)(dst + i) = *(uint4*)h;
}

// ---------------- fused weight transpose + fp16: Wh[z][n][k] ----------------
__global__ __launch_bounds__(256) void transpose_all(
    const float* __restrict__ Wq, const float* __restrict__ Wk,
    const float* __restrict__ Wv, const float* __restrict__ Wo,
    __half* __restrict__ Wh)
{
    __shared__ float t[32][33];
    const int z = blockIdx.z;
    const float* W = (z == 0) ? Wq : (z == 1) ? Wk : (z == 2) ? Wv : Wo;
    const int K = (z == 1 || z == 2) ? XD : CC;
    __half* Wt = Wh + (size_t)z * (XD * CC);

    const int k0 = blockIdx.y * 32, n0 = blockIdx.x * 32;
    if (k0 >= K) return;
    const int tx = threadIdx.x & 31, ty = threadIdx.x >> 5;
    #pragma unroll
    for (int i = ty; i < 32; i += 8) {
        int k = k0 + i, n = n0 + tx;
        if (k < K) t[i][tx] = W[(size_t)k * CC + n];
    }
    __syncthreads();
    #pragma unroll
    for (int i = ty; i < 32; i += 8) {
        int n = n0 + i, k = k0 + tx;
        if (k < K)
            Wt[(size_t)n * K + k] = __float2half_rn(t[tx][i]);
    }
}

// =====================================================================
// FP16 tensor-core GEMM v3: C[M,640] = A[M,K] @ W[K,640]
// A fp16; W as Wt[640,K] fp16; output fp32/fp16 selected at runtime.
// Dual-B: blocks with bx >= nsplit compute A @ B2 -> C2 (outh2).
// CTA tile 256x128x32, 8 warps (4x2), warp tile 64x64, m16n8k16.
// 3-stage cp.async pipeline. M guarded; K % 32 == 0.
// =====================================================================
#define HSTR 40
#define A3_BUF (256 * HSTR)     // halfs per stage
#define B3_BUF (128 * HSTR)
#define GV3_SMEM (3 * (A3_BUF + B3_BUF) * 2)   // 92160 B

__global__ __launch_bounds__(256) void gemm_v3(
    const __half* __restrict__ A,
    const __half* __restrict__ B1, const float* __restrict__ bias,
    void* __restrict__ C1, int outh1,
    const __half* __restrict__ B2, void* __restrict__ C2, int outh2,
    int nsplit, int M, int K)
{
    extern __shared__ __half sh[];
    const int tid = threadIdx.x;
    int bx = blockIdx.x;
    const __half* Bt = B1;
    void* Cp = C1;
    int outh = outh1;
    const float* bp = bias;
    if (B2 != nullptr && bx >= nsplit) { Bt = B2; Cp = C2; outh = outh2; bp = nullptr; bx -= nsplit; }

    const int wid = tid >> 5, lane = tid & 31;
    const int wm = wid >> 1, wn = wid & 1;     // 4 x 2 warp grid
    const int g = lane >> 2, tg = lane & 3;
    const int row0 = blockIdx.y * 256, col0 = bx * 128;

    const unsigned smem_base = (unsigned)__cvta_generic_to_shared(sh);
    const int cr = tid >> 2;            // 0..63
    const int cc = (tid & 3) * 8;       // 0,8,16,24 (halfs)

    float acc[4][8][4];
    #pragma unroll
    for (int i = 0; i < 4; i++)
        #pragma unroll
        for (int j = 0; j < 8; j++)
            #pragma unroll
            for (int r = 0; r < 4; r++) acc[i][j][r] = 0.0f;

    const int KT = K / 32;

    auto issue = [&](int tile, int stage) {
        const unsigned sb = smem_base + stage * (A3_BUF + B3_BUF) * 2;
        #pragma unroll
        for (int j = 0; j < 4; j++) {
            int r = cr + j * 64;
            int gr = row0 + r;
            int sz = (gr < M) ? 16 : 0;
            const __half* src = A + (size_t)(gr < M ? gr : (M - 1)) * K + tile * 32 + cc;
            unsigned dst = sb + (r * HSTR + cc) * 2;
            asm volatile("cp.async.cg.shared.global [%0], [%1], 16, %2;"
                         :: "r"(dst), "l"(src), "r"(sz));
        }
        #pragma unroll
        for (int j = 0; j < 2; j++) {
            int r = cr + j * 64;
            const __half* src = Bt + (size_t)(col0 + r) * K + tile * 32 + cc;
            unsigned dst = sb + (A3_BUF + r * HSTR + cc) * 2;
            asm volatile("cp.async.cg.shared.global [%0], [%1], 16, %2;"
                         :: "r"(dst), "l"(src), "r"(16));
        }
        asm volatile("cp.async.commit_group;");
    };

    issue(0, 0);
    if (KT > 1) issue(1, 1);
    else        asm volatile("cp.async.commit_group;");   // keep group count sane

    #pragma unroll 1
    for (int kt = 0; kt < KT; kt++) {
        if (kt == KT - 1) asm volatile("cp.async.wait_group 0;");
        else              asm volatile("cp.async.wait_group 1;");
        __syncthreads();
        if (kt + 2 < KT) issue(kt + 2, (kt + 2) % 3);

        const unsigned int* Au = (const unsigned int*)(sh + (kt % 3) * (A3_BUF + B3_BUF));
        const unsigned int* Bu = Au + A3_BUF / 2;
        #pragma unroll
        for (int k16 = 0; k16 < 2; k16++) {
            unsigned int af[4][4], bf[8][2];
            #pragma unroll
            for (int i = 0; i < 4; i++) {
                const unsigned int* p = Au + (wm * 64 + i * 16 + g) * (HSTR / 2) + k16 * 8 + tg;
                af[i][0] = p[0];
                af[i][1] = p[8 * (HSTR / 2)];
                af[i][2] = p[4];
                af[i][3] = p[8 * (HSTR / 2) + 4];
            }
            #pragma unroll
            for (int jn = 0; jn < 8; jn++) {
                const unsigned int* p = Bu + (wn * 64 + jn * 8 + g) * (HSTR / 2) + k16 * 8 + tg;
                bf[jn][0] = p[0];
                bf[jn][1] = p[4];
            }
            #pragma unroll
            for (int i = 0; i < 4; i++)
                #pragma unroll
                for (int jn = 0; jn < 8; jn++) {
                    asm volatile(
                        "mma.sync.aligned.m16n8k16.row.col.f32.f16.f16.f32 "
                        "{%0,%1,%2,%3}, {%4,%5,%6,%7}, {%8,%9}, {%0,%1,%2,%3};"
                        : "+f"(acc[i][jn][0]), "+f"(acc[i][jn][1]),
                          "+f"(acc[i][jn][2]), "+f"(acc[i][jn][3])
                        : "r"(af[i][0]), "r"(af[i][1]), "r"(af[i][2]), "r"(af[i][3]),
                          "r"(bf[jn][0]), "r"(bf[jn][1]));
                }
        }
        __syncthreads();
    }

    // epilogue (M-guarded), runtime output dtype
    #pragma unroll
    for (int i = 0; i < 4; i++) {
        #pragma unroll
        for (int jn = 0; jn < 8; jn++) {
            int row = row0 + wm * 64 + i * 16 + g;
            int col = col0 + wn * 64 + jn * 8 + tg * 2;
            float b0 = 0.f, b1 = 0.f;
            if (bp != nullptr) { b0 = bp[col]; b1 = bp[col + 1]; }
            if (row < M) {
                if (outh)
                    *(__half2*)((__half*)Cp + (size_t)row * CC + col) =
                        __floats2half2_rn(acc[i][jn][0] + b0, acc[i][jn][1] + b1);
                else
                    *(float2*)((float*)Cp + (size_t)row * CC + col) =
                        make_float2(acc[i][jn][0] + b0, acc[i][jn][1] + b1);
            }
            if (row + 8 < M) {
                if (outh)
                    *(__half2*)((__half*)Cp + (size_t)(row + 8) * CC + col) =
                        __floats2half2_rn(acc[i][jn][2] + b0, acc[i][jn][3] + b1);
                else
                    *(float2*)((float*)Cp + (size_t)(row + 8) * CC + col) =
                        make_float2(acc[i][jn][2] + b0, acc[i][jn][3] + b1);
            }
        }
    }
}

// ---------------- CORA prep ----------------
__global__ __launch_bounds__(256) void cora_prep(
    const float* __restrict__ target, const float* __restrict__ anchor,
    const float* __restrict__ pres,
    float* __restrict__ uhat, float* __restrict__ ahat, float* __restrict__ Gout)
{
    __shared__ float red[32];
    __shared__ float ud[CC], ad[CC];
    const int s = blockIdx.x, tid = threadIdx.x;
    const float* p0 = pres + (size_t)s * CC;
    const float* p1 = pres + (size_t)(SS + s) * CC;
    const float* tg = target + (size_t)s * CC;
    const float* an = anchor + (size_t)s * CC;

    float g00 = 0, g01 = 0, g11 = 0, bt0 = 0, bt1 = 0, ba0 = 0, ba1 = 0;
    for (int d = tid; d < CC; d += 256) {
        float a = p0[d], b = p1[d], t = tg[d], u = an[d];
        g00 += a * a; g01 += a * b; g11 += b * b;
        bt0 += a * t; bt1 += b * t;
        ba0 += a * u; ba1 += b * u;
    }
    g00 = blockSum(g00, red); g01 = blockSum(g01, red); g11 = blockSum(g11, red);
    bt0 = blockSum(bt0, red); bt1 = blockSum(bt1, red);
    ba0 = blockSum(ba0, red); ba1 = blockSum(ba1, red);

    float det = g00 * g11 - g01 * g01;
    float ct0 = (g11 * bt0 - g01 * bt1) / det, ct1 = (g00 * bt1 - g01 * bt0) / det;
    float ca0 = (g11 * ba0 - g01 * ba1) / det, ca1 = (g00 * ba1 - g01 * ba0) / det;

    float nu2 = 0;
    for (int d = tid; d < CC; d += 256) {
        float udv = tg[d] - (p0[d] * ct0 + p1[d] * ct1);
        float adv = an[d] - (p0[d] * ca0 + p1[d] * ca1);
        ud[d] = udv; ad[d] = adv;
        nu2 += udv * udv;
    }
    nu2 = blockSum(nu2, red);
    float nu = sqrtf(nu2) + EPSI;

    float dua = 0;
    for (int d = tid; d < CC; d += 256) {
        float uh = ud[d] / nu;
        ud[d] = uh;
        uhat[(size_t)s * CC + d] = uh;
        dua += uh * ad[d];
    }
    dua = blockSum(dua, red);

    float na2 = 0;
    for (int d = tid; d < CC; d += 256) {
        float at = ad[d] - dua * ud[d];
        ad[d] = at;
        na2 += at * at;
    }
    na2 = blockSum(na2, red);
    float na = sqrtf(na2) + EPSI;

    for (int d = tid; d < CC; d += 256)
        ahat[(size_t)s * CC + d] = ad[d] / na;

    if (tid == 0) { Gout[s * 3 + 0] = g00; Gout[s * 3 + 1] = g01; Gout[s * 3 + 2] = g11; }
}

// ---------------- CORA apply ----------------
__global__ __launch_bounds__(256) void cora_apply(
    const float* __restrict__ Vin, const float* __restrict__ pres,
    const float* __restrict__ G, const float* __restrict__ uhat,
    const float* __restrict__ ahat, float* __restrict__ Ve)
{
    __shared__ float red[32];
    const int bs = blockIdx.x, s = bs % SS, tid = threadIdx.x;
    const float* v = Vin + (size_t)bs * CC;
    const float* p0 = pres + (size_t)s * CC;
    const float* p1 = pres + (size_t)(SS + s) * CC;
    const float* uh = uhat + (size_t)s * CC;
    const float* ah = ahat + (size_t)s * CC;

    float b0 = 0, b1 = 0;
    for (int d = tid; d < CC; d += 256) {
        float vd = v[d];
        b0 += p0[d] * vd; b1 += p1[d] * vd;
    }
    b0 = blockSum(b0, red); b1 = blockSum(b1, red);

    float g00 = G[s * 3], g01 = G[s * 3 + 1], g11 = G[s * 3 + 2];
    float det = g00 * g11 - g01 * g01;
    float c0 = (g11 * b0 - g01 * b1) / det;
    float c1 = (g00 * b1 - g01 * b0) / det;

    float nf2 = 0, t = 0;
    for (int d = tid; d < CC; d += 256) {
        float vp = p0[d] * c0 + p1[d] * c1;
        float vf = v[d] - vp;
        nf2 += vf * vf;
        t += uh[d] * vf;
    }
    nf2 = blockSum(nf2, red);
    t = blockSum(t, red);

    float denom = sqrtf(nf2) + EPSI;
    bool keep = (fabsf(t) / denom) < TAU;

    for (int d = tid; d < CC; d += 256) {
        float vp = p0[d] * c0 + p1[d] * c1;
        float vf = v[d] - vp;
        float vn = vp + vf - t * uh[d] + BETA * t * ah[d];
        Ve[(size_t)bs * CC + d] = keep ? v[d] : vn;
    }
}

// =====================================================================
// Tensor-core attention (unchanged from R8): per (b, h, 128-row tile).
// =====================================================================
#define AQ_ROWS 128
#define ASTRH 88
#define ATTN2_SMEM ((AQ_ROWS * ASTRH + 80 * ASTRH + 80 * ASTRH) * 2)

__global__ __launch_bounds__(256) void attn_tc(
    const __half* __restrict__ Q, const __half* __restrict__ Kp,
    const float* __restrict__ Vp, __half* __restrict__ O)
{
    extern __shared__ __half ash[];
    __half* Qs = ash;
    __half* Ks = Qs + AQ_ROWS * ASTRH;
    __half* Vt = Ks + 80 * ASTRH;

    const int b = blockIdx.z, h = blockIdx.y;
    const int n0 = blockIdx.x * AQ_ROWS;
    const int tid = threadIdx.x;

    {
        unsigned int* z = (unsigned int*)Ks;
        for (int i = tid; i < 2 * 80 * ASTRH / 2; i += 256) z[i] = 0u;
    }
    __syncthreads();

    for (int i = tid * 4; i < AQ_ROWS * DH; i += 1024) {
        int r = i / DH, d = i % DH;
        *(uint2*)&Qs[r * ASTRH + d] =
            *(const uint2*)(Q + ((size_t)(b * NN + n0 + r)) * CC + h * DH + d);
    }
    for (int i = tid * 4; i < SS * DH; i += 1024) {
        int r = i / DH, d = i % DH;
        *(uint2*)&Ks[r * ASTRH + d] =
            *(const uint2*)(Kp + ((size_t)(b * SS + r)) * CC + h * DH + d);
    }
    for (int i = tid; i < SS * DH; i += 256) {
        int s = i / DH, d = i % DH;
        Vt[d * ASTRH + s] =
            __float2half_rn(Vp[((size_t)(b * SS + s)) * CC + h * DH + d]);
    }
    __syncthreads();

    const int w = tid >> 5, lane = tid & 31;
    const int g = lane >> 2, tg = lane & 3;
    const int qrow = w * 16;

    float c[10][4];
    #pragma unroll
    for (int j = 0; j < 10; j++)
        #pragma unroll
        for (int e = 0; e < 4; e++) c[j][e] = 0.0f;

    const unsigned int* Qu = (const unsigned int*)Qs;
    const unsigned int* Ku = (const unsigned int*)Ks;
    #pragma unroll
    for (int kk = 0; kk < 5; kk++) {
        unsigned int a0, a1, a2, a3;
        const unsigned int* p = Qu + (qrow + g) * (ASTRH / 2) + kk * 8 + tg;
        a0 = p[0];
        a1 = p[8 * (ASTRH / 2)];
        a2 = p[4];
        a3 = p[8 * (ASTRH / 2) + 4];
        #pragma unroll
        for (int j = 0; j < 10; j++) {
            const unsigned int* q = Ku + (j * 8 + g) * (ASTRH / 2) + kk * 8 + tg;
            unsigned int b0 = q[0], b1 = q[4];
            asm volatile(
                "mma.sync.aligned.m16n8k16.row.col.f32.f16.f16.f32 "
                "{%0,%1,%2,%3}, {%4,%5,%6,%7}, {%8,%9}, {%0,%1,%2,%3};"
                : "+f"(c[j][0]), "+f"(c[j][1]), "+f"(c[j][2]), "+f"(c[j][3])
                : "r"(a0), "r"(a1), "r"(a2), "r"(a3), "r"(b0), "r"(b1));
        }
    }

    const float scale = 0.11180339887498948f;
    const float NEG = -1e30f;
    #pragma unroll
    for (int j = 0; j < 10; j++)
        #pragma unroll
        for (int e = 0; e < 4; e++) c[j][e] *= scale;
    if (tg == 2) { c[9][1] = NEG; c[9][3] = NEG; }
    if (tg == 3) { c[9][0] = NEG; c[9][1] = NEG; c[9][2] = NEG; c[9][3] = NEG; }

    float m0 = NEG, m1 = NEG;
    #pragma unroll
    for (int j = 0; j < 10; j++) {
        m0 = fmaxf(m0, fmaxf(c[j][0], c[j][1]));
        m1 = fmaxf(m1, fmaxf(c[j][2], c[j][3]));
    }
    m0 = fmaxf(m0, __shfl_xor_sync(0xffffffffu, m0, 1));
    m0 = fmaxf(m0, __shfl_xor_sync(0xffffffffu, m0, 2));
    m1 = fmaxf(m1, __shfl_xor_sync(0xffffffffu, m1, 1));
    m1 = fmaxf(m1, __shfl_xor_sync(0xffffffffu, m1, 2));

    float s0 = 0.f, s1 = 0.f;
    #pragma unroll
    for (int j = 0; j < 10; j++) {
        c[j][0] = expf(c[j][0] - m0);
        c[j][1] = expf(c[j][1] - m0);
        c[j][2] = expf(c[j][2] - m1);
        c[j][3] = expf(c[j][3] - m1);
        s0 += c[j][0] + c[j][1];
        s1 += c[j][2] + c[j][3];
    }
    s0 += __shfl_xor_sync(0xffffffffu, s0, 1);
    s0 += __shfl_xor_sync(0xffffffffu, s0, 2);
    s1 += __shfl_xor_sync(0xffffffffu, s1, 1);
    s1 += __shfl_xor_sync(0xffffffffu, s1, 2);
    const float i0 = 1.0f / s0, i1 = 1.0f / s1;
    #pragma unroll
    for (int j = 0; j < 10; j++) {
        c[j][0] *= i0; c[j][1] *= i0;
        c[j][2] *= i1; c[j][3] *= i1;
    }

    float o[10][4];
    #pragma unroll
    for (int j = 0; j < 10; j++)
        #pragma unroll
        for (int e = 0; e < 4; e++) o[j][e] = 0.0f;

    const unsigned int* Vu = (const unsigned int*)Vt;
    #pragma unroll
    for (int kk = 0; kk < 5; kk++) {
        __half2 ha0 = __floats2half2_rn(c[2 * kk][0],     c[2 * kk][1]);
        __half2 ha1 = __floats2half2_rn(c[2 * kk][2],     c[2 * kk][3]);
        __half2 ha2 = __floats2half2_rn(c[2 * kk + 1][0], c[2 * kk + 1][1]);
        __half2 ha3 = __floats2half2_rn(c[2 * kk + 1][2], c[2 * kk + 1][3]);
        unsigned int a0 = *(unsigned int*)&ha0;
        unsigned int a1 = *(unsigned int*)&ha1;
        unsigned int a2 = *(unsigned int*)&ha2;
        unsigned int a3 = *(unsigned int*)&ha3;
        #pragma unroll
        for (int jd = 0; jd < 10; jd++) {
            const unsigned int* q = Vu + (jd * 8 + g) * (ASTRH / 2) + kk * 8 + tg;
            unsigned int b0 = q[0], b1 = q[4];
            asm volatile(
                "mma.sync.aligned.m16n8k16.row.col.f32.f16.f16.f32 "
                "{%0,%1,%2,%3}, {%4,%5,%6,%7}, {%8,%9}, {%0,%1,%2,%3};"
                : "+f"(o[jd][0]), "+f"(o[jd][1]), "+f"(o[jd][2]), "+f"(o[jd][3])
                : "r"(a0), "r"(a1), "r"(a2), "r"(a3), "r"(b0), "r"(b1));
        }
    }

    const int r0 = n0 + qrow + g;
    #pragma unroll
    for (int jd = 0; jd < 10; jd++) {
        int col = h * DH + jd * 8 + tg * 2;
        *(__half2*)(O + ((size_t)(b * NN + r0)) * CC + col) =
            __floats2half2_rn(o[jd][0], o[jd][1]);
        *(__half2*)(O + ((size_t)(b * NN + r0 + 8)) * CC + col) =
            __floats2half2_rn(o[jd][2], o[jd][3]);
    }
}

// ---------------- launch ----------------
extern "C" void kernel_launch(void* const* d_in, const int* in_sizes, int n_in,
                              void* d_out, int out_size)
{
    static float *Vb = nullptr, *Veb = nullptr, *Uh = nullptr, *Ah = nullptr,
                 *Gm = nullptr;
    static __half *Xh = nullptr, *Eh = nullptr, *Qh = nullptr, *Kh = nullptr,
                  *Attnh = nullptr, *Wh = nullptr;
    static bool init = false;
    if (!init) {
        cudaGetSymbolAddress((void**)&Xh, g_Xh);
        cudaGetSymbolAddress((void**)&Eh, g_Eh);
        cudaGetSymbolAddress((void**)&Qh, g_Qh);
        cudaGetSymbolAddress((void**)&Attnh, g_attnh);
        cudaGetSymbolAddress((void**)&Kh, g_Kh);
        cudaGetSymbolAddress((void**)&Vb, g_V);
        cudaGetSymbolAddress((void**)&Veb, g_Ve);
        cudaGetSymbolAddress((void**)&Uh, g_uhat);
        cudaGetSymbolAddress((void**)&Ah, g_ahat);
        cudaGetSymbolAddress((void**)&Gm, g_G);
        cudaGetSymbolAddress((void**)&Wh, g_Wh);
        cudaFuncSetAttribute(attn_tc, cudaFuncAttributeMaxDynamicSharedMemorySize,
                             ATTN2_SMEM);
        cudaFuncSetAttribute(gemm_v3, cudaFuncAttributeMaxDynamicSharedMemorySize,
                             GV3_SMEM);
        init = true;
    }

    const float* X    = (const float*)d_in[0];
    const float* E    = (const float*)d_in[1];
    const float* Wq   = (const float*)d_in[2];
    const float* Wk   = (const float*)d_in[3];
    const float* Wv   = (const float*)d_in[4];
    const float* Wo   = (const float*)d_in[5];
    const float* bo   = (const float*)d_in[6];
    const float* tgt  = (const float*)d_in[7];
    const float* anc  = (const float*)d_in[8];
    const float* pres = (const float*)d_in[9];
    float* out = (float*)d_out;

    __half* WqT = Wh + 0 * (XD * CC);
    __half* WkT = Wh + 1 * (XD * CC);
    __half* WvT = Wh + 2 * (XD * CC);
    __half* WoT = Wh + 3 * (XD * CC);

    // fp16 conversions + fused weight transpose
    to_half8<<<(BB * NN * CC) / 8 / 256, 256>>>(X, Xh, BB * NN * CC);
    to_half8<<<((BB * SS * XD) / 8 + 255) / 256, 256>>>(E, Eh, BB * SS * XD);
    transpose_all<<<dim3(CC / 32, XD / 32, 4), 256>>>(Wq, Wk, Wv, Wo, Wh);

    // Q projection: [32768,640] x [640,640] -> fp16
    gemm_v3<<<dim3(CC / 128, (BB * NN) / 256), 256, GV3_SMEM>>>(
        Xh, WqT, nullptr, Qh, 1, nullptr, nullptr, 0, CC / 128, BB * NN, CC);

    // K (fp16 out) + V (fp32 out) projections in ONE launch (dual-B)
    gemm_v3<<<dim3(2 * (CC / 128), (BB * SS + 255) / 256), 256, GV3_SMEM>>>(
        Eh, WkT, nullptr, Kh, 1, WvT, Vb, 0, CC / 128, BB * SS, XD);

    // CORA erase on V
    cora_prep<<<SS, 256>>>(tgt, anc, pres, Uh, Ah, Gm);
    cora_apply<<<BB * SS, 256>>>(Vb, pres, Gm, Uh, Ah, Veb);

    // tensor-core attention (writes fp16)
    attn_tc<<<dim3(NN / AQ_ROWS, HH, BB), 256, ATTN2_SMEM>>>(Qh, Kh, Veb, Attnh);

    // output projection + bias (fp32 out)
    gemm_v3<<<dim3(CC / 128, (BB * NN) / 256), 256, GV3_SMEM>>>(
        Attnh, WoT, bo, out, 0, nullptr, nullptr, 0, CC / 128, BB * NN, CC);
}

// round 10
// speedup vs baseline: 4.0847x; 1.0033x over previous
#include <cuda_runtime.h>
#include <cuda_fp16.h>
#include <math.h>
#include <stdint.h>

// Problem constants
#define BB 8
#define NN 4096
#define CC 640
#define SS 77
#define XD 768
#define HH 8
#define DH 80
#define BETA 0.5f
#define TAU 0.1f
#define EPSI 1e-8f

// ---------------- scratch (no cudaMalloc allowed) ----------------
__device__ __half g_Xh[BB * NN * CC];      // 41.9 MB (X, fp16)
__device__ __half g_Qh[BB * NN * CC];      // 41.9 MB (Q, fp16)
__device__ __half g_attnh[BB * NN * CC];   // 41.9 MB (attention out, fp16)
__device__ __half g_Eh[BB * SS * XD];      // E, fp16
__device__ __half g_Kh[BB * SS * CC];      // K, fp16
__device__ float g_V[BB * SS * CC];
__device__ float g_Ve[BB * SS * CC];
__device__ float g_uhat[SS * CC];
__device__ float g_ahat[SS * CC];
__device__ float g_G[SS * 3];
__device__ __half g_Wh[4][XD * CC];        // transposed fp16 weights [n][k]

// ---------------- block reduce helper ----------------
__device__ __forceinline__ float blockSum(float v, float* red) {
    #pragma unroll
    for (int o = 16; o; o >>= 1) v += __shfl_xor_sync(0xffffffffu, v, o);
    int w = threadIdx.x >> 5, l = threadIdx.x & 31;
    __syncthreads();
    if (l == 0) red[w] = v;
    __syncthreads();
    if (w == 0) {
        float x = (l < (int)(blockDim.x >> 5)) ? red[l] : 0.0f;
        #pragma unroll
        for (int o = 4; o; o >>= 1) x += __shfl_xor_sync(0xffffffffu, x, o);
        if (l == 0) red[0] = x;
    }
    __syncthreads();
    return red[0];
}

// ---------------- fp32 -> fp16 bulk convert (n % 8 == 0) ----------------
__global__ __launch_bounds__(256) void to_half8(
    const float* __restrict__ src, __half* __restrict__ dst, int n)
{
    int i = (blockIdx.x * 256 + threadIdx.x) * 8;
    if (i >= n) return;
    float4 a = *(const float4*)(src + i);
    float4 b = *(const float4*)(src + i + 4);
    __half2 h[4];
    h[0] = __floats2half2_rn(a.x, a.y);
    h[1] = __floats2half2_rn(a.z, a.w);
    h[2] = __floats2half2_rn(b.x, b.y);
    h[3] = __floats2half2_rn(b.z, b.w);
    *(uint4*)(dst + i) = *(uint4*)h;
}

// ---------------- fused weight transpose + fp16: Wh[z][n][k] ----------------
__global__ __launch_bounds__(256) void transpose_all(
    const float* __restrict__ Wq, const float* __restrict__ Wk,
    const float* __restrict__ Wv, const float* __restrict__ Wo,
    __half* __restrict__ Wh)
{
    __shared__ float t[32][33];
    const int z = blockIdx.z;
    const float* W = (z == 0) ? Wq : (z == 1) ? Wk : (z == 2) ? Wv : Wo;
    const int K = (z == 1 || z == 2) ? XD : CC;
    __half* Wt = Wh + (size_t)z * (XD * CC);

    const int k0 = blockIdx.y * 32, n0 = blockIdx.x * 32;
    if (k0 >= K) return;
    const int tx = threadIdx.x & 31, ty = threadIdx.x >> 5;
    #pragma unroll
    for (int i = ty; i < 32; i += 8) {
        int k = k0 + i, n = n0 + tx;
        if (k < K) t[i][tx] = W[(size_t)k * CC + n];
    }
    __syncthreads();
    #pragma unroll
    for (int i = ty; i < 32; i += 8) {
        int n = n0 + i, k = k0 + tx;
        if (k < K)
            Wt[(size_t)n * K + k] = __float2half_rn(t[tx][i]);
    }
}

// =====================================================================
// FP16 tensor-core GEMM v4: C[M,640] = A[M,K] @ W[K,640]
// A fp16; W as Wt[640,K] fp16; output dtype runtime-selected; dual-B.
// CTA 256x128x32, 8 warps (4x2), warp tile 64x64, m16n8k16.
// 4-stage cp.async pipeline, ldmatrix fragment loads, 1 sync per k-tile.
// =====================================================================
#define HSTR 40
#define A4_BUF (256 * HSTR)     // halfs per stage
#define B4_BUF (128 * HSTR)
#define ST_BUF (A4_BUF + B4_BUF)
#define GV4_SMEM (4 * ST_BUF * 2)   // 122880 B

__global__ __launch_bounds__(256) void gemm_v4(
    const __half* __restrict__ A,
    const __half* __restrict__ B1, const float* __restrict__ bias,
    void* __restrict__ C1, int outh1,
    const __half* __restrict__ B2, void* __restrict__ C2, int outh2,
    int nsplit, int M, int K)
{
    extern __shared__ __half sh[];
    const int tid = threadIdx.x;
    int bx = blockIdx.x;
    const __half* Bt = B1;
    void* Cp = C1;
    int outh = outh1;
    const float* bp = bias;
    if (B2 != nullptr && bx >= nsplit) { Bt = B2; Cp = C2; outh = outh2; bp = nullptr; bx -= nsplit; }

    const int wid = tid >> 5, lane = tid & 31;
    const int wm = wid >> 1, wn = wid & 1;     // 4 x 2 warp grid
    const int g = lane >> 2, tg = lane & 3;
    const int row0 = blockIdx.y * 256, col0 = bx * 128;

    const unsigned smem_base = (unsigned)__cvta_generic_to_shared(sh);
    const int cr = tid >> 2;            // 0..63
    const int cc = (tid & 3) * 8;       // 0,8,16,24 (halfs)
    const int mi = lane >> 3;           // ldmatrix sub-matrix index 0..3
    const int mr = lane & 7;            // ldmatrix row within sub-matrix

    float acc[4][8][4];
    #pragma unroll
    for (int i = 0; i < 4; i++)
        #pragma unroll
        for (int j = 0; j < 8; j++)
            #pragma unroll
            for (int r = 0; r < 4; r++) acc[i][j][r] = 0.0f;

    const int KT = K / 32;

    auto issue = [&](int tile, int stage) {
        const unsigned sb = smem_base + stage * ST_BUF * 2;
        #pragma unroll
        for (int j = 0; j < 4; j++) {
            int r = cr + j * 64;
            int gr = row0 + r;
            int sz = (gr < M) ? 16 : 0;
            const __half* src = A + (size_t)(gr < M ? gr : (M - 1)) * K + tile * 32 + cc;
            unsigned dst = sb + (r * HSTR + cc) * 2;
            asm volatile("cp.async.cg.shared.global [%0], [%1], 16, %2;"
                         :: "r"(dst), "l"(src), "r"(sz));
        }
        #pragma unroll
        for (int j = 0; j < 2; j++) {
            int r = cr + j * 64;
            const __half* src = Bt + (size_t)(col0 + r) * K + tile * 32 + cc;
            unsigned dst = sb + (A4_BUF + r * HSTR + cc) * 2;
            asm volatile("cp.async.cg.shared.global [%0], [%1], 16, %2;"
                         :: "r"(dst), "l"(src), "r"(16));
        }
        asm volatile("cp.async.commit_group;");
    };

    issue(0, 0);
    if (KT > 1) issue(1, 1);
    if (KT > 2) issue(2, 2);

    #pragma unroll 1
    for (int kt = 0; kt < KT; kt++) {
        if (kt < KT - 2) asm volatile("cp.async.wait_group 2;");
        else             asm volatile("cp.async.wait_group 0;");
        __syncthreads();
        if (kt + 3 < KT) issue(kt + 3, (kt + 3) & 3);

        const unsigned st = smem_base + (kt & 3) * ST_BUF * 2;   // byte addr of stage
        #pragma unroll
        for (int k16 = 0; k16 < 2; k16++) {
            unsigned int af[4][4], bf[8][2];
            // A fragments: 4 x ldmatrix.x4 (i = m-subtile)
            #pragma unroll
            for (int i = 0; i < 4; i++) {
                int rowA = wm * 64 + i * 16 + mr + ((mi & 1) << 3);
                int colA = k16 * 16 + ((mi >> 1) << 3);
                unsigned addr = st + (rowA * HSTR + colA) * 2;
                asm volatile(
                    "ldmatrix.sync.aligned.m8n8.x4.shared.b16 {%0,%1,%2,%3}, [%4];"
                    : "=r"(af[i][0]), "=r"(af[i][1]), "=r"(af[i][2]), "=r"(af[i][3])
                    : "r"(addr));
            }
            // B fragments: 4 x ldmatrix.x4 (each covers jn=2*jp, 2*jp+1)
            #pragma unroll
            for (int jp = 0; jp < 4; jp++) {
                int rowB = wn * 64 + jp * 16 + mr + ((mi >> 1) << 3);
                int colB = k16 * 16 + ((mi & 1) << 3);
                unsigned addr = st + (A4_BUF + rowB * HSTR + colB) * 2;
                asm volatile(
                    "ldmatrix.sync.aligned.m8n8.x4.shared.b16 {%0,%1,%2,%3}, [%4];"
                    : "=r"(bf[2 * jp][0]), "=r"(bf[2 * jp][1]),
                      "=r"(bf[2 * jp + 1][0]), "=r"(bf[2 * jp + 1][1])
                    : "r"(addr));
            }
            #pragma unroll
            for (int i = 0; i < 4; i++)
                #pragma unroll
                for (int jn = 0; jn < 8; jn++) {
                    asm volatile(
                        "mma.sync.aligned.m16n8k16.row.col.f32.f16.f16.f32 "
                        "{%0,%1,%2,%3}, {%4,%5,%6,%7}, {%8,%9}, {%0,%1,%2,%3};"
                        : "+f"(acc[i][jn][0]), "+f"(acc[i][jn][1]),
                          "+f"(acc[i][jn][2]), "+f"(acc[i][jn][3])
                        : "r"(af[i][0]), "r"(af[i][1]), "r"(af[i][2]), "r"(af[i][3]),
                          "r"(bf[jn][0]), "r"(bf[jn][1]));
                }
        }
    }

    // epilogue (M-guarded), runtime output dtype
    #pragma unroll
    for (int i = 0; i < 4; i++) {
        #pragma unroll
        for (int jn = 0; jn < 8; jn++) {
            int row = row0 + wm * 64 + i * 16 + g;
            int col = col0 + wn * 64 + jn * 8 + tg * 2;
            float b0 = 0.f, b1 = 0.f;
            if (bp != nullptr) { b0 = bp[col]; b1 = bp[col + 1]; }
            if (row < M) {
                if (outh)
                    *(__half2*)((__half*)Cp + (size_t)row * CC + col) =
                        __floats2half2_rn(acc[i][jn][0] + b0, acc[i][jn][1] + b1);
                else
                    *(float2*)((float*)Cp + (size_t)row * CC + col) =
                        make_float2(acc[i][jn][0] + b0, acc[i][jn][1] + b1);
            }
            if (row + 8 < M) {
                if (outh)
                    *(__half2*)((__half*)Cp + (size_t)(row + 8) * CC + col) =
                        __floats2half2_rn(acc[i][jn][2] + b0, acc[i][jn][3] + b1);
                else
                    *(float2*)((float*)Cp + (size_t)(row + 8) * CC + col) =
                        make_float2(acc[i][jn][2] + b0, acc[i][jn][3] + b1);
            }
        }
    }
}

// ---------------- CORA prep ----------------
__global__ __launch_bounds__(256) void cora_prep(
    const float* __restrict__ target, const float* __restrict__ anchor,
    const float* __restrict__ pres,
    float* __restrict__ uhat, float* __restrict__ ahat, float* __restrict__ Gout)
{
    __shared__ float red[32];
    __shared__ float ud[CC], ad[CC];
    const int s = blockIdx.x, tid = threadIdx.x;
    const float* p0 = pres + (size_t)s * CC;
    const float* p1 = pres + (size_t)(SS + s) * CC;
    const float* tg = target + (size_t)s * CC;
    const float* an = anchor + (size_t)s * CC;

    float g00 = 0, g01 = 0, g11 = 0, bt0 = 0, bt1 = 0, ba0 = 0, ba1 = 0;
    for (int d = tid; d < CC; d += 256) {
        float a = p0[d], b = p1[d], t = tg[d], u = an[d];
        g00 += a * a; g01 += a * b; g11 += b * b;
        bt0 += a * t; bt1 += b * t;
        ba0 += a * u; ba1 += b * u;
    }
    g00 = blockSum(g00, red); g01 = blockSum(g01, red); g11 = blockSum(g11, red);
    bt0 = blockSum(bt0, red); bt1 = blockSum(bt1, red);
    ba0 = blockSum(ba0, red); ba1 = blockSum(ba1, red);

    float det = g00 * g11 - g01 * g01;
    float ct0 = (g11 * bt0 - g01 * bt1) / det, ct1 = (g00 * bt1 - g01 * bt0) / det;
    float ca0 = (g11 * ba0 - g01 * ba1) / det, ca1 = (g00 * ba1 - g01 * ba0) / det;

    float nu2 = 0;
    for (int d = tid; d < CC; d += 256) {
        float udv = tg[d] - (p0[d] * ct0 + p1[d] * ct1);
        float adv = an[d] - (p0[d] * ca0 + p1[d] * ca1);
        ud[d] = udv; ad[d] = adv;
        nu2 += udv * udv;
    }
    nu2 = blockSum(nu2, red);
    float nu = sqrtf(nu2) + EPSI;

    float dua = 0;
    for (int d = tid; d < CC; d += 256) {
        float uh = ud[d] / nu;
        ud[d] = uh;
        uhat[(size_t)s * CC + d] = uh;
        dua += uh * ad[d];
    }
    dua = blockSum(dua, red);

    float na2 = 0;
    for (int d = tid; d < CC; d += 256) {
        float at = ad[d] - dua * ud[d];
        ad[d] = at;
        na2 += at * at;
    }
    na2 = blockSum(na2, red);
    float na = sqrtf(na2) + EPSI;

    for (int d = tid; d < CC; d += 256)
        ahat[(size_t)s * CC + d] = ad[d] / na;

    if (tid == 0) { Gout[s * 3 + 0] = g00; Gout[s * 3 + 1] = g01; Gout[s * 3 + 2] = g11; }
}

// ---------------- CORA apply ----------------
__global__ __launch_bounds__(256) void cora_apply(
    const float* __restrict__ Vin, const float* __restrict__ pres,
    const float* __restrict__ G, const float* __restrict__ uhat,
    const float* __restrict__ ahat, float* __restrict__ Ve)
{
    __shared__ float red[32];
    const int bs = blockIdx.x, s = bs % SS, tid = threadIdx.x;
    const float* v = Vin + (size_t)bs * CC;
    const float* p0 = pres + (size_t)s * CC;
    const float* p1 = pres + (size_t)(SS + s) * CC;
    const float* uh = uhat + (size_t)s * CC;
    const float* ah = ahat + (size_t)s * CC;

    float b0 = 0, b1 = 0;
    for (int d = tid; d < CC; d += 256) {
        float vd = v[d];
        b0 += p0[d] * vd; b1 += p1[d] * vd;
    }
    b0 = blockSum(b0, red); b1 = blockSum(b1, red);

    float g00 = G[s * 3], g01 = G[s * 3 + 1], g11 = G[s * 3 + 2];
    float det = g00 * g11 - g01 * g01;
    float c0 = (g11 * b0 - g01 * b1) / det;
    float c1 = (g00 * b1 - g01 * b0) / det;

    float nf2 = 0, t = 0;
    for (int d = tid; d < CC; d += 256) {
        float vp = p0[d] * c0 + p1[d] * c1;
        float vf = v[d] - vp;
        nf2 += vf * vf;
        t += uh[d] * vf;
    }
    nf2 = blockSum(nf2, red);
    t = blockSum(t, red);

    float denom = sqrtf(nf2) + EPSI;
    bool keep = (fabsf(t) / denom) < TAU;

    for (int d = tid; d < CC; d += 256) {
        float vp = p0[d] * c0 + p1[d] * c1;
        float vf = v[d] - vp;
        float vn = vp + vf - t * uh[d] + BETA * t * ah[d];
        Ve[(size_t)bs * CC + d] = keep ? v[d] : vn;
    }
}

// =====================================================================
// Tensor-core attention: per (b, h, 128-row tile).
// =====================================================================
#define AQ_ROWS 128
#define ASTRH 88
#define ATTN2_SMEM ((AQ_ROWS * ASTRH + 80 * ASTRH + 80 * ASTRH) * 2)

__global__ __launch_bounds__(256) void attn_tc(
    const __half* __restrict__ Q, const __half* __restrict__ Kp,
    const float* __restrict__ Vp, __half* __restrict__ O)
{
    extern __shared__ __half ash[];
    __half* Qs = ash;
    __half* Ks = Qs + AQ_ROWS * ASTRH;
    __half* Vt = Ks + 80 * ASTRH;

    const int b = blockIdx.z, h = blockIdx.y;
    const int n0 = blockIdx.x * AQ_ROWS;
    const int tid = threadIdx.x;

    {
        unsigned int* z = (unsigned int*)Ks;
        for (int i = tid; i < 2 * 80 * ASTRH / 2; i += 256) z[i] = 0u;
    }
    __syncthreads();

    for (int i = tid * 4; i < AQ_ROWS * DH; i += 1024) {
        int r = i / DH, d = i % DH;
        *(uint2*)&Qs[r * ASTRH + d] =
            *(const uint2*)(Q + ((size_t)(b * NN + n0 + r)) * CC + h * DH + d);
    }
    for (int i = tid * 4; i < SS * DH; i += 1024) {
        int r = i / DH, d = i % DH;
        *(uint2*)&Ks[r * ASTRH + d] =
            *(const uint2*)(Kp + ((size_t)(b * SS + r)) * CC + h * DH + d);
    }
    for (int i = tid; i < SS * DH; i += 256) {
        int s = i / DH, d = i % DH;
        Vt[d * ASTRH + s] =
            __float2half_rn(Vp[((size_t)(b * SS + s)) * CC + h * DH + d]);
    }
    __syncthreads();

    const int w = tid >> 5, lane = tid & 31;
    const int g = lane >> 2, tg = lane & 3;
    const int qrow = w * 16;

    float c[10][4];
    #pragma unroll
    for (int j = 0; j < 10; j++)
        #pragma unroll
        for (int e = 0; e < 4; e++) c[j][e] = 0.0f;

    const unsigned int* Qu = (const unsigned int*)Qs;
    const unsigned int* Ku = (const unsigned int*)Ks;
    #pragma unroll
    for (int kk = 0; kk < 5; kk++) {
        unsigned int a0, a1, a2, a3;
        const unsigned int* p = Qu + (qrow + g) * (ASTRH / 2) + kk * 8 + tg;
        a0 = p[0];
        a1 = p[8 * (ASTRH / 2)];
        a2 = p[4];
        a3 = p[8 * (ASTRH / 2) + 4];
        #pragma unroll
        for (int j = 0; j < 10; j++) {
            const unsigned int* q = Ku + (j * 8 + g) * (ASTRH / 2) + kk * 8 + tg;
            unsigned int b0 = q[0], b1 = q[4];
            asm volatile(
                "mma.sync.aligned.m16n8k16.row.col.f32.f16.f16.f32 "
                "{%0,%1,%2,%3}, {%4,%5,%6,%7}, {%8,%9}, {%0,%1,%2,%3};"
                : "+f"(c[j][0]), "+f"(c[j][1]), "+f"(c[j][2]), "+f"(c[j][3])
                : "r"(a0), "r"(a1), "r"(a2), "r"(a3), "r"(b0), "r"(b1));
        }
    }

    const float scale = 0.11180339887498948f;
    const float NEG = -1e30f;
    #pragma unroll
    for (int j = 0; j < 10; j++)
        #pragma unroll
        for (int e = 0; e < 4; e++) c[j][e] *= scale;
    if (tg == 2) { c[9][1] = NEG; c[9][3] = NEG; }
    if (tg == 3) { c[9][0] = NEG; c[9][1] = NEG; c[9][2] = NEG; c[9][3] = NEG; }

    float m0 = NEG, m1 = NEG;
    #pragma unroll
    for (int j = 0; j < 10; j++) {
        m0 = fmaxf(m0, fmaxf(c[j][0], c[j][1]));
        m1 = fmaxf(m1, fmaxf(c[j][2], c[j][3]));
    }
    m0 = fmaxf(m0, __shfl_xor_sync(0xffffffffu, m0, 1));
    m0 = fmaxf(m0, __shfl_xor_sync(0xffffffffu, m0, 2));
    m1 = fmaxf(m1, __shfl_xor_sync(0xffffffffu, m1, 1));
    m1 = fmaxf(m1, __shfl_xor_sync(0xffffffffu, m1, 2));

    float s0 = 0.f, s1 = 0.f;
    #pragma unroll
    for (int j = 0; j < 10; j++) {
        c[j][0] = expf(c[j][0] - m0);
        c[j][1] = expf(c[j][1] - m0);
        c[j][2] = expf(c[j][2] - m1);
        c[j][3] = expf(c[j][3] - m1);
        s0 += c[j][0] + c[j][1];
        s1 += c[j][2] + c[j][3];
    }
    s0 += __shfl_xor_sync(0xffffffffu, s0, 1);
    s0 += __shfl_xor_sync(0xffffffffu, s0, 2);
    s1 += __shfl_xor_sync(0xffffffffu, s1, 1);
    s1 += __shfl_xor_sync(0xffffffffu, s1, 2);
    const float i0 = 1.0f / s0, i1 = 1.0f / s1;
    #pragma unroll
    for (int j = 0; j < 10; j++) {
        c[j][0] *= i0; c[j][1] *= i0;
        c[j][2] *= i1; c[j][3] *= i1;
    }

    float o[10][4];
    #pragma unroll
    for (int j = 0; j < 10; j++)
        #pragma unroll
        for (int e = 0; e < 4; e++) o[j][e] = 0.0f;

    const unsigned int* Vu = (const unsigned int*)Vt;
    #pragma unroll
    for (int kk = 0; kk < 5; kk++) {
        __half2 ha0 = __floats2half2_rn(c[2 * kk][0],     c[2 * kk][1]);
        __half2 ha1 = __floats2half2_rn(c[2 * kk][2],     c[2 * kk][3]);
        __half2 ha2 = __floats2half2_rn(c[2 * kk + 1][0], c[2 * kk + 1][1]);
        __half2 ha3 = __floats2half2_rn(c[2 * kk + 1][2], c[2 * kk + 1][3]);
        unsigned int a0 = *(unsigned int*)&ha0;
        unsigned int a1 = *(unsigned int*)&ha1;
        unsigned int a2 = *(unsigned int*)&ha2;
        unsigned int a3 = *(unsigned int*)&ha3;
        #pragma unroll
        for (int jd = 0; jd < 10; jd++) {
            const unsigned int* q = Vu + (jd * 8 + g) * (ASTRH / 2) + kk * 8 + tg;
            unsigned int b0 = q[0], b1 = q[4];
            asm volatile(
                "mma.sync.aligned.m16n8k16.row.col.f32.f16.f16.f32 "
                "{%0,%1,%2,%3}, {%4,%5,%6,%7}, {%8,%9}, {%0,%1,%2,%3};"
                : "+f"(o[jd][0]), "+f"(o[jd][1]), "+f"(o[jd][2]), "+f"(o[jd][3])
                : "r"(a0), "r"(a1), "r"(a2), "r"(a3), "r"(b0), "r"(b1));
        }
    }

    const int r0 = n0 + qrow + g;
    #pragma unroll
    for (int jd = 0; jd < 10; jd++) {
        int col = h * DH + jd * 8 + tg * 2;
        *(__half2*)(O + ((size_t)(b * NN + r0)) * CC + col) =
            __floats2half2_rn(o[jd][0], o[jd][1]);
        *(__half2*)(O + ((size_t)(b * NN + r0 + 8)) * CC + col) =
            __floats2half2_rn(o[jd][2], o[jd][3]);
    }
}

// ---------------- launch ----------------
extern "C" void kernel_launch(void* const* d_in, const int* in_sizes, int n_in,
                              void* d_out, int out_size)
{
    static float *Vb = nullptr, *Veb = nullptr, *Uh = nullptr, *Ah = nullptr,
                 *Gm = nullptr;
    static __half *Xh = nullptr, *Eh = nullptr, *Qh = nullptr, *Kh = nullptr,
                  *Attnh = nullptr, *Wh = nullptr;
    static bool init = false;
    if (!init) {
        cudaGetSymbolAddress((void**)&Xh, g_Xh);
        cudaGetSymbolAddress((void**)&Eh, g_Eh);
        cudaGetSymbolAddress((void**)&Qh, g_Qh);
        cudaGetSymbolAddress((void**)&Attnh, g_attnh);
        cudaGetSymbolAddress((void**)&Kh, g_Kh);
        cudaGetSymbolAddress((void**)&Vb, g_V);
        cudaGetSymbolAddress((void**)&Veb, g_Ve);
        cudaGetSymbolAddress((void**)&Uh, g_uhat);
        cudaGetSymbolAddress((void**)&Ah, g_ahat);
        cudaGetSymbolAddress((void**)&Gm, g_G);
        cudaGetSymbolAddress((void**)&Wh, g_Wh);
        cudaFuncSetAttribute(attn_tc, cudaFuncAttributeMaxDynamicSharedMemorySize,
                             ATTN2_SMEM);
        cudaFuncSetAttribute(gemm_v4, cudaFuncAttributeMaxDynamicSharedMemorySize,
                             GV4_SMEM);
        init = true;
    }

    const float* X    = (const float*)d_in[0];
    const float* E    = (const float*)d_in[1];
    const float* Wq   = (const float*)d_in[2];
    const float* Wk   = (const float*)d_in[3];
    const float* Wv   = (const float*)d_in[4];
    const float* Wo   = (const float*)d_in[5];
    const float* bo   = (const float*)d_in[6];
    const float* tgt  = (const float*)d_in[7];
    const float* anc  = (const float*)d_in[8];
    const float* pres = (const float*)d_in[9];
    float* out = (float*)d_out;

    __half* WqT = Wh + 0 * (XD * CC);
    __half* WkT = Wh + 1 * (XD * CC);
    __half* WvT = Wh + 2 * (XD * CC);
    __half* WoT = Wh + 3 * (XD * CC);

    // fp16 conversions + fused weight transpose
    to_half8<<<(BB * NN * CC) / 8 / 256, 256>>>(X, Xh, BB * NN * CC);
    to_half8<<<((BB * SS * XD) / 8 + 255) / 256, 256>>>(E, Eh, BB * SS * XD);
    transpose_all<<<dim3(CC / 32, XD / 32, 4), 256>>>(Wq, Wk, Wv, Wo, Wh);

    // Q projection: [32768,640] x [640,640] -> fp16
    gemm_v4<<<dim3(CC / 128, (BB * NN) / 256), 256, GV4_SMEM>>>(
        Xh, WqT, nullptr, Qh, 1, nullptr, nullptr, 0, CC / 128, BB * NN, CC);

    // K (fp16 out) + V (fp32 out) projections in ONE launch (dual-B)
    gemm_v4<<<dim3(2 * (CC / 128), (BB * SS + 255) / 256), 256, GV4_SMEM>>>(
        Eh, WkT, nullptr, Kh, 1, WvT, Vb, 0, CC / 128, BB * SS, XD);

    // CORA erase on V
    cora_prep<<<SS, 256>>>(tgt, anc, pres, Uh, Ah, Gm);
    cora_apply<<<BB * SS, 256>>>(Vb, pres, Gm, Uh, Ah, Veb);

    // tensor-core attention (writes fp16)
    attn_tc<<<dim3(NN / AQ_ROWS, HH, BB), 256, ATTN2_SMEM>>>(Qh, Kh, Veb, Attnh);

    // output projection + bias (fp32 out)
    gemm_v4<<<dim3(CC / 128, (BB * NN) / 256), 256, GV4_SMEM>>>(
        Attnh, WoT, bo, out, 0, nullptr, nullptr, 0, CC / 128, BB * NN, CC);
}

// round 11
// speedup vs baseline: 5.0847x; 1.2448x over previous
#include <cuda_runtime.h>
#include <cuda_fp16.h>
#include <math.h>
#include <stdint.h>

// Problem constants
#define BB 8
#define NN 4096
#define CC 640
#define SS 77
#define XD 768
#define HH 8
#define DH 80
#define BETA 0.5f
#define TAU 0.1f
#define EPSI 1e-8f

// ---------------- scratch (no cudaMalloc allowed) ----------------
__device__ __half g_Xh[BB * NN * CC];      // 41.9 MB (X, fp16)
__device__ __half g_Qh[BB * NN * CC];      // 41.9 MB (Q, fp16)
__device__ __half g_attnh[BB * NN * CC];   // 41.9 MB (attention out, fp16)
__device__ __half g_Eh[BB * SS * XD];      // E, fp16
__device__ __half g_Kh[BB * SS * CC];      // K, fp16
__device__ float g_V[BB * SS * CC];
__device__ float g_Ve[BB * SS * CC];
__device__ float g_uhat[SS * CC];
__device__ float g_ahat[SS * CC];
__device__ float g_G[SS * 3];
__device__ __half g_Wh[4][XD * CC];        // transposed fp16 weights [n][k]

// ---------------- block reduce helper ----------------
__device__ __forceinline__ float blockSum(float v, float* red) {
    #pragma unroll
    for (int o = 16; o; o >>= 1) v += __shfl_xor_sync(0xffffffffu, v, o);
    int w = threadIdx.x >> 5, l = threadIdx.x & 31;
    __syncthreads();
    if (l == 0) red[w] = v;
    __syncthreads();
    if (w == 0) {
        float x = (l < (int)(blockDim.x >> 5)) ? red[l] : 0.0f;
        #pragma unroll
        for (int o = 4; o; o >>= 1) x += __shfl_xor_sync(0xffffffffu, x, o);
        if (l == 0) red[0] = x;
    }
    __syncthreads();
    return red[0];
}

// ---------------- fp32 -> fp16 bulk convert (n % 8 == 0) ----------------
__global__ __launch_bounds__(256) void to_half8(
    const float* __restrict__ src, __half* __restrict__ dst, int n)
{
    int i = (blockIdx.x * 256 + threadIdx.x) * 8;
    if (i >= n) return;
    float4 a = *(const float4*)(src + i);
    float4 b = *(const float4*)(src + i + 4);
    __half2 h[4];
    h[0] = __floats2half2_rn(a.x, a.y);
    h[1] = __floats2half2_rn(a.z, a.w);
    h[2] = __floats2half2_rn(b.x, b.y);
    h[3] = __floats2half2_rn(b.z, b.w);
    *(uint4*)(dst + i) = *(uint4*)h;
}

// ---------------- fused weight transpose + fp16: Wh[z][n][k] ----------------
__global__ __launch_bounds__(256) void transpose_all(
    const float* __restrict__ Wq, const float* __restrict__ Wk,
    const float* __restrict__ Wv, const float* __restrict__ Wo,
    __half* __restrict__ Wh)
{
    __shared__ float t[32][33];
    const int z = blockIdx.z;
    const float* W = (z == 0) ? Wq : (z == 1) ? Wk : (z == 2) ? Wv : Wo;
    const int K = (z == 1 || z == 2) ? XD : CC;
    __half* Wt = Wh + (size_t)z * (XD * CC);

    const int k0 = blockIdx.y * 32, n0 = blockIdx.x * 32;
    if (k0 >= K) return;
    const int tx = threadIdx.x & 31, ty = threadIdx.x >> 5;
    #pragma unroll
    for (int i = ty; i < 32; i += 8) {
        int k = k0 + i, n = n0 + tx;
        if (k < K) t[i][tx] = W[(size_t)k * CC + n];
    }
    __syncthreads();
    #pragma unroll
    for (int i = ty; i < 32; i += 8) {
        int n = n0 + i, k = k0 + tx;
        if (k < K)
            Wt[(size_t)n * K + k] = __float2half_rn(t[tx][i]);
    }
}

// =====================================================================
// FP16 tensor-core GEMM v5: C[M,640] = A[M,K] @ W[K,640]
// CTA 128x128x32, 8 warps (2x4), warp tile 64x32, m16n8k16.
// 4-stage cp.async pipeline + ldmatrix; __launch_bounds__(256,2) for
// 2 CTAs/SM co-residency (bubble filling). Dual-B, runtime out dtype.
// =====================================================================
#define HSTR 40
#define A5_BUF (128 * HSTR)     // halfs per stage (A)
#define B5_BUF (128 * HSTR)     // halfs per stage (B)
#define ST5_BUF (A5_BUF + B5_BUF)
#define GV5_SMEM (4 * ST5_BUF * 2)   // 81920 B

__global__ __launch_bounds__(256, 2) void gemm_v5(
    const __half* __restrict__ A,
    const __half* __restrict__ B1, const float* __restrict__ bias,
    void* __restrict__ C1, int outh1,
    const __half* __restrict__ B2, void* __restrict__ C2, int outh2,
    int nsplit, int M, int K)
{
    extern __shared__ __half sh[];
    const int tid = threadIdx.x;
    int bx = blockIdx.x;
    const __half* Bt = B1;
    void* Cp = C1;
    int outh = outh1;
    const float* bp = bias;
    if (B2 != nullptr && bx >= nsplit) { Bt = B2; Cp = C2; outh = outh2; bp = nullptr; bx -= nsplit; }

    const int wid = tid >> 5, lane = tid & 31;
    const int wm = wid >> 2, wn = wid & 3;     // 2 x 4 warp grid
    const int g = lane >> 2, tg = lane & 3;
    const int row0 = blockIdx.y * 128, col0 = bx * 128;

    const unsigned smem_base = (unsigned)__cvta_generic_to_shared(sh);
    const int cr = tid >> 2;            // 0..63
    const int cc = (tid & 3) * 8;       // 0,8,16,24 (halfs)
    const int mi = lane >> 3;           // ldmatrix sub-matrix index 0..3
    const int mr = lane & 7;            // ldmatrix row within sub-matrix

    float acc[4][4][4];
    #pragma unroll
    for (int i = 0; i < 4; i++)
        #pragma unroll
        for (int j = 0; j < 4; j++)
            #pragma unroll
            for (int r = 0; r < 4; r++) acc[i][j][r] = 0.0f;

    const int KT = K / 32;

    auto issue = [&](int tile, int stage) {
        const unsigned sb = smem_base + stage * ST5_BUF * 2;
        #pragma unroll
        for (int j = 0; j < 2; j++) {
            int r = cr + j * 64;
            int gr = row0 + r;
            int sz = (gr < M) ? 16 : 0;
            const __half* src = A + (size_t)(gr < M ? gr : (M - 1)) * K + tile * 32 + cc;
            unsigned dst = sb + (r * HSTR + cc) * 2;
            asm volatile("cp.async.cg.shared.global [%0], [%1], 16, %2;"
                         :: "r"(dst), "l"(src), "r"(sz));
        }
        #pragma unroll
        for (int j = 0; j < 2; j++) {
            int r = cr + j * 64;
            const __half* src = Bt + (size_t)(col0 + r) * K + tile * 32 + cc;
            unsigned dst = sb + (A5_BUF + r * HSTR + cc) * 2;
            asm volatile("cp.async.cg.shared.global [%0], [%1], 16, %2;"
                         :: "r"(dst), "l"(src), "r"(16));
        }
        asm volatile("cp.async.commit_group;");
    };

    issue(0, 0);
    if (KT > 1) issue(1, 1);
    if (KT > 2) issue(2, 2);

    #pragma unroll 1
    for (int kt = 0; kt < KT; kt++) {
        if (kt < KT - 2) asm volatile("cp.async.wait_group 2;");
        else             asm volatile("cp.async.wait_group 0;");
        __syncthreads();
        if (kt + 3 < KT) issue(kt + 3, (kt + 3) & 3);

        const unsigned st = smem_base + (kt & 3) * ST5_BUF * 2;
        #pragma unroll
        for (int k16 = 0; k16 < 2; k16++) {
            unsigned int af[4][4], bf[4][2];
            #pragma unroll
            for (int i = 0; i < 4; i++) {
                int rowA = wm * 64 + i * 16 + mr + ((mi & 1) << 3);
                int colA = k16 * 16 + ((mi >> 1) << 3);
                unsigned addr = st + (rowA * HSTR + colA) * 2;
                asm volatile(
                    "ldmatrix.sync.aligned.m8n8.x4.shared.b16 {%0,%1,%2,%3}, [%4];"
                    : "=r"(af[i][0]), "=r"(af[i][1]), "=r"(af[i][2]), "=r"(af[i][3])
                    : "r"(addr));
            }
            #pragma unroll
            for (int jp = 0; jp < 2; jp++) {
                int rowB = wn * 32 + jp * 16 + mr + ((mi >> 1) << 3);
                int colB = k16 * 16 + ((mi & 1) << 3);
                unsigned addr = st + (A5_BUF + rowB * HSTR + colB) * 2;
                asm volatile(
                    "ldmatrix.sync.aligned.m8n8.x4.shared.b16 {%0,%1,%2,%3}, [%4];"
                    : "=r"(bf[2 * jp][0]), "=r"(bf[2 * jp][1]),
                      "=r"(bf[2 * jp + 1][0]), "=r"(bf[2 * jp + 1][1])
                    : "r"(addr));
            }
            #pragma unroll
            for (int i = 0; i < 4; i++)
                #pragma unroll
                for (int jn = 0; jn < 4; jn++) {
                    asm volatile(
                        "mma.sync.aligned.m16n8k16.row.col.f32.f16.f16.f32 "
                        "{%0,%1,%2,%3}, {%4,%5,%6,%7}, {%8,%9}, {%0,%1,%2,%3};"
                        : "+f"(acc[i][jn][0]), "+f"(acc[i][jn][1]),
                          "+f"(acc[i][jn][2]), "+f"(acc[i][jn][3])
                        : "r"(af[i][0]), "r"(af[i][1]), "r"(af[i][2]), "r"(af[i][3]),
                          "r"(bf[jn][0]), "r"(bf[jn][1]));
                }
        }
    }

    // epilogue (M-guarded), runtime output dtype
    #pragma unroll
    for (int i = 0; i < 4; i++) {
        #pragma unroll
        for (int jn = 0; jn < 4; jn++) {
            int row = row0 + wm * 64 + i * 16 + g;
            int col = col0 + wn * 32 + jn * 8 + tg * 2;
            float b0 = 0.f, b1 = 0.f;
            if (bp != nullptr) { b0 = bp[col]; b1 = bp[col + 1]; }
            if (row < M) {
                if (outh)
                    *(__half2*)((__half*)Cp + (size_t)row * CC + col) =
                        __floats2half2_rn(acc[i][jn][0] + b0, acc[i][jn][1] + b1);
                else
                    *(float2*)((float*)Cp + (size_t)row * CC + col) =
                        make_float2(acc[i][jn][0] + b0, acc[i][jn][1] + b1);
            }
            if (row + 8 < M) {
                if (outh)
                    *(__half2*)((__half*)Cp + (size_t)(row + 8) * CC + col) =
                        __floats2half2_rn(acc[i][jn][2] + b0, acc[i][jn][3] + b1);
                else
                    *(float2*)((float*)Cp + (size_t)(row + 8) * CC + col) =
                        make_float2(acc[i][jn][2] + b0, acc[i][jn][3] + b1);
            }
        }
    }
}

// ---------------- CORA prep ----------------
__global__ __launch_bounds__(256) void cora_prep(
    const float* __restrict__ target, const float* __restrict__ anchor,
    const float* __restrict__ pres,
    float* __restrict__ uhat, float* __restrict__ ahat, float* __restrict__ Gout)
{
    __shared__ float red[32];
    __shared__ float ud[CC], ad[CC];
    const int s = blockIdx.x, tid = threadIdx.x;
    const float* p0 = pres + (size_t)s * CC;
    const float* p1 = pres + (size_t)(SS + s) * CC;
    const float* tg = target + (size_t)s * CC;
    const float* an = anchor + (size_t)s * CC;

    float g00 = 0, g01 = 0, g11 = 0, bt0 = 0, bt1 = 0, ba0 = 0, ba1 = 0;
    for (int d = tid; d < CC; d += 256) {
        float a = p0[d], b = p1[d], t = tg[d], u = an[d];
        g00 += a * a; g01 += a * b; g11 += b * b;
        bt0 += a * t; bt1 += b * t;
        ba0 += a * u; ba1 += b * u;
    }
    g00 = blockSum(g00, red); g01 = blockSum(g01, red); g11 = blockSum(g11, red);
    bt0 = blockSum(bt0, red); bt1 = blockSum(bt1, red);
    ba0 = blockSum(ba0, red); ba1 = blockSum(ba1, red);

    float det = g00 * g11 - g01 * g01;
    float ct0 = (g11 * bt0 - g01 * bt1) / det, ct1 = (g00 * bt1 - g01 * bt0) / det;
    float ca0 = (g11 * ba0 - g01 * ba1) / det, ca1 = (g00 * ba1 - g01 * ba0) / det;

    float nu2 = 0;
    for (int d = tid; d < CC; d += 256) {
        float udv = tg[d] - (p0[d] * ct0 + p1[d] * ct1);
        float adv = an[d] - (p0[d] * ca0 + p1[d] * ca1);
        ud[d] = udv; ad[d] = adv;
        nu2 += udv * udv;
    }
    nu2 = blockSum(nu2, red);
    float nu = sqrtf(nu2) + EPSI;

    float dua = 0;
    for (int d = tid; d < CC; d += 256) {
        float uh = ud[d] / nu;
        ud[d] = uh;
        uhat[(size_t)s * CC + d] = uh;
        dua += uh * ad[d];
    }
    dua = blockSum(dua, red);

    float na2 = 0;
    for (int d = tid; d < CC; d += 256) {
        float at = ad[d] - dua * ud[d];
        ad[d] = at;
        na2 += at * at;
    }
    na2 = blockSum(na2, red);
    float na = sqrtf(na2) + EPSI;

    for (int d = tid; d < CC; d += 256)
        ahat[(size_t)s * CC + d] = ad[d] / na;

    if (tid == 0) { Gout[s * 3 + 0] = g00; Gout[s * 3 + 1] = g01; Gout[s * 3 + 2] = g11; }
}

// ---------------- CORA apply ----------------
__global__ __launch_bounds__(256) void cora_apply(
    const float* __restrict__ Vin, const float* __restrict__ pres,
    const float* __restrict__ G, const float* __restrict__ uhat,
    const float* __restrict__ ahat, float* __restrict__ Ve)
{
    __shared__ float red[32];
    const int bs = blockIdx.x, s = bs % SS, tid = threadIdx.x;
    const float* v = Vin + (size_t)bs * CC;
    const float* p0 = pres + (size_t)s * CC;
    const float* p1 = pres + (size_t)(SS + s) * CC;
    const float* uh = uhat + (size_t)s * CC;
    const float* ah = ahat + (size_t)s * CC;

    float b0 = 0, b1 = 0;
    for (int d = tid; d < CC; d += 256) {
        float vd = v[d];
        b0 += p0[d] * vd; b1 += p1[d] * vd;
    }
    b0 = blockSum(b0, red); b1 = blockSum(b1, red);

    float g00 = G[s * 3], g01 = G[s * 3 + 1], g11 = G[s * 3 + 2];
    float det = g00 * g11 - g01 * g01;
    float c0 = (g11 * b0 - g01 * b1) / det;
    float c1 = (g00 * b1 - g01 * b0) / det;

    float nf2 = 0, t = 0;
    for (int d = tid; d < CC; d += 256) {
        float vp = p0[d] * c0 + p1[d] * c1;
        float vf = v[d] - vp;
        nf2 += vf * vf;
        t += uh[d] * vf;
    }
    nf2 = blockSum(nf2, red);
    t = blockSum(t, red);

    float denom = sqrtf(nf2) + EPSI;
    bool keep = (fabsf(t) / denom) < TAU;

    for (int d = tid; d < CC; d += 256) {
        float vp = p0[d] * c0 + p1[d] * c1;
        float vf = v[d] - vp;
        float vn = vp + vf - t * uh[d] + BETA * t * ah[d];
        Ve[(size_t)bs * CC + d] = keep ? v[d] : vn;
    }
}

// =====================================================================
// Tensor-core attention: per (b, h, 128-row tile).
// =====================================================================
#define AQ_ROWS 128
#define ASTRH 88
#define ATTN2_SMEM ((AQ_ROWS * ASTRH + 80 * ASTRH + 80 * ASTRH) * 2)

__global__ __launch_bounds__(256) void attn_tc(
    const __half* __restrict__ Q, const __half* __restrict__ Kp,
    const float* __restrict__ Vp, __half* __restrict__ O)
{
    extern __shared__ __half ash[];
    __half* Qs = ash;
    __half* Ks = Qs + AQ_ROWS * ASTRH;
    __half* Vt = Ks + 80 * ASTRH;

    const int b = blockIdx.z, h = blockIdx.y;
    const int n0 = blockIdx.x * AQ_ROWS;
    const int tid = threadIdx.x;

    {
        unsigned int* z = (unsigned int*)Ks;
        for (int i = tid; i < 2 * 80 * ASTRH / 2; i += 256) z[i] = 0u;
    }
    __syncthreads();

    for (int i = tid * 4; i < AQ_ROWS * DH; i += 1024) {
        int r = i / DH, d = i % DH;
        *(uint2*)&Qs[r * ASTRH + d] =
            *(const uint2*)(Q + ((size_t)(b * NN + n0 + r)) * CC + h * DH + d);
    }
    for (int i = tid * 4; i < SS * DH; i += 1024) {
        int r = i / DH, d = i % DH;
        *(uint2*)&Ks[r * ASTRH + d] =
            *(const uint2*)(Kp + ((size_t)(b * SS + r)) * CC + h * DH + d);
    }
    for (int i = tid; i < SS * DH; i += 256) {
        int s = i / DH, d = i % DH;
        Vt[d * ASTRH + s] =
            __float2half_rn(Vp[((size_t)(b * SS + s)) * CC + h * DH + d]);
    }
    __syncthreads();

    const int w = tid >> 5, lane = tid & 31;
    const int g = lane >> 2, tg = lane & 3;
    const int qrow = w * 16;

    float c[10][4];
    #pragma unroll
    for (int j = 0; j < 10; j++)
        #pragma unroll
        for (int e = 0; e < 4; e++) c[j][e] = 0.0f;

    const unsigned int* Qu = (const unsigned int*)Qs;
    const unsigned int* Ku = (const unsigned int*)Ks;
    #pragma unroll
    for (int kk = 0; kk < 5; kk++) {
        unsigned int a0, a1, a2, a3;
        const unsigned int* p = Qu + (qrow + g) * (ASTRH / 2) + kk * 8 + tg;
        a0 = p[0];
        a1 = p[8 * (ASTRH / 2)];
        a2 = p[4];
        a3 = p[8 * (ASTRH / 2) + 4];
        #pragma unroll
        for (int j = 0; j < 10; j++) {
            const unsigned int* q = Ku + (j * 8 + g) * (ASTRH / 2) + kk * 8 + tg;
            unsigned int b0 = q[0], b1 = q[4];
            asm volatile(
                "mma.sync.aligned.m16n8k16.row.col.f32.f16.f16.f32 "
                "{%0,%1,%2,%3}, {%4,%5,%6,%7}, {%8,%9}, {%0,%1,%2,%3};"
                : "+f"(c[j][0]), "+f"(c[j][1]), "+f"(c[j][2]), "+f"(c[j][3])
                : "r"(a0), "r"(a1), "r"(a2), "r"(a3), "r"(b0), "r"(b1));
        }
    }

    const float scale = 0.11180339887498948f;
    const float NEG = -1e30f;
    #pragma unroll
    for (int j = 0; j < 10; j++)
        #pragma unroll
        for (int e = 0; e < 4; e++) c[j][e] *= scale;
    if (tg == 2) { c[9][1] = NEG; c[9][3] = NEG; }
    if (tg == 3) { c[9][0] = NEG; c[9][1] = NEG; c[9][2] = NEG; c[9][3] = NEG; }

    float m0 = NEG, m1 = NEG;
    #pragma unroll
    for (int j = 0; j < 10; j++) {
        m0 = fmaxf(m0, fmaxf(c[j][0], c[j][1]));
        m1 = fmaxf(m1, fmaxf(c[j][2], c[j][3]));
    }
    m0 = fmaxf(m0, __shfl_xor_sync(0xffffffffu, m0, 1));
    m0 = fmaxf(m0, __shfl_xor_sync(0xffffffffu, m0, 2));
    m1 = fmaxf(m1, __shfl_xor_sync(0xffffffffu, m1, 1));
    m1 = fmaxf(m1, __shfl_xor_sync(0xffffffffu, m1, 2));

    float s0 = 0.f, s1 = 0.f;
    #pragma unroll
    for (int j = 0; j < 10; j++) {
        c[j][0] = expf(c[j][0] - m0);
        c[j][1] = expf(c[j][1] - m0);
        c[j][2] = expf(c[j][2] - m1);
        c[j][3] = expf(c[j][3] - m1);
        s0 += c[j][0] + c[j][1];
        s1 += c[j][2] + c[j][3];
    }
    s0 += __shfl_xor_sync(0xffffffffu, s0, 1);
    s0 += __shfl_xor_sync(0xffffffffu, s0, 2);
    s1 += __shfl_xor_sync(0xffffffffu, s1, 1);
    s1 += __shfl_xor_sync(0xffffffffu, s1, 2);
    const float i0 = 1.0f / s0, i1 = 1.0f / s1;
    #pragma unroll
    for (int j = 0; j < 10; j++) {
        c[j][0] *= i0; c[j][1] *= i0;
        c[j][2] *= i1; c[j][3] *= i1;
    }

    float o[10][4];
    #pragma unroll
    for (int j = 0; j < 10; j++)
        #pragma unroll
        for (int e = 0; e < 4; e++) o[j][e] = 0.0f;

    const unsigned int* Vu = (const unsigned int*)Vt;
    #pragma unroll
    for (int kk = 0; kk < 5; kk++) {
        __half2 ha0 = __floats2half2_rn(c[2 * kk][0],     c[2 * kk][1]);
        __half2 ha1 = __floats2half2_rn(c[2 * kk][2],     c[2 * kk][3]);
        __half2 ha2 = __floats2half2_rn(c[2 * kk + 1][0], c[2 * kk + 1][1]);
        __half2 ha3 = __floats2half2_rn(c[2 * kk + 1][2], c[2 * kk + 1][3]);
        unsigned int a0 = *(unsigned int*)&ha0;
        unsigned int a1 = *(unsigned int*)&ha1;
        unsigned int a2 = *(unsigned int*)&ha2;
        unsigned int a3 = *(unsigned int*)&ha3;
        #pragma unroll
        for (int jd = 0; jd < 10; jd++) {
            const unsigned int* q = Vu + (jd * 8 + g) * (ASTRH / 2) + kk * 8 + tg;
            unsigned int b0 = q[0], b1 = q[4];
            asm volatile(
                "mma.sync.aligned.m16n8k16.row.col.f32.f16.f16.f32 "
                "{%0,%1,%2,%3}, {%4,%5,%6,%7}, {%8,%9}, {%0,%1,%2,%3};"
                : "+f"(o[jd][0]), "+f"(o[jd][1]), "+f"(o[jd][2]), "+f"(o[jd][3])
                : "r"(a0), "r"(a1), "r"(a2), "r"(a3), "r"(b0), "r"(b1));
        }
    }

    const int r0 = n0 + qrow + g;
    #pragma unroll
    for (int jd = 0; jd < 10; jd++) {
        int col = h * DH + jd * 8 + tg * 2;
        *(__half2*)(O + ((size_t)(b * NN + r0)) * CC + col) =
            __floats2half2_rn(o[jd][0], o[jd][1]);
        *(__half2*)(O + ((size_t)(b * NN + r0 + 8)) * CC + col) =
            __floats2half2_rn(o[jd][2], o[jd][3]);
    }
}

// ---------------- launch ----------------
extern "C" void kernel_launch(void* const* d_in, const int* in_sizes, int n_in,
                              void* d_out, int out_size)
{
    static float *Vb = nullptr, *Veb = nullptr, *Uh = nullptr, *Ah = nullptr,
                 *Gm = nullptr;
    static __half *Xh = nullptr, *Eh = nullptr, *Qh = nullptr, *Kh = nullptr,
                  *Attnh = nullptr, *Wh = nullptr;
    static bool init = false;
    if (!init) {
        cudaGetSymbolAddress((void**)&Xh, g_Xh);
        cudaGetSymbolAddress((void**)&Eh, g_Eh);
        cudaGetSymbolAddress((void**)&Qh, g_Qh);
        cudaGetSymbolAddress((void**)&Attnh, g_attnh);
        cudaGetSymbolAddress((void**)&Kh, g_Kh);
        cudaGetSymbolAddress((void**)&Vb, g_V);
        cudaGetSymbolAddress((void**)&Veb, g_Ve);
        cudaGetSymbolAddress((void**)&Uh, g_uhat);
        cudaGetSymbolAddress((void**)&Ah, g_ahat);
        cudaGetSymbolAddress((void**)&Gm, g_G);
        cudaGetSymbolAddress((void**)&Wh, g_Wh);
        cudaFuncSetAttribute(attn_tc, cudaFuncAttributeMaxDynamicSharedMemorySize,
                             ATTN2_SMEM);
        cudaFuncSetAttribute(gemm_v5, cudaFuncAttributeMaxDynamicSharedMemorySize,
                             GV5_SMEM);
        init = true;
    }

    const float* X    = (const float*)d_in[0];
    const float* E    = (const float*)d_in[1];
    const float* Wq   = (const float*)d_in[2];
    const float* Wk   = (const float*)d_in[3];
    const float* Wv   = (const float*)d_in[4];
    const float* Wo   = (const float*)d_in[5];
    const float* bo   = (const float*)d_in[6];
    const float* tgt  = (const float*)d_in[7];
    const float* anc  = (const float*)d_in[8];
    const float* pres = (const float*)d_in[9];
    float* out = (float*)d_out;

    __half* WqT = Wh + 0 * (XD * CC);
    __half* WkT = Wh + 1 * (XD * CC);
    __half* WvT = Wh + 2 * (XD * CC);
    __half* WoT = Wh + 3 * (XD * CC);

    // fp16 conversions + fused weight transpose
    to_half8<<<(BB * NN * CC) / 8 / 256, 256>>>(X, Xh, BB * NN * CC);
    to_half8<<<((BB * SS * XD) / 8 + 255) / 256, 256>>>(E, Eh, BB * SS * XD);
    transpose_all<<<dim3(CC / 32, XD / 32, 4), 256>>>(Wq, Wk, Wv, Wo, Wh);

    // Q projection: [32768,640] x [640,640] -> fp16
    gemm_v5<<<dim3(CC / 128, (BB * NN) / 128), 256, GV5_SMEM>>>(
        Xh, WqT, nullptr, Qh, 1, nullptr, nullptr, 0, CC / 128, BB * NN, CC);

    // K (fp16 out) + V (fp32 out) projections in ONE launch (dual-B)
    gemm_v5<<<dim3(2 * (CC / 128), (BB * SS + 127) / 128), 256, GV5_SMEM>>>(
        Eh, WkT, nullptr, Kh, 1, WvT, Vb, 0, CC / 128, BB * SS, XD);

    // CORA erase on V
    cora_prep<<<SS, 256>>>(tgt, anc, pres, Uh, Ah, Gm);
    cora_apply<<<BB * SS, 256>>>(Vb, pres, Gm, Uh, Ah, Veb);

    // tensor-core attention (writes fp16)
    attn_tc<<<dim3(NN / AQ_ROWS, HH, BB), 256, ATTN2_SMEM>>>(Qh, Kh, Veb, Attnh);

    // output projection + bias (fp32 out)
    gemm_v5<<<dim3(CC / 128, (BB * NN) / 128), 256, GV5_SMEM>>>(
        Attnh, WoT, bo, out, 0, nullptr, nullptr, 0, CC / 128, BB * NN, CC);
}

// round 12
// speedup vs baseline: 5.3600x; 1.0541x over previous
#include <cuda_runtime.h>
#include <cuda_fp16.h>
#include <math.h>
#include <stdint.h>

// Problem constants
#define BB 8
#define NN 4096
#define CC 640
#define SS 77
#define XD 768
#define HH 8
#define DH 80
#define BETA 0.5f
#define TAU 0.1f
#define EPSI 1e-8f

// ---------------- scratch (no cudaMalloc allowed) ----------------
__device__ __half g_Xh[BB * NN * CC];      // 41.9 MB (X, fp16)
__device__ __half g_Qh[BB * NN * CC];      // 41.9 MB (Q, fp16)
__device__ __half g_attnh[BB * NN * CC];   // 41.9 MB (attention out, fp16)
__device__ __half g_Eh[BB * SS * XD];      // E, fp16
__device__ __half g_Kh[BB * SS * CC];      // K, fp16
__device__ float g_V[BB * SS * CC];
__device__ float g_Ve[BB * SS * CC];
__device__ float g_uhat[SS * CC];
__device__ float g_ahat[SS * CC];
__device__ float g_G[SS * 3];
__device__ __half g_Wh[4][XD * CC];        // transposed fp16 weights [n][k]

// ---------------- block reduce helper ----------------
__device__ __forceinline__ float blockSum(float v, float* red) {
    #pragma unroll
    for (int o = 16; o; o >>= 1) v += __shfl_xor_sync(0xffffffffu, v, o);
    int w = threadIdx.x >> 5, l = threadIdx.x & 31;
    __syncthreads();
    if (l == 0) red[w] = v;
    __syncthreads();
    if (w == 0) {
        float x = (l < (int)(blockDim.x >> 5)) ? red[l] : 0.0f;
        #pragma unroll
        for (int o = 4; o; o >>= 1) x += __shfl_xor_sync(0xffffffffu, x, o);
        if (l == 0) red[0] = x;
    }
    __syncthreads();
    return red[0];
}

// ---------------- fp32 -> fp16 bulk convert (n % 8 == 0) ----------------
__global__ __launch_bounds__(256) void to_half8(
    const float* __restrict__ src, __half* __restrict__ dst, int n)
{
    int i = (blockIdx.x * 256 + threadIdx.x) * 8;
    if (i >= n) return;
    float4 a = *(const float4*)(src + i);
    float4 b = *(const float4*)(src + i + 4);
    __half2 h[4];
    h[0] = __floats2half2_rn(a.x, a.y);
    h[1] = __floats2half2_rn(a.z, a.w);
    h[2] = __floats2half2_rn(b.x, b.y);
    h[3] = __floats2half2_rn(b.z, b.w);
    *(uint4*)(dst + i) = *(uint4*)h;
}

// ---------------- fused weight transpose + fp16: Wh[z][n][k] ----------------
__global__ __launch_bounds__(256) void transpose_all(
    const float* __restrict__ Wq, const float* __restrict__ Wk,
    const float* __restrict__ Wv, const float* __restrict__ Wo,
    __half* __restrict__ Wh)
{
    __shared__ float t[32][33];
    const int z = blockIdx.z;
    const float* W = (z == 0) ? Wq : (z == 1) ? Wk : (z == 2) ? Wv : Wo;
    const int K = (z == 1 || z == 2) ? XD : CC;
    __half* Wt = Wh + (size_t)z * (XD * CC);

    const int k0 = blockIdx.y * 32, n0 = blockIdx.x * 32;
    if (k0 >= K) return;
    const int tx = threadIdx.x & 31, ty = threadIdx.x >> 5;
    #pragma unroll
    for (int i = ty; i < 32; i += 8) {
        int k = k0 + i, n = n0 + tx;
        if (k < K) t[i][tx] = W[(size_t)k * CC + n];
    }
    __syncthreads();
    #pragma unroll
    for (int i = ty; i < 32; i += 8) {
        int n = n0 + i, k = k0 + tx;
        if (k < K)
            Wt[(size_t)n * K + k] = __float2half_rn(t[tx][i]);
    }
}

// =====================================================================
// FP16 tensor-core GEMM v6: C[M,640] = A[M,K] @ W[K,640]
// CTA 128x128, 8 warps (2x4), warp tile 64x32, m16n8k16.
// k64 pipeline stages (3-stage cp.async) + ldmatrix; 1 sync per k64.
// __launch_bounds__(256,2) for 2 CTAs/SM. Dual-B, runtime out dtype.
// Requires K % 64 == 0.
// =====================================================================
#define HSTR6 72                 // halfs per smem row (64 + 8 pad)
#define A6_BUF (128 * HSTR6)     // halfs per stage (A)
#define B6_BUF (128 * HSTR6)     // halfs per stage (B)
#define ST6_BUF (A6_BUF + B6_BUF)
#define GV6_SMEM (3 * ST6_BUF * 2)   // 110592 B

__global__ __launch_bounds__(256, 2) void gemm_v6(
    const __half* __restrict__ A,
    const __half* __restrict__ B1, const float* __restrict__ bias,
    void* __restrict__ C1, int outh1,
    const __half* __restrict__ B2, void* __restrict__ C2, int outh2,
    int nsplit, int M, int K)
{
    extern __shared__ __half sh[];
    const int tid = threadIdx.x;
    int bx = blockIdx.x;
    const __half* Bt = B1;
    void* Cp = C1;
    int outh = outh1;
    const float* bp = bias;
    if (B2 != nullptr && bx >= nsplit) { Bt = B2; Cp = C2; outh = outh2; bp = nullptr; bx -= nsplit; }

    const int wid = tid >> 5, lane = tid & 31;
    const int wm = wid >> 2, wn = wid & 3;     // 2 x 4 warp grid
    const int g = lane >> 2, tg = lane & 3;
    const int row0 = blockIdx.y * 128, col0 = bx * 128;

    const unsigned smem_base = (unsigned)__cvta_generic_to_shared(sh);
    const int mi = lane >> 3;           // ldmatrix sub-matrix index 0..3
    const int mr = lane & 7;            // ldmatrix row within sub-matrix

    float acc[4][4][4];
    #pragma unroll
    for (int i = 0; i < 4; i++)
        #pragma unroll
        for (int j = 0; j < 4; j++)
            #pragma unroll
            for (int r = 0; r < 4; r++) acc[i][j][r] = 0.0f;

    const int KT = K / 64;

    // per-stage load: A 128x64 + B 128x64, 8 x 16B per thread
    auto issue = [&](int tile, int stage) {
        const unsigned sb = smem_base + stage * ST6_BUF * 2;
        #pragma unroll
        for (int j = 0; j < 4; j++) {
            int idx = tid + j * 256;        // 0..1023
            int r = idx >> 3;               // 0..127
            int c = (idx & 7) * 8;          // 0..56 halfs
            int gr = row0 + r;
            int sz = (gr < M) ? 16 : 0;
            const __half* src = A + (size_t)(gr < M ? gr : (M - 1)) * K + tile * 64 + c;
            unsigned dst = sb + (r * HSTR6 + c) * 2;
            asm volatile("cp.async.cg.shared.global [%0], [%1], 16, %2;"
                         :: "r"(dst), "l"(src), "r"(sz));
        }
        #pragma unroll
        for (int j = 0; j < 4; j++) {
            int idx = tid + j * 256;
            int r = idx >> 3;
            int c = (idx & 7) * 8;
            const __half* src = Bt + (size_t)(col0 + r) * K + tile * 64 + c;
            unsigned dst = sb + (A6_BUF + r * HSTR6 + c) * 2;
            asm volatile("cp.async.cg.shared.global [%0], [%1], 16, %2;"
                         :: "r"(dst), "l"(src), "r"(16));
        }
        asm volatile("cp.async.commit_group;");
    };

    issue(0, 0);
    if (KT > 1) issue(1, 1);

    #pragma unroll 1
    for (int kt = 0; kt < KT; kt++) {
        if (kt < KT - 1) asm volatile("cp.async.wait_group 1;");
        else             asm volatile("cp.async.wait_group 0;");
        __syncthreads();
        if (kt + 2 < KT) issue(kt + 2, (kt + 2) % 3);

        const unsigned st = smem_base + (kt % 3) * ST6_BUF * 2;
        #pragma unroll
        for (int k16 = 0; k16 < 4; k16++) {
            unsigned int af[4][4], bf[4][2];
            #pragma unroll
            for (int i = 0; i < 4; i++) {
                int rowA = wm * 64 + i * 16 + mr + ((mi & 1) << 3);
                int colA = k16 * 16 + ((mi >> 1) << 3);
                unsigned addr = st + (rowA * HSTR6 + colA) * 2;
                asm volatile(
                    "ldmatrix.sync.aligned.m8n8.x4.shared.b16 {%0,%1,%2,%3}, [%4];"
                    : "=r"(af[i][0]), "=r"(af[i][1]), "=r"(af[i][2]), "=r"(af[i][3])
                    : "r"(addr));
            }
            #pragma unroll
            for (int jp = 0; jp < 2; jp++) {
                int rowB = wn * 32 + jp * 16 + mr + ((mi >> 1) << 3);
                int colB = k16 * 16 + ((mi & 1) << 3);
                unsigned addr = st + (A6_BUF + rowB * HSTR6 + colB) * 2;
                asm volatile(
                    "ldmatrix.sync.aligned.m8n8.x4.shared.b16 {%0,%1,%2,%3}, [%4];"
                    : "=r"(bf[2 * jp][0]), "=r"(bf[2 * jp][1]),
                      "=r"(bf[2 * jp + 1][0]), "=r"(bf[2 * jp + 1][1])
                    : "r"(addr));
            }
            #pragma unroll
            for (int i = 0; i < 4; i++)
                #pragma unroll
                for (int jn = 0; jn < 4; jn++) {
                    asm volatile(
                        "mma.sync.aligned.m16n8k16.row.col.f32.f16.f16.f32 "
                        "{%0,%1,%2,%3}, {%4,%5,%6,%7}, {%8,%9}, {%0,%1,%2,%3};"
                        : "+f"(acc[i][jn][0]), "+f"(acc[i][jn][1]),
                          "+f"(acc[i][jn][2]), "+f"(acc[i][jn][3])
                        : "r"(af[i][0]), "r"(af[i][1]), "r"(af[i][2]), "r"(af[i][3]),
                          "r"(bf[jn][0]), "r"(bf[jn][1]));
                }
        }
    }

    // epilogue (M-guarded), runtime output dtype
    #pragma unroll
    for (int i = 0; i < 4; i++) {
        #pragma unroll
        for (int jn = 0; jn < 4; jn++) {
            int row = row0 + wm * 64 + i * 16 + g;
            int col = col0 + wn * 32 + jn * 8 + tg * 2;
            float b0 = 0.f, b1 = 0.f;
            if (bp != nullptr) { b0 = bp[col]; b1 = bp[col + 1]; }
            if (row < M) {
                if (outh)
                    *(__half2*)((__half*)Cp + (size_t)row * CC + col) =
                        __floats2half2_rn(acc[i][jn][0] + b0, acc[i][jn][1] + b1);
                else
                    *(float2*)((float*)Cp + (size_t)row * CC + col) =
                        make_float2(acc[i][jn][0] + b0, acc[i][jn][1] + b1);
            }
            if (row + 8 < M) {
                if (outh)
                    *(__half2*)((__half*)Cp + (size_t)(row + 8) * CC + col) =
                        __floats2half2_rn(acc[i][jn][2] + b0, acc[i][jn][3] + b1);
                else
                    *(float2*)((float*)Cp + (size_t)(row + 8) * CC + col) =
                        make_float2(acc[i][jn][2] + b0, acc[i][jn][3] + b1);
            }
        }
    }
}

// ---------------- CORA prep ----------------
__global__ __launch_bounds__(256) void cora_prep(
    const float* __restrict__ target, const float* __restrict__ anchor,
    const float* __restrict__ pres,
    float* __restrict__ uhat, float* __restrict__ ahat, float* __restrict__ Gout)
{
    __shared__ float red[32];
    __shared__ float ud[CC], ad[CC];
    const int s = blockIdx.x, tid = threadIdx.x;
    const float* p0 = pres + (size_t)s * CC;
    const float* p1 = pres + (size_t)(SS + s) * CC;
    const float* tg = target + (size_t)s * CC;
    const float* an = anchor + (size_t)s * CC;

    float g00 = 0, g01 = 0, g11 = 0, bt0 = 0, bt1 = 0, ba0 = 0, ba1 = 0;
    for (int d = tid; d < CC; d += 256) {
        float a = p0[d], b = p1[d], t = tg[d], u = an[d];
        g00 += a * a; g01 += a * b; g11 += b * b;
        bt0 += a * t; bt1 += b * t;
        ba0 += a * u; ba1 += b * u;
    }
    g00 = blockSum(g00, red); g01 = blockSum(g01, red); g11 = blockSum(g11, red);
    bt0 = blockSum(bt0, red); bt1 = blockSum(bt1, red);
    ba0 = blockSum(ba0, red); ba1 = blockSum(ba1, red);

    float det = g00 * g11 - g01 * g01;
    float ct0 = (g11 * bt0 - g01 * bt1) / det, ct1 = (g00 * bt1 - g01 * bt0) / det;
    float ca0 = (g11 * ba0 - g01 * ba1) / det, ca1 = (g00 * ba1 - g01 * ba0) / det;

    float nu2 = 0;
    for (int d = tid; d < CC; d += 256) {
        float udv = tg[d] - (p0[d] * ct0 + p1[d] * ct1);
        float adv = an[d] - (p0[d] * ca0 + p1[d] * ca1);
        ud[d] = udv; ad[d] = adv;
        nu2 += udv * udv;
    }
    nu2 = blockSum(nu2, red);
    float nu = sqrtf(nu2) + EPSI;

    float dua = 0;
    for (int d = tid; d < CC; d += 256) {
        float uh = ud[d] / nu;
        ud[d] = uh;
        uhat[(size_t)s * CC + d] = uh;
        dua += uh * ad[d];
    }
    dua = blockSum(dua, red);

    float na2 = 0;
    for (int d = tid; d < CC; d += 256) {
        float at = ad[d] - dua * ud[d];
        ad[d] = at;
        na2 += at * at;
    }
    na2 = blockSum(na2, red);
    float na = sqrtf(na2) + EPSI;

    for (int d = tid; d < CC; d += 256)
        ahat[(size_t)s * CC + d] = ad[d] / na;

    if (tid == 0) { Gout[s * 3 + 0] = g00; Gout[s * 3 + 1] = g01; Gout[s * 3 + 2] = g11; }
}

// ---------------- CORA apply ----------------
__global__ __launch_bounds__(256) void cora_apply(
    const float* __restrict__ Vin, const float* __restrict__ pres,
    const float* __restrict__ G, const float* __restrict__ uhat,
    const float* __restrict__ ahat, float* __restrict__ Ve)
{
    __shared__ float red[32];
    const int bs = blockIdx.x, s = bs % SS, tid = threadIdx.x;
    const float* v = Vin + (size_t)bs * CC;
    const float* p0 = pres + (size_t)s * CC;
    const float* p1 = pres + (size_t)(SS + s) * CC;
    const float* uh = uhat + (size_t)s * CC;
    const float* ah = ahat + (size_t)s * CC;

    float b0 = 0, b1 = 0;
    for (int d = tid; d < CC; d += 256) {
        float vd = v[d];
        b0 += p0[d] * vd; b1 += p1[d] * vd;
    }
    b0 = blockSum(b0, red); b1 = blockSum(b1, red);

    float g00 = G[s * 3], g01 = G[s * 3 + 1], g11 = G[s * 3 + 2];
    float det = g00 * g11 - g01 * g01;
    float c0 = (g11 * b0 - g01 * b1) / det;
    float c1 = (g00 * b1 - g01 * b0) / det;

    float nf2 = 0, t = 0;
    for (int d = tid; d < CC; d += 256) {
        float vp = p0[d] * c0 + p1[d] * c1;
        float vf = v[d] - vp;
        nf2 += vf * vf;
        t += uh[d] * vf;
    }
    nf2 = blockSum(nf2, red);
    t = blockSum(t, red);

    float denom = sqrtf(nf2) + EPSI;
    bool keep = (fabsf(t) / denom) < TAU;

    for (int d = tid; d < CC; d += 256) {
        float vp = p0[d] * c0 + p1[d] * c1;
        float vf = v[d] - vp;
        float vn = vp + vf - t * uh[d] + BETA * t * ah[d];
        Ve[(size_t)bs * CC + d] = keep ? v[d] : vn;
    }
}

// =====================================================================
// Tensor-core attention: per (b, h, 128-row tile).
// =====================================================================
#define AQ_ROWS 128
#define ASTRH 88
#define ATTN2_SMEM ((AQ_ROWS * ASTRH + 80 * ASTRH + 80 * ASTRH) * 2)

__global__ __launch_bounds__(256) void attn_tc(
    const __half* __restrict__ Q, const __half* __restrict__ Kp,
    const float* __restrict__ Vp, __half* __restrict__ O)
{
    extern __shared__ __half ash[];
    __half* Qs = ash;
    __half* Ks = Qs + AQ_ROWS * ASTRH;
    __half* Vt = Ks + 80 * ASTRH;

    const int b = blockIdx.z, h = blockIdx.y;
    const int n0 = blockIdx.x * AQ_ROWS;
    const int tid = threadIdx.x;

    {
        unsigned int* z = (unsigned int*)Ks;
        for (int i = tid; i < 2 * 80 * ASTRH / 2; i += 256) z[i] = 0u;
    }
    __syncthreads();

    for (int i = tid * 4; i < AQ_ROWS * DH; i += 1024) {
        int r = i / DH, d = i % DH;
        *(uint2*)&Qs[r * ASTRH + d] =
            *(const uint2*)(Q + ((size_t)(b * NN + n0 + r)) * CC + h * DH + d);
    }
    for (int i = tid * 4; i < SS * DH; i += 1024) {
        int r = i / DH, d = i % DH;
        *(uint2*)&Ks[r * ASTRH + d] =
            *(const uint2*)(Kp + ((size_t)(b * SS + r)) * CC + h * DH + d);
    }
    for (int i = tid; i < SS * DH; i += 256) {
        int s = i / DH, d = i % DH;
        Vt[d * ASTRH + s] =
            __float2half_rn(Vp[((size_t)(b * SS + s)) * CC + h * DH + d]);
    }
    __syncthreads();

    const int w = tid >> 5, lane = tid & 31;
    const int g = lane >> 2, tg = lane & 3;
    const int qrow = w * 16;

    float c[10][4];
    #pragma unroll
    for (int j = 0; j < 10; j++)
        #pragma unroll
        for (int e = 0; e < 4; e++) c[j][e] = 0.0f;

    const unsigned int* Qu = (const unsigned int*)Qs;
    const unsigned int* Ku = (const unsigned int*)Ks;
    #pragma unroll
    for (int kk = 0; kk < 5; kk++) {
        unsigned int a0, a1, a2, a3;
        const unsigned int* p = Qu + (qrow + g) * (ASTRH / 2) + kk * 8 + tg;
        a0 = p[0];
        a1 = p[8 * (ASTRH / 2)];
        a2 = p[4];
        a3 = p[8 * (ASTRH / 2) + 4];
        #pragma unroll
        for (int j = 0; j < 10; j++) {
            const unsigned int* q = Ku + (j * 8 + g) * (ASTRH / 2) + kk * 8 + tg;
            unsigned int b0 = q[0], b1 = q[4];
            asm volatile(
                "mma.sync.aligned.m16n8k16.row.col.f32.f16.f16.f32 "
                "{%0,%1,%2,%3}, {%4,%5,%6,%7}, {%8,%9}, {%0,%1,%2,%3};"
                : "+f"(c[j][0]), "+f"(c[j][1]), "+f"(c[j][2]), "+f"(c[j][3])
                : "r"(a0), "r"(a1), "r"(a2), "r"(a3), "r"(b0), "r"(b1));
        }
    }

    const float scale = 0.11180339887498948f;
    const float NEG = -1e30f;
    #pragma unroll
    for (int j = 0; j < 10; j++)
        #pragma unroll
        for (int e = 0; e < 4; e++) c[j][e] *= scale;
    if (tg == 2) { c[9][1] = NEG; c[9][3] = NEG; }
    if (tg == 3) { c[9][0] = NEG; c[9][1] = NEG; c[9][2] = NEG; c[9][3] = NEG; }

    float m0 = NEG, m1 = NEG;
    #pragma unroll
    for (int j = 0; j < 10; j++) {
        m0 = fmaxf(m0, fmaxf(c[j][0], c[j][1]));
        m1 = fmaxf(m1, fmaxf(c[j][2], c[j][3]));
    }
    m0 = fmaxf(m0, __shfl_xor_sync(0xffffffffu, m0, 1));
    m0 = fmaxf(m0, __shfl_xor_sync(0xffffffffu, m0, 2));
    m1 = fmaxf(m1, __shfl_xor_sync(0xffffffffu, m1, 1));
    m1 = fmaxf(m1, __shfl_xor_sync(0xffffffffu, m1, 2));

    float s0 = 0.f, s1 = 0.f;
    #pragma unroll
    for (int j = 0; j < 10; j++) {
        c[j][0] = expf(c[j][0] - m0);
        c[j][1] = expf(c[j][1] - m0);
        c[j][2] = expf(c[j][2] - m1);
        c[j][3] = expf(c[j][3] - m1);
        s0 += c[j][0] + c[j][1];
        s1 += c[j][2] + c[j][3];
    }
    s0 += __shfl_xor_sync(0xffffffffu, s0, 1);
    s0 += __shfl_xor_sync(0xffffffffu, s0, 2);
    s1 += __shfl_xor_sync(0xffffffffu, s1, 1);
    s1 += __shfl_xor_sync(0xffffffffu, s1, 2);
    const float i0 = 1.0f / s0, i1 = 1.0f / s1;
    #pragma unroll
    for (int j = 0; j < 10; j++) {
        c[j][0] *= i0; c[j][1] *= i0;
        c[j][2] *= i1; c[j][3] *= i1;
    }

    float o[10][4];
    #pragma unroll
    for (int j = 0; j < 10; j++)
        #pragma unroll
        for (int e = 0; e < 4; e++) o[j][e] = 0.0f;

    const unsigned int* Vu = (const unsigned int*)Vt;
    #pragma unroll
    for (int kk = 0; kk < 5; kk++) {
        __half2 ha0 = __floats2half2_rn(c[2 * kk][0],     c[2 * kk][1]);
        __half2 ha1 = __floats2half2_rn(c[2 * kk][2],     c[2 * kk][3]);
        __half2 ha2 = __floats2half2_rn(c[2 * kk + 1][0], c[2 * kk + 1][1]);
        __half2 ha3 = __floats2half2_rn(c[2 * kk + 1][2], c[2 * kk + 1][3]);
        unsigned int a0 = *(unsigned int*)&ha0;
        unsigned int a1 = *(unsigned int*)&ha1;
        unsigned int a2 = *(unsigned int*)&ha2;
        unsigned int a3 = *(unsigned int*)&ha3;
        #pragma unroll
        for (int jd = 0; jd < 10; jd++) {
            const unsigned int* q = Vu + (jd * 8 + g) * (ASTRH / 2) + kk * 8 + tg;
            unsigned int b0 = q[0], b1 = q[4];
            asm volatile(
                "mma.sync.aligned.m16n8k16.row.col.f32.f16.f16.f32 "
                "{%0,%1,%2,%3}, {%4,%5,%6,%7}, {%8,%9}, {%0,%1,%2,%3};"
                : "+f"(o[jd][0]), "+f"(o[jd][1]), "+f"(o[jd][2]), "+f"(o[jd][3])
                : "r"(a0), "r"(a1), "r"(a2), "r"(a3), "r"(b0), "r"(b1));
        }
    }

    const int r0 = n0 + qrow + g;
    #pragma unroll
    for (int jd = 0; jd < 10; jd++) {
        int col = h * DH + jd * 8 + tg * 2;
        *(__half2*)(O + ((size_t)(b * NN + r0)) * CC + col) =
            __floats2half2_rn(o[jd][0], o[jd][1]);
        *(__half2*)(O + ((size_t)(b * NN + r0 + 8)) * CC + col) =
            __floats2half2_rn(o[jd][2], o[jd][3]);
    }
}

// ---------------- launch ----------------
extern "C" void kernel_launch(void* const* d_in, const int* in_sizes, int n_in,
                              void* d_out, int out_size)
{
    static float *Vb = nullptr, *Veb = nullptr, *Uh = nullptr, *Ah = nullptr,
                 *Gm = nullptr;
    static __half *Xh = nullptr, *Eh = nullptr, *Qh = nullptr, *Kh = nullptr,
                  *Attnh = nullptr, *Wh = nullptr;
    static bool init = false;
    if (!init) {
        cudaGetSymbolAddress((void**)&Xh, g_Xh);
        cudaGetSymbolAddress((void**)&Eh, g_Eh);
        cudaGetSymbolAddress((void**)&Qh, g_Qh);
        cudaGetSymbolAddress((void**)&Attnh, g_attnh);
        cudaGetSymbolAddress((void**)&Kh, g_Kh);
        cudaGetSymbolAddress((void**)&Vb, g_V);
        cudaGetSymbolAddress((void**)&Veb, g_Ve);
        cudaGetSymbolAddress((void**)&Uh, g_uhat);
        cudaGetSymbolAddress((void**)&Ah, g_ahat);
        cudaGetSymbolAddress((void**)&Gm, g_G);
        cudaGetSymbolAddress((void**)&Wh, g_Wh);
        cudaFuncSetAttribute(attn_tc, cudaFuncAttributeMaxDynamicSharedMemorySize,
                             ATTN2_SMEM);
        cudaFuncSetAttribute(gemm_v6, cudaFuncAttributeMaxDynamicSharedMemorySize,
                             GV6_SMEM);
        init = true;
    }

    const float* X    = (const float*)d_in[0];
    const float* E    = (const float*)d_in[1];
    const float* Wq   = (const float*)d_in[2];
    const float* Wk   = (const float*)d_in[3];
    const float* Wv   = (const float*)d_in[4];
    const float* Wo   = (const float*)d_in[5];
    const float* bo   = (const float*)d_in[6];
    const float* tgt  = (const float*)d_in[7];
    const float* anc  = (const float*)d_in[8];
    const float* pres = (const float*)d_in[9];
    float* out = (float*)d_out;

    __half* WqT = Wh + 0 * (XD * CC);
    __half* WkT = Wh + 1 * (XD * CC);
    __half* WvT = Wh + 2 * (XD * CC);
    __half* WoT = Wh + 3 * (XD * CC);

    // fp16 conversions + fused weight transpose
    to_half8<<<(BB * NN * CC) / 8 / 256, 256>>>(X, Xh, BB * NN * CC);
    to_half8<<<((BB * SS * XD) / 8 + 255) / 256, 256>>>(E, Eh, BB * SS * XD);
    transpose_all<<<dim3(CC / 32, XD / 32, 4), 256>>>(Wq, Wk, Wv, Wo, Wh);

    // Q projection: [32768,640] x [640,640] -> fp16
    gemm_v6<<<dim3(CC / 128, (BB * NN) / 128), 256, GV6_SMEM>>>(
        Xh, WqT, nullptr, Qh, 1, nullptr, nullptr, 0, CC / 128, BB * NN, CC);

    // K (fp16 out) + V (fp32 out) projections in ONE launch (dual-B)
    gemm_v6<<<dim3(2 * (CC / 128), (BB * SS + 127) / 128), 256, GV6_SMEM>>>(
        Eh, WkT, nullptr, Kh, 1, WvT, Vb, 0, CC / 128, BB * SS, XD);

    // CORA erase on V
    cora_prep<<<SS, 256>>>(tgt, anc, pres, Uh, Ah, Gm);
    cora_apply<<<BB * SS, 256>>>(Vb, pres, Gm, Uh, Ah, Veb);

    // tensor-core attention (writes fp16)
    attn_tc<<<dim3(NN / AQ_ROWS, HH, BB), 256, ATTN2_SMEM>>>(Qh, Kh, Veb, Attnh);

    // output projection + bias (fp32 out)
    gemm_v6<<<dim3(CC / 128, (BB * NN) / 128), 256, GV6_SMEM>>>(
        Attnh, WoT, bo, out, 0, nullptr, nullptr, 0, CC / 128, BB * NN, CC);
}

// round 13
// speedup vs baseline: 5.7807x; 1.0785x over previous
#include <cuda_runtime.h>
#include <cuda_fp16.h>
#include <math.h>
#include <stdint.h>

// Problem constants
#define BB 8
#define NN 4096
#define CC 640
#define SS 77
#define XD 768
#define HH 8
#define DH 80
#define BETA 0.5f
#define TAU 0.1f
#define EPSI 1e-8f

// ---------------- scratch (no cudaMalloc allowed) ----------------
__device__ __half g_Xh[BB * NN * CC];      // 41.9 MB (X, fp16)
__device__ __half g_Qh[BB * NN * CC];      // 41.9 MB (Q, fp16)
__device__ __half g_attnh[BB * NN * CC];   // 41.9 MB (attention out, fp16)
__device__ __half g_Eh[BB * SS * XD];      // E, fp16
__device__ __half g_Kh[BB * SS * CC];      // K, fp16
__device__ float g_V[BB * SS * CC];
__device__ float g_Ve[BB * SS * CC];
__device__ float g_uhat[SS * CC];
__device__ float g_ahat[SS * CC];
__device__ float g_G[SS * 3];
__device__ __half g_Wh[4][XD * CC];        // transposed fp16 weights [n][k]

// ---------------- block reduce helper ----------------
__device__ __forceinline__ float blockSum(float v, float* red) {
    #pragma unroll
    for (int o = 16; o; o >>= 1) v += __shfl_xor_sync(0xffffffffu, v, o);
    int w = threadIdx.x >> 5, l = threadIdx.x & 31;
    __syncthreads();
    if (l == 0) red[w] = v;
    __syncthreads();
    if (w == 0) {
        float x = (l < (int)(blockDim.x >> 5)) ? red[l] : 0.0f;
        #pragma unroll
        for (int o = 4; o; o >>= 1) x += __shfl_xor_sync(0xffffffffu, x, o);
        if (l == 0) red[0] = x;
    }
    __syncthreads();
    return red[0];
}

// ---------------- fp32 -> fp16 bulk convert (n % 8 == 0) ----------------
__global__ __launch_bounds__(256) void to_half8(
    const float* __restrict__ src, __half* __restrict__ dst, int n)
{
    int i = (blockIdx.x * 256 + threadIdx.x) * 8;
    if (i >= n) return;
    float4 a = *(const float4*)(src + i);
    float4 b = *(const float4*)(src + i + 4);
    __half2 h[4];
    h[0] = __floats2half2_rn(a.x, a.y);
    h[1] = __floats2half2_rn(a.z, a.w);
    h[2] = __floats2half2_rn(b.x, b.y);
    h[3] = __floats2half2_rn(b.z, b.w);
    *(uint4*)(dst + i) = *(uint4*)h;
}

// ---------------- fused weight transpose + fp16: Wh[z][n][k] ----------------
__global__ __launch_bounds__(256) void transpose_all(
    const float* __restrict__ Wq, const float* __restrict__ Wk,
    const float* __restrict__ Wv, const float* __restrict__ Wo,
    __half* __restrict__ Wh)
{
    __shared__ float t[32][33];
    const int z = blockIdx.z;
    const float* W = (z == 0) ? Wq : (z == 1) ? Wk : (z == 2) ? Wv : Wo;
    const int K = (z == 1 || z == 2) ? XD : CC;
    __half* Wt = Wh + (size_t)z * (XD * CC);

    const int k0 = blockIdx.y * 32, n0 = blockIdx.x * 32;
    if (k0 >= K) return;
    const int tx = threadIdx.x & 31, ty = threadIdx.x >> 5;
    #pragma unroll
    for (int i = ty; i < 32; i += 8) {
        int k = k0 + i, n = n0 + tx;
        if (k < K) t[i][tx] = W[(size_t)k * CC + n];
    }
    __syncthreads();
    #pragma unroll
    for (int i = ty; i < 32; i += 8) {
        int n = n0 + i, k = k0 + tx;
        if (k < K)
            Wt[(size_t)n * K + k] = __float2half_rn(t[tx][i]);
    }
}

// =====================================================================
// FP16 tensor-core GEMM v6 (unchanged from R12 — proven): k64 stages,
// 3-stage cp.async + ldmatrix, 2 CTAs/SM, dual-B, runtime out dtype.
// =====================================================================
#define HSTR6 72
#define A6_BUF (128 * HSTR6)
#define B6_BUF (128 * HSTR6)
#define ST6_BUF (A6_BUF + B6_BUF)
#define GV6_SMEM (3 * ST6_BUF * 2)   // 110592 B

__global__ __launch_bounds__(256, 2) void gemm_v6(
    const __half* __restrict__ A,
    const __half* __restrict__ B1, const float* __restrict__ bias,
    void* __restrict__ C1, int outh1,
    const __half* __restrict__ B2, void* __restrict__ C2, int outh2,
    int nsplit, int M, int K)
{
    extern __shared__ __half sh[];
    const int tid = threadIdx.x;
    int bx = blockIdx.x;
    const __half* Bt = B1;
    void* Cp = C1;
    int outh = outh1;
    const float* bp = bias;
    if (B2 != nullptr && bx >= nsplit) { Bt = B2; Cp = C2; outh = outh2; bp = nullptr; bx -= nsplit; }

    const int wid = tid >> 5, lane = tid & 31;
    const int wm = wid >> 2, wn = wid & 3;
    const int g = lane >> 2, tg = lane & 3;
    const int row0 = blockIdx.y * 128, col0 = bx * 128;

    const unsigned smem_base = (unsigned)__cvta_generic_to_shared(sh);
    const int mi = lane >> 3;
    const int mr = lane & 7;

    float acc[4][4][4];
    #pragma unroll
    for (int i = 0; i < 4; i++)
        #pragma unroll
        for (int j = 0; j < 4; j++)
            #pragma unroll
            for (int r = 0; r < 4; r++) acc[i][j][r] = 0.0f;

    const int KT = K / 64;

    auto issue = [&](int tile, int stage) {
        const unsigned sb = smem_base + stage * ST6_BUF * 2;
        #pragma unroll
        for (int j = 0; j < 4; j++) {
            int idx = tid + j * 256;
            int r = idx >> 3;
            int c = (idx & 7) * 8;
            int gr = row0 + r;
            int sz = (gr < M) ? 16 : 0;
            const __half* src = A + (size_t)(gr < M ? gr : (M - 1)) * K + tile * 64 + c;
            unsigned dst = sb + (r * HSTR6 + c) * 2;
            asm volatile("cp.async.cg.shared.global [%0], [%1], 16, %2;"
                         :: "r"(dst), "l"(src), "r"(sz));
        }
        #pragma unroll
        for (int j = 0; j < 4; j++) {
            int idx = tid + j * 256;
            int r = idx >> 3;
            int c = (idx & 7) * 8;
            const __half* src = Bt + (size_t)(col0 + r) * K + tile * 64 + c;
            unsigned dst = sb + (A6_BUF + r * HSTR6 + c) * 2;
            asm volatile("cp.async.cg.shared.global [%0], [%1], 16, %2;"
                         :: "r"(dst), "l"(src), "r"(16));
        }
        asm volatile("cp.async.commit_group;");
    };

    issue(0, 0);
    if (KT > 1) issue(1, 1);

    #pragma unroll 1
    for (int kt = 0; kt < KT; kt++) {
        if (kt < KT - 1) asm volatile("cp.async.wait_group 1;");
        else             asm volatile("cp.async.wait_group 0;");
        __syncthreads();
        if (kt + 2 < KT) issue(kt + 2, (kt + 2) % 3);

        const unsigned st = smem_base + (kt % 3) * ST6_BUF * 2;
        #pragma unroll
        for (int k16 = 0; k16 < 4; k16++) {
            unsigned int af[4][4], bf[4][2];
            #pragma unroll
            for (int i = 0; i < 4; i++) {
                int rowA = wm * 64 + i * 16 + mr + ((mi & 1) << 3);
                int colA = k16 * 16 + ((mi >> 1) << 3);
                unsigned addr = st + (rowA * HSTR6 + colA) * 2;
                asm volatile(
                    "ldmatrix.sync.aligned.m8n8.x4.shared.b16 {%0,%1,%2,%3}, [%4];"
                    : "=r"(af[i][0]), "=r"(af[i][1]), "=r"(af[i][2]), "=r"(af[i][3])
                    : "r"(addr));
            }
            #pragma unroll
            for (int jp = 0; jp < 2; jp++) {
                int rowB = wn * 32 + jp * 16 + mr + ((mi >> 1) << 3);
                int colB = k16 * 16 + ((mi & 1) << 3);
                unsigned addr = st + (A6_BUF + rowB * HSTR6 + colB) * 2;
                asm volatile(
                    "ldmatrix.sync.aligned.m8n8.x4.shared.b16 {%0,%1,%2,%3}, [%4];"
                    : "=r"(bf[2 * jp][0]), "=r"(bf[2 * jp][1]),
                      "=r"(bf[2 * jp + 1][0]), "=r"(bf[2 * jp + 1][1])
                    : "r"(addr));
            }
            #pragma unroll
            for (int i = 0; i < 4; i++)
                #pragma unroll
                for (int jn = 0; jn < 4; jn++) {
                    asm volatile(
                        "mma.sync.aligned.m16n8k16.row.col.f32.f16.f16.f32 "
                        "{%0,%1,%2,%3}, {%4,%5,%6,%7}, {%8,%9}, {%0,%1,%2,%3};"
                        : "+f"(acc[i][jn][0]), "+f"(acc[i][jn][1]),
                          "+f"(acc[i][jn][2]), "+f"(acc[i][jn][3])
                        : "r"(af[i][0]), "r"(af[i][1]), "r"(af[i][2]), "r"(af[i][3]),
                          "r"(bf[jn][0]), "r"(bf[jn][1]));
                }
        }
    }

    #pragma unroll
    for (int i = 0; i < 4; i++) {
        #pragma unroll
        for (int jn = 0; jn < 4; jn++) {
            int row = row0 + wm * 64 + i * 16 + g;
            int col = col0 + wn * 32 + jn * 8 + tg * 2;
            float b0 = 0.f, b1 = 0.f;
            if (bp != nullptr) { b0 = bp[col]; b1 = bp[col + 1]; }
            if (row < M) {
                if (outh)
                    *(__half2*)((__half*)Cp + (size_t)row * CC + col) =
                        __floats2half2_rn(acc[i][jn][0] + b0, acc[i][jn][1] + b1);
                else
                    *(float2*)((float*)Cp + (size_t)row * CC + col) =
                        make_float2(acc[i][jn][0] + b0, acc[i][jn][1] + b1);
            }
            if (row + 8 < M) {
                if (outh)
                    *(__half2*)((__half*)Cp + (size_t)(row + 8) * CC + col) =
                        __floats2half2_rn(acc[i][jn][2] + b0, acc[i][jn][3] + b1);
                else
                    *(float2*)((float*)Cp + (size_t)(row + 8) * CC + col) =
                        make_float2(acc[i][jn][2] + b0, acc[i][jn][3] + b1);
            }
        }
    }
}

// ---------------- CORA prep ----------------
__global__ __launch_bounds__(256) void cora_prep(
    const float* __restrict__ target, const float* __restrict__ anchor,
    const float* __restrict__ pres,
    float* __restrict__ uhat, float* __restrict__ ahat, float* __restrict__ Gout)
{
    __shared__ float red[32];
    __shared__ float ud[CC], ad[CC];
    const int s = blockIdx.x, tid = threadIdx.x;
    const float* p0 = pres + (size_t)s * CC;
    const float* p1 = pres + (size_t)(SS + s) * CC;
    const float* tg = target + (size_t)s * CC;
    const float* an = anchor + (size_t)s * CC;

    float g00 = 0, g01 = 0, g11 = 0, bt0 = 0, bt1 = 0, ba0 = 0, ba1 = 0;
    for (int d = tid; d < CC; d += 256) {
        float a = p0[d], b = p1[d], t = tg[d], u = an[d];
        g00 += a * a; g01 += a * b; g11 += b * b;
        bt0 += a * t; bt1 += b * t;
        ba0 += a * u; ba1 += b * u;
    }
    g00 = blockSum(g00, red); g01 = blockSum(g01, red); g11 = blockSum(g11, red);
    bt0 = blockSum(bt0, red); bt1 = blockSum(bt1, red);
    ba0 = blockSum(ba0, red); ba1 = blockSum(ba1, red);

    float det = g00 * g11 - g01 * g01;
    float ct0 = (g11 * bt0 - g01 * bt1) / det, ct1 = (g00 * bt1 - g01 * bt0) / det;
    float ca0 = (g11 * ba0 - g01 * ba1) / det, ca1 = (g00 * ba1 - g01 * ba0) / det;

    float nu2 = 0;
    for (int d = tid; d < CC; d += 256) {
        float udv = tg[d] - (p0[d] * ct0 + p1[d] * ct1);
        float adv = an[d] - (p0[d] * ca0 + p1[d] * ca1);
        ud[d] = udv; ad[d] = adv;
        nu2 += udv * udv;
    }
    nu2 = blockSum(nu2, red);
    float nu = sqrtf(nu2) + EPSI;

    float dua = 0;
    for (int d = tid; d < CC; d += 256) {
        float uh = ud[d] / nu;
        ud[d] = uh;
        uhat[(size_t)s * CC + d] = uh;
        dua += uh * ad[d];
    }
    dua = blockSum(dua, red);

    float na2 = 0;
    for (int d = tid; d < CC; d += 256) {
        float at = ad[d] - dua * ud[d];
        ad[d] = at;
        na2 += at * at;
    }
    na2 = blockSum(na2, red);
    float na = sqrtf(na2) + EPSI;

    for (int d = tid; d < CC; d += 256)
        ahat[(size_t)s * CC + d] = ad[d] / na;

    if (tid == 0) { Gout[s * 3 + 0] = g00; Gout[s * 3 + 1] = g01; Gout[s * 3 + 2] = g11; }
}

// ---------------- CORA apply ----------------
__global__ __launch_bounds__(256) void cora_apply(
    const float* __restrict__ Vin, const float* __restrict__ pres,
    const float* __restrict__ G, const float* __restrict__ uhat,
    const float* __restrict__ ahat, float* __restrict__ Ve)
{
    __shared__ float red[32];
    const int bs = blockIdx.x, s = bs % SS, tid = threadIdx.x;
    const float* v = Vin + (size_t)bs * CC;
    const float* p0 = pres + (size_t)s * CC;
    const float* p1 = pres + (size_t)(SS + s) * CC;
    const float* uh = uhat + (size_t)s * CC;
    const float* ah = ahat + (size_t)s * CC;

    float b0 = 0, b1 = 0;
    for (int d = tid; d < CC; d += 256) {
        float vd = v[d];
        b0 += p0[d] * vd; b1 += p1[d] * vd;
    }
    b0 = blockSum(b0, red); b1 = blockSum(b1, red);

    float g00 = G[s * 3], g01 = G[s * 3 + 1], g11 = G[s * 3 + 2];
    float det = g00 * g11 - g01 * g01;
    float c0 = (g11 * b0 - g01 * b1) / det;
    float c1 = (g00 * b1 - g01 * b0) / det;

    float nf2 = 0, t = 0;
    for (int d = tid; d < CC; d += 256) {
        float vp = p0[d] * c0 + p1[d] * c1;
        float vf = v[d] - vp;
        nf2 += vf * vf;
        t += uh[d] * vf;
    }
    nf2 = blockSum(nf2, red);
    t = blockSum(t, red);

    float denom = sqrtf(nf2) + EPSI;
    bool keep = (fabsf(t) / denom) < TAU;

    for (int d = tid; d < CC; d += 256) {
        float vp = p0[d] * c0 + p1[d] * c1;
        float vf = v[d] - vp;
        float vn = vp + vf - t * uh[d] + BETA * t * ah[d];
        Ve[(size_t)bs * CC + d] = keep ? v[d] : vn;
    }
}

// =====================================================================
// Tensor-core attention: per (b, h, 128-row tile).
// =====================================================================
#define AQ_ROWS 128
#define ASTRH 88
#define ATTN2_SMEM ((AQ_ROWS * ASTRH + 80 * ASTRH + 80 * ASTRH) * 2)

__global__ __launch_bounds__(256) void attn_tc(
    const __half* __restrict__ Q, const __half* __restrict__ Kp,
    const float* __restrict__ Vp, __half* __restrict__ O)
{
    extern __shared__ __half ash[];
    __half* Qs = ash;
    __half* Ks = Qs + AQ_ROWS * ASTRH;
    __half* Vt = Ks + 80 * ASTRH;

    const int b = blockIdx.z, h = blockIdx.y;
    const int n0 = blockIdx.x * AQ_ROWS;
    const int tid = threadIdx.x;

    {
        unsigned int* z = (unsigned int*)Ks;
        for (int i = tid; i < 2 * 80 * ASTRH / 2; i += 256) z[i] = 0u;
    }
    __syncthreads();

    for (int i = tid * 4; i < AQ_ROWS * DH; i += 1024) {
        int r = i / DH, d = i % DH;
        *(uint2*)&Qs[r * ASTRH + d] =
            *(const uint2*)(Q + ((size_t)(b * NN + n0 + r)) * CC + h * DH + d);
    }
    for (int i = tid * 4; i < SS * DH; i += 1024) {
        int r = i / DH, d = i % DH;
        *(uint2*)&Ks[r * ASTRH + d] =
            *(const uint2*)(Kp + ((size_t)(b * SS + r)) * CC + h * DH + d);
    }
    for (int i = tid; i < SS * DH; i += 256) {
        int s = i / DH, d = i % DH;
        Vt[d * ASTRH + s] =
            __float2half_rn(Vp[((size_t)(b * SS + s)) * CC + h * DH + d]);
    }
    __syncthreads();

    const int w = tid >> 5, lane = tid & 31;
    const int g = lane >> 2, tg = lane & 3;
    const int qrow = w * 16;

    float c[10][4];
    #pragma unroll
    for (int j = 0; j < 10; j++)
        #pragma unroll
        for (int e = 0; e < 4; e++) c[j][e] = 0.0f;

    const unsigned int* Qu = (const unsigned int*)Qs;
    const unsigned int* Ku = (const unsigned int*)Ks;
    #pragma unroll
    for (int kk = 0; kk < 5; kk++) {
        unsigned int a0, a1, a2, a3;
        const unsigned int* p = Qu + (qrow + g) * (ASTRH / 2) + kk * 8 + tg;
        a0 = p[0];
        a1 = p[8 * (ASTRH / 2)];
        a2 = p[4];
        a3 = p[8 * (ASTRH / 2) + 4];
        #pragma unroll
        for (int j = 0; j < 10; j++) {
            const unsigned int* q = Ku + (j * 8 + g) * (ASTRH / 2) + kk * 8 + tg;
            unsigned int b0 = q[0], b1 = q[4];
            asm volatile(
                "mma.sync.aligned.m16n8k16.row.col.f32.f16.f16.f32 "
                "{%0,%1,%2,%3}, {%4,%5,%6,%7}, {%8,%9}, {%0,%1,%2,%3};"
                : "+f"(c[j][0]), "+f"(c[j][1]), "+f"(c[j][2]), "+f"(c[j][3])
                : "r"(a0), "r"(a1), "r"(a2), "r"(a3), "r"(b0), "r"(b1));
        }
    }

    const float scale = 0.11180339887498948f;
    const float NEG = -1e30f;
    #pragma unroll
    for (int j = 0; j < 10; j++)
        #pragma unroll
        for (int e = 0; e < 4; e++) c[j][e] *= scale;
    if (tg == 2) { c[9][1] = NEG; c[9][3] = NEG; }
    if (tg == 3) { c[9][0] = NEG; c[9][1] = NEG; c[9][2] = NEG; c[9][3] = NEG; }

    float m0 = NEG, m1 = NEG;
    #pragma unroll
    for (int j = 0; j < 10; j++) {
        m0 = fmaxf(m0, fmaxf(c[j][0], c[j][1]));
        m1 = fmaxf(m1, fmaxf(c[j][2], c[j][3]));
    }
    m0 = fmaxf(m0, __shfl_xor_sync(0xffffffffu, m0, 1));
    m0 = fmaxf(m0, __shfl_xor_sync(0xffffffffu, m0, 2));
    m1 = fmaxf(m1, __shfl_xor_sync(0xffffffffu, m1, 1));
    m1 = fmaxf(m1, __shfl_xor_sync(0xffffffffu, m1, 2));

    float s0 = 0.f, s1 = 0.f;
    #pragma unroll
    for (int j = 0; j < 10; j++) {
        c[j][0] = expf(c[j][0] - m0);
        c[j][1] = expf(c[j][1] - m0);
        c[j][2] = expf(c[j][2] - m1);
        c[j][3] = expf(c[j][3] - m1);
        s0 += c[j][0] + c[j][1];
        s1 += c[j][2] + c[j][3];
    }
    s0 += __shfl_xor_sync(0xffffffffu, s0, 1);
    s0 += __shfl_xor_sync(0xffffffffu, s0, 2);
    s1 += __shfl_xor_sync(0xffffffffu, s1, 1);
    s1 += __shfl_xor_sync(0xffffffffu, s1, 2);
    const float i0 = 1.0f / s0, i1 = 1.0f / s1;
    #pragma unroll
    for (int j = 0; j < 10; j++) {
        c[j][0] *= i0; c[j][1] *= i0;
        c[j][2] *= i1; c[j][3] *= i1;
    }

    float o[10][4];
    #pragma unroll
    for (int j = 0; j < 10; j++)
        #pragma unroll
        for (int e = 0; e < 4; e++) o[j][e] = 0.0f;

    const unsigned int* Vu = (const unsigned int*)Vt;
    #pragma unroll
    for (int kk = 0; kk < 5; kk++) {
        __half2 ha0 = __floats2half2_rn(c[2 * kk][0],     c[2 * kk][1]);
        __half2 ha1 = __floats2half2_rn(c[2 * kk][2],     c[2 * kk][3]);
        __half2 ha2 = __floats2half2_rn(c[2 * kk + 1][0], c[2 * kk + 1][1]);
        __half2 ha3 = __floats2half2_rn(c[2 * kk + 1][2], c[2 * kk + 1][3]);
        unsigned int a0 = *(unsigned int*)&ha0;
        unsigned int a1 = *(unsigned int*)&ha1;
        unsigned int a2 = *(unsigned int*)&ha2;
        unsigned int a3 = *(unsigned int*)&ha3;
        #pragma unroll
        for (int jd = 0; jd < 10; jd++) {
            const unsigned int* q = Vu + (jd * 8 + g) * (ASTRH / 2) + kk * 8 + tg;
            unsigned int b0 = q[0], b1 = q[4];
            asm volatile(
                "mma.sync.aligned.m16n8k16.row.col.f32.f16.f16.f32 "
                "{%0,%1,%2,%3}, {%4,%5,%6,%7}, {%8,%9}, {%0,%1,%2,%3};"
                : "+f"(o[jd][0]), "+f"(o[jd][1]), "+f"(o[jd][2]), "+f"(o[jd][3])
                : "r"(a0), "r"(a1), "r"(a2), "r"(a3), "r"(b0), "r"(b1));
        }
    }

    const int r0 = n0 + qrow + g;
    #pragma unroll
    for (int jd = 0; jd < 10; jd++) {
        int col = h * DH + jd * 8 + tg * 2;
        *(__half2*)(O + ((size_t)(b * NN + r0)) * CC + col) =
            __floats2half2_rn(o[jd][0], o[jd][1]);
        *(__half2*)(O + ((size_t)(b * NN + r0 + 8)) * CC + col) =
            __floats2half2_rn(o[jd][2], o[jd][3]);
    }
}

// ---------------- launch ----------------
extern "C" void kernel_launch(void* const* d_in, const int* in_sizes, int n_in,
                              void* d_out, int out_size)
{
    static float *Vb = nullptr, *Veb = nullptr, *Uh = nullptr, *Ah = nullptr,
                 *Gm = nullptr;
    static __half *Xh = nullptr, *Eh = nullptr, *Qh = nullptr, *Kh = nullptr,
                  *Attnh = nullptr, *Wh = nullptr;
    static cudaStream_t sSide = nullptr;
    static cudaEvent_t evFork = nullptr, evW = nullptr, evJoin = nullptr;
    static bool init = false;
    if (!init) {
        cudaGetSymbolAddress((void**)&Xh, g_Xh);
        cudaGetSymbolAddress((void**)&Eh, g_Eh);
        cudaGetSymbolAddress((void**)&Qh, g_Qh);
        cudaGetSymbolAddress((void**)&Attnh, g_attnh);
        cudaGetSymbolAddress((void**)&Kh, g_Kh);
        cudaGetSymbolAddress((void**)&Vb, g_V);
        cudaGetSymbolAddress((void**)&Veb, g_Ve);
        cudaGetSymbolAddress((void**)&Uh, g_uhat);
        cudaGetSymbolAddress((void**)&Ah, g_ahat);
        cudaGetSymbolAddress((void**)&Gm, g_G);
        cudaGetSymbolAddress((void**)&Wh, g_Wh);
        cudaFuncSetAttribute(attn_tc, cudaFuncAttributeMaxDynamicSharedMemorySize,
                             ATTN2_SMEM);
        cudaFuncSetAttribute(gemm_v6, cudaFuncAttributeMaxDynamicSharedMemorySize,
                             GV6_SMEM);
        cudaStreamCreateWithFlags(&sSide, cudaStreamNonBlocking);
        cudaEventCreateWithFlags(&evFork, cudaEventDisableTiming);
        cudaEventCreateWithFlags(&evW, cudaEventDisableTiming);
        cudaEventCreateWithFlags(&evJoin, cudaEventDisableTiming);
        init = true;
    }

    const float* X    = (const float*)d_in[0];
    const float* E    = (const float*)d_in[1];
    const float* Wq   = (const float*)d_in[2];
    const float* Wk   = (const float*)d_in[3];
    const float* Wv   = (const float*)d_in[4];
    const float* Wo   = (const float*)d_in[5];
    const float* bo   = (const float*)d_in[6];
    const float* tgt  = (const float*)d_in[7];
    const float* anc  = (const float*)d_in[8];
    const float* pres = (const float*)d_in[9];
    float* out = (float*)d_out;

    __half* WqT = Wh + 0 * (XD * CC);
    __half* WkT = Wh + 1 * (XD * CC);
    __half* WvT = Wh + 2 * (XD * CC);
    __half* WoT = Wh + 3 * (XD * CC);

    // ---- fork side stream ----
    cudaEventRecord(evFork, 0);
    cudaStreamWaitEvent(sSide, evFork, 0);

    // side chain: weights + E path + K/V proj + CORA
    transpose_all<<<dim3(CC / 32, XD / 32, 4), 256, 0, sSide>>>(Wq, Wk, Wv, Wo, Wh);
    cudaEventRecord(evW, sSide);   // WqT/WoT ready for main
    to_half8<<<((BB * SS * XD) / 8 + 255) / 256, 256, 0, sSide>>>(E, Eh, BB * SS * XD);
    gemm_v6<<<dim3(2 * (CC / 128), (BB * SS + 127) / 128), 256, GV6_SMEM, sSide>>>(
        Eh, WkT, nullptr, Kh, 1, WvT, Vb, 0, CC / 128, BB * SS, XD);
    cora_prep<<<SS, 256, 0, sSide>>>(tgt, anc, pres, Uh, Ah, Gm);
    cora_apply<<<BB * SS, 256, 0, sSide>>>(Vb, pres, Gm, Uh, Ah, Veb);
    cudaEventRecord(evJoin, sSide);

    // main chain: X path + Q proj
    to_half8<<<(BB * NN * CC) / 8 / 256, 256>>>(X, Xh, BB * NN * CC);
    cudaStreamWaitEvent(0, evW, 0);
    gemm_v6<<<dim3(CC / 128, (BB * NN) / 128), 256, GV6_SMEM>>>(
        Xh, WqT, nullptr, Qh, 1, nullptr, nullptr, 0, CC / 128, BB * NN, CC);

    // join: attention needs Kh + Veb
    cudaStreamWaitEvent(0, evJoin, 0);
    attn_tc<<<dim3(NN / AQ_ROWS, HH, BB), 256, ATTN2_SMEM>>>(Qh, Kh, Veb, Attnh);

    // output projection + bias (fp32 out)
    gemm_v6<<<dim3(CC / 128, (BB * NN) / 128), 256, GV6_SMEM>>>(
        Attnh, WoT, bo, out, 0, nullptr, nullptr, 0, CC / 128, BB * NN, CC);
}